// round 4
// baseline (speedup 1.0000x reference)
#include <cuda_runtime.h>
#include <math.h>

#define N_ACT 4096
#define N_KEY 4096
#define DMODEL 512
#define NHEAD 4
#define DKH 128
#define NEGV (-1e9f)
#define QSCALE 0.08838834764831845f

#define BN 32
#define BM 32
#define LDQ 516
#define LDB 36

// scratch (static device allocations — allowed)
__device__ float g_q[N_ACT * DMODEL];
__device__ float g_k[N_KEY * DMODEL];
__device__ float g_v[N_KEY * DMODEL];
__device__ float g_ctx[N_ACT * DMODEL];
__device__ float g_wt[DKH * DMODEL];
__device__ float g_bt[DKH];
__device__ int   g_valid[N_ACT];
__device__ float g_zb[N_ACT];
__device__ float g_eb[(long long)N_ACT * N_KEY];
__device__ unsigned char g_mask[(long long)N_ACT * N_KEY];
__device__ int   g_mflag;   // 0 = bool bytes, 1 = int32, 2 = float32

__device__ __forceinline__ float nanfix(float x) {
    if (isnan(x)) return 0.f;
    if (isinf(x)) return x > 0.f ? 1.f : -1.f;
    return x;
}

// Fast exp for x <= 0, FFMA-only (no MUFU). ~2e-6 rel error.
__device__ __forceinline__ float fexp(float x) {
    x = fminf(x, 0.f);
    x = fmaxf(x, -87.0f);
    const float LOG2E = 1.4426950408889634f;
    float t = fmaf(x, LOG2E, 12582912.f);
    float jf = t - 12582912.f;
    int ji = (__float_as_int(t) & 0x7FFFFF) - 0x400000;
    float r = fmaf(x, LOG2E, -jf);
    float g = r * 0.6931471805599453f;
    float p = fmaf(g, 0.0083333333f, 0.0416666666f);
    p = fmaf(p, g, 0.1666666666f);
    p = fmaf(p, g, 0.5f);
    p = fmaf(p, g, 1.0f);
    p = fmaf(p, g, 1.0f);
    return __int_as_float((ji + 127) << 23) * p;
}

// ---------------------------------------------------------------------------
// Mask dtype detection + repack to canonical uint8
// ---------------------------------------------------------------------------
__global__ void mask_detect_kernel(const unsigned int* __restrict__ m) {
    __shared__ int cF, cHi;
    if (threadIdx.x == 0) { cF = 0; cHi = 0; }
    __syncthreads();
    int lf = 0, lh = 0;
    for (int i = threadIdx.x; i < 16384; i += 256) {
        unsigned int w = m[i];
        if (w == 0x3F800000u) lf++;
        else if ((w & 0xFFFFFF00u) != 0u) lh++;
    }
    atomicAdd(&cF, lf);
    atomicAdd(&cHi, lh);
    __syncthreads();
    if (threadIdx.x == 0) {
        if (cF > 16) g_mflag = 2;
        else if (cHi > 16) g_mflag = 0;
        else g_mflag = 1;
    }
}

__global__ void mask_repack_kernel(const void* __restrict__ mraw) {
    const long long i4 = (long long)blockIdx.x * 256 + threadIdx.x;
    if (i4 * 4 >= (long long)N_ACT * N_KEY) return;
    const int flag = g_mflag;
    uchar4 o;
    if (flag == 0) {
        uchar4 b = ((const uchar4*)mraw)[i4];
        o.x = b.x ? 1 : 0; o.y = b.y ? 1 : 0; o.z = b.z ? 1 : 0; o.w = b.w ? 1 : 0;
    } else if (flag == 1) {
        int4 b = ((const int4*)mraw)[i4];
        o.x = b.x ? 1 : 0; o.y = b.y ? 1 : 0; o.z = b.z ? 1 : 0; o.w = b.w ? 1 : 0;
    } else {
        float4 b = ((const float4*)mraw)[i4];
        o.x = (b.x != 0.f) ? 1 : 0; o.y = (b.y != 0.f) ? 1 : 0;
        o.z = (b.z != 0.f) ? 1 : 0; o.w = (b.w != 0.f) ? 1 : 0;
    }
    ((uchar4*)g_mask)[i4] = o;
}

// ---------------------------------------------------------------------------
// Bias softmax pre-pass: per row n compute Mb, Zb, valid, and EB = exp(b - Mb)
// ---------------------------------------------------------------------------
__global__ __launch_bounds__(256) void bias_prep_kernel(const float* __restrict__ weight) {
    __shared__ float red[256];
    __shared__ int sv;
    const int n = blockIdx.x, tid = threadIdx.x;
    if (tid == 0) sv = 0;
    __syncthreads();
    const long long base = (long long)n * N_KEY;
    float b[16];
    float mx = -INFINITY; int anym = 0;
#pragma unroll
    for (int j = 0; j < 4; ++j) {
        int m = tid * 4 + j * 1024;
        float4 w = *(const float4*)&weight[base + m];
        uchar4 mk = *(const uchar4*)&g_mask[base + m];
        float b0 = mk.x ? nanfix(w.x) : NEGV;
        float b1 = mk.y ? nanfix(w.y) : NEGV;
        float b2 = mk.z ? nanfix(w.z) : NEGV;
        float b3 = mk.w ? nanfix(w.w) : NEGV;
        b[j*4+0] = b0; b[j*4+1] = b1; b[j*4+2] = b2; b[j*4+3] = b3;
        anym |= (mk.x | mk.y | mk.z | mk.w);
        mx = fmaxf(fmaxf(fmaxf(mx, b0), fmaxf(b1, b2)), b3);
    }
    if (anym) atomicOr(&sv, 1);
    red[tid] = mx;
    __syncthreads();
    for (int s = 128; s > 0; s >>= 1) {
        if (tid < s) red[tid] = fmaxf(red[tid], red[tid + s]);
        __syncthreads();
    }
    float Mb = red[0];
    __syncthreads();
    float zs = 0.f;
#pragma unroll
    for (int j = 0; j < 4; ++j) {
        int m = tid * 4 + j * 1024;
        float4 e;
        e.x = fexp(b[j*4+0] - Mb);
        e.y = fexp(b[j*4+1] - Mb);
        e.z = fexp(b[j*4+2] - Mb);
        e.w = fexp(b[j*4+3] - Mb);
        *(float4*)&g_eb[base + m] = e;
        zs += (e.x + e.y) + (e.z + e.w);
    }
    red[tid] = zs;
    __syncthreads();
    for (int s = 128; s > 0; s >>= 1) {
        if (tid < s) red[tid] += red[tid + s];
        __syncthreads();
    }
    if (tid == 0) { g_zb[n] = red[0]; g_valid[n] = sv; }
}

// ---------------------------------------------------------------------------
// Build reduced out-proj weight: wt[dk][c] = mean_h out_w[h*128+dk][c]
// ---------------------------------------------------------------------------
__global__ void build_wt_kernel(const float* __restrict__ ow,
                                const float* __restrict__ ob) {
    int idx = blockIdx.x * 256 + threadIdx.x;
    if (idx < DKH * DMODEL) {
        int dk = idx >> 9, c = idx & 511;
        g_wt[idx] = 0.25f * (ow[dk * DMODEL + c] +
                             ow[(dk + DKH) * DMODEL + c] +
                             ow[(dk + 2 * DKH) * DMODEL + c] +
                             ow[(dk + 3 * DKH) * DMODEL + c]);
    }
    if (idx < DKH) {
        g_bt[idx] = 0.25f * (ob[idx] + ob[idx + DKH] + ob[idx + 2 * DKH] + ob[idx + 3 * DKH]);
    }
}

// ---------------------------------------------------------------------------
// Fused QKV projection: 128x128 tile, 256 threads, 8x8 micro, double-buffered.
// grid (12, 32): blockIdx.x -> which weight slab (0-3 q, 4-7 k, 8-11 v)
// ---------------------------------------------------------------------------
__global__ __launch_bounds__(256) void proj_kernel(
    const float* __restrict__ A, const float* __restrict__ BV,
    const float* __restrict__ ipw, const float* __restrict__ ipb)
{
    __shared__ float Xs[2][16 * 128];
    __shared__ float Ws[2][16 * 128];
    const int tid = threadIdx.x;
    const int cx = blockIdx.x;
    const int which = cx >> 2;              // 0 q, 1 k, 2 v
    const int rowBase = blockIdx.y * 128;
    const int wBase = cx * 128;             // row in packed in_proj [0,1536)
    const float* X = (which == 0) ? A : BV;

    const int lr = tid & 127;               // staging row
    const int kg = tid >> 7;                // 0/1 -> k offset 8
    const float* xg = X + (long long)(rowBase + lr) * 512 + kg * 8;
    const float* wg = ipw + (long long)(wBase + lr) * 512 + kg * 8;

    const int ty = tid >> 4, tx = tid & 15;

    float acc[8][8];
#pragma unroll
    for (int i = 0; i < 8; ++i)
#pragma unroll
        for (int j = 0; j < 8; ++j) acc[i][j] = 0.f;

    // prologue chunk 0
    {
        float4 x0 = *(const float4*)(xg);
        float4 x1 = *(const float4*)(xg + 4);
        float4 w0 = *(const float4*)(wg);
        float4 w1 = *(const float4*)(wg + 4);
        x0.x = nanfix(x0.x); x0.y = nanfix(x0.y); x0.z = nanfix(x0.z); x0.w = nanfix(x0.w);
        x1.x = nanfix(x1.x); x1.y = nanfix(x1.y); x1.z = nanfix(x1.z); x1.w = nanfix(x1.w);
        float xv[8] = {x0.x,x0.y,x0.z,x0.w,x1.x,x1.y,x1.z,x1.w};
        float wv[8] = {w0.x,w0.y,w0.z,w0.w,w1.x,w1.y,w1.z,w1.w};
#pragma unroll
        for (int e = 0; e < 8; ++e) {
            Xs[0][(kg * 8 + e) * 128 + lr] = xv[e];
            Ws[0][(kg * 8 + e) * 128 + lr] = wv[e];
        }
    }

    for (int c = 0; c < 32; ++c) {
        __syncthreads();
        const int cur = c & 1;
        float4 nx0, nx1, nw0, nw1;
        if (c < 31) {
            const float* xp = xg + (c + 1) * 16;
            const float* wp = wg + (c + 1) * 16;
            nx0 = *(const float4*)(xp);
            nx1 = *(const float4*)(xp + 4);
            nw0 = *(const float4*)(wp);
            nw1 = *(const float4*)(wp + 4);
        }
#pragma unroll
        for (int k = 0; k < 16; ++k) {
            const float* xr = &Xs[cur][k * 128];
            const float* wr = &Ws[cur][k * 128];
            float4 xa0 = *(const float4*)&xr[ty * 4];
            float4 xa1 = *(const float4*)&xr[64 + ty * 4];
            float4 wb0 = *(const float4*)&wr[tx * 4];
            float4 wb1 = *(const float4*)&wr[64 + tx * 4];
            float xv[8] = {xa0.x,xa0.y,xa0.z,xa0.w,xa1.x,xa1.y,xa1.z,xa1.w};
            float wv[8] = {wb0.x,wb0.y,wb0.z,wb0.w,wb1.x,wb1.y,wb1.z,wb1.w};
#pragma unroll
            for (int i = 0; i < 8; ++i)
#pragma unroll
                for (int j = 0; j < 8; ++j)
                    acc[i][j] = fmaf(xv[i], wv[j], acc[i][j]);
        }
        if (c < 31) {
            const int nb = cur ^ 1;
            nx0.x = nanfix(nx0.x); nx0.y = nanfix(nx0.y); nx0.z = nanfix(nx0.z); nx0.w = nanfix(nx0.w);
            nx1.x = nanfix(nx1.x); nx1.y = nanfix(nx1.y); nx1.z = nanfix(nx1.z); nx1.w = nanfix(nx1.w);
            float xv[8] = {nx0.x,nx0.y,nx0.z,nx0.w,nx1.x,nx1.y,nx1.z,nx1.w};
            float wv[8] = {nw0.x,nw0.y,nw0.z,nw0.w,nw1.x,nw1.y,nw1.z,nw1.w};
#pragma unroll
            for (int e = 0; e < 8; ++e) {
                Xs[nb][(kg * 8 + e) * 128 + lr] = xv[e];
                Ws[nb][(kg * 8 + e) * 128 + lr] = wv[e];
            }
        }
    }

    const float scale = (which == 0) ? QSCALE : 1.f;
    float* dst = (which == 0) ? g_q : ((which == 1) ? g_k : g_v);
#pragma unroll
    for (int ri = 0; ri < 2; ++ri)
#pragma unroll
        for (int i = 0; i < 4; ++i) {
            const int n = rowBase + ri * 64 + ty * 4 + i;
#pragma unroll
            for (int ci = 0; ci < 2; ++ci) {
                const int ob = wBase + ci * 64 + tx * 4;
                const int og = ob & 511;
                float4 o;
                o.x = scale * (acc[ri*4+i][ci*4+0] + ipb[ob + 0]);
                o.y = scale * (acc[ri*4+i][ci*4+1] + ipb[ob + 1]);
                o.z = scale * (acc[ri*4+i][ci*4+2] + ipb[ob + 2]);
                o.w = scale * (acc[ri*4+i][ci*4+3] + ipb[ob + 3]);
                *(float4*)&dst[(long long)n * 512 + og] = o;
            }
        }
}

// ---------------------------------------------------------------------------
// Topic GEMM (small): C[n][o] = (ctx . wt[o]) + bt[o], valid-gated. 64x64 tile.
// ---------------------------------------------------------------------------
__global__ __launch_bounds__(256) void gemm_nt_kernel(
    const float* __restrict__ X, const float* __restrict__ W,
    const float* __restrict__ bias, float* __restrict__ out,
    int ldo, const int* __restrict__ valid)
{
    __shared__ float Xs[64 * 36];
    __shared__ float Ws[64 * 36];
    const int tid = threadIdx.x;
    const int rowBase = blockIdx.y * 64;
    const int colBase = blockIdx.x * 64;
    const int og = tid & 15, ngr = tid >> 4;

    float acc[4][4];
#pragma unroll
    for (int i = 0; i < 4; ++i)
#pragma unroll
        for (int j = 0; j < 4; ++j) acc[i][j] = 0.f;

    for (int kk = 0; kk < 512; kk += 32) {
#pragma unroll
        for (int jj = 0; jj < 2; ++jj) {
            int idx = tid + jj * 256;
            int r = idx >> 3, c4 = (idx & 7) << 2;
            *(float4*)&Xs[r * 36 + c4] = *(const float4*)&X[(rowBase + r) * 512 + kk + c4];
            *(float4*)&Ws[r * 36 + c4] = *(const float4*)&W[(colBase + r) * 512 + kk + c4];
        }
        __syncthreads();
#pragma unroll
        for (int k4 = 0; k4 < 32; k4 += 4) {
            float4 xv[4], wv[4];
#pragma unroll
            for (int i = 0; i < 4; ++i) xv[i] = *(const float4*)&Xs[(ngr * 4 + i) * 36 + k4];
#pragma unroll
            for (int j = 0; j < 4; ++j) wv[j] = *(const float4*)&Ws[(og * 4 + j) * 36 + k4];
#pragma unroll
            for (int i = 0; i < 4; ++i)
#pragma unroll
                for (int j = 0; j < 4; ++j) {
                    acc[i][j] = fmaf(xv[i].x, wv[j].x, acc[i][j]);
                    acc[i][j] = fmaf(xv[i].y, wv[j].y, acc[i][j]);
                    acc[i][j] = fmaf(xv[i].z, wv[j].z, acc[i][j]);
                    acc[i][j] = fmaf(xv[i].w, wv[j].w, acc[i][j]);
                }
        }
        __syncthreads();
    }
#pragma unroll
    for (int i = 0; i < 4; ++i) {
        int n = rowBase + ngr * 4 + i;
        float vmul = valid[n] ? 1.f : 0.f;
#pragma unroll
        for (int j = 0; j < 4; ++j) {
            int o = colBase + og * 4 + j;
            out[n * ldo + o] = vmul * (acc[i][j] + bias[o]);
        }
    }
}

// ---------------------------------------------------------------------------
// Fused flash-attention + influence. BN=32 rows, 4 heads, 256 threads.
// ---------------------------------------------------------------------------
__global__ __launch_bounds__(256, 1) void attn_kernel(
    const float* __restrict__ weight,
    float* __restrict__ inf_out)
{
    extern __shared__ float sm[];
    float* Qs   = sm;                         // 32*516
    float* KVs  = Qs + 32 * LDQ;              // 32*516
    float* Ss   = KVs + 32 * LDQ;             // 4*32*36
    float* Bs   = Ss + 4 * 32 * LDB;          // 32*36
    float* EBs  = Bs + 32 * LDB;              // 32*36
    float* Alph = EBs + 32 * LDB;             // 128
    float* Zsh  = Alph + 128;                 // 128
    float* CHs  = Zsh + 128;                  // 128

    const int tid = threadIdx.x;
    const int nBase = blockIdx.x * BN;

    // Q tile (persistent)
#pragma unroll
    for (int j = 0; j < 16; ++j) {
        int idx = tid + j * 256;
        int r = idx >> 7, c = (idx & 127) << 2;
        *(float4*)&Qs[r * LDQ + c] = *(const float4*)&g_q[(long long)(nBase + r) * DMODEL + c];
    }
    __syncthreads();

    float acc[8][8];
#pragma unroll
    for (int i = 0; i < 8; ++i)
#pragma unroll
        for (int k = 0; k < 8; ++k) acc[i][k] = 0.f;

    float Mh = -INFINITY, Zh = 0.f, Ch = 0.f;   // per (n,h), tid<128

    // role mappings
    const int h1 = tid >> 5, l1 = tid & 31;
    const int mg1 = l1 & 3, ng1 = l1 >> 2;          // phase1 (tid<128): 4n x 8m micro
    const int h2 = tid >> 5, n2 = tid & 31;         // phase2b (tid<128)
    const int t2 = tid - 128;                       // aux group (tid>=128)
    const int ng3 = tid & 3, jg3 = tid >> 2;        // phase3 (all)
    const int h3 = jg3 >> 4, d3 = jg3 << 3, n3 = ng3 << 3;
    const int br = tid >> 3, bc = (tid & 7) << 2;   // bias tile load

    for (int mt = 0; mt < N_KEY / BM; ++mt) {
        const int mBase = mt * BM;
        // K tile (all threads)
#pragma unroll
        for (int j = 0; j < 16; ++j) {
            int idx = tid + j * 256;
            int r = idx >> 7, c = (idx & 127) << 2;
            *(float4*)&KVs[r * LDQ + c] = *(const float4*)&g_k[(long long)(mBase + r) * DMODEL + c];
        }
        // bias tile
        {
            const float4 wv = *(const float4*)&weight[(long long)(nBase + br) * N_KEY + mBase + bc];
            const uchar4 mk = *(const uchar4*)&g_mask[(long long)(nBase + br) * N_KEY + mBase + bc];
            Bs[br * LDB + bc + 0] = mk.x ? nanfix(wv.x) : NEGV;
            Bs[br * LDB + bc + 1] = mk.y ? nanfix(wv.y) : NEGV;
            Bs[br * LDB + bc + 2] = mk.z ? nanfix(wv.z) : NEGV;
            Bs[br * LDB + bc + 3] = mk.w ? nanfix(wv.w) : NEGV;
        }
        __syncthreads();   // S1

        if (tid < 128) {
            // phase 1: scores (4 heads x 32n x 32m over 128 threads)
            float s[4][8];
#pragma unroll
            for (int i = 0; i < 4; ++i)
#pragma unroll
                for (int j = 0; j < 8; ++j) s[i][j] = 0.f;
            const float* qb = Qs + (ng1 * 4) * LDQ + h1 * DKH;
            const float* kb = KVs + (mg1 * 8) * LDQ + h1 * DKH;
#pragma unroll 4
            for (int k = 0; k < DKH; k += 4) {
                float4 qv[4], kv[8];
#pragma unroll
                for (int i = 0; i < 4; ++i) qv[i] = *(const float4*)(qb + i * LDQ + k);
#pragma unroll
                for (int j = 0; j < 8; ++j) kv[j] = *(const float4*)(kb + j * LDQ + k);
#pragma unroll
                for (int i = 0; i < 4; ++i)
#pragma unroll
                    for (int j = 0; j < 8; ++j) {
                        s[i][j] = fmaf(qv[i].x, kv[j].x, s[i][j]);
                        s[i][j] = fmaf(qv[i].y, kv[j].y, s[i][j]);
                        s[i][j] = fmaf(qv[i].z, kv[j].z, s[i][j]);
                        s[i][j] = fmaf(qv[i].w, kv[j].w, s[i][j]);
                    }
            }
            float* sb = Ss + h1 * (32 * LDB);
#pragma unroll
            for (int i = 0; i < 4; ++i) {
                const int rr = ng1 * 4 + i;
                float4 b0 = *(const float4*)&Bs[rr * LDB + mg1 * 8];
                float4 b1 = *(const float4*)&Bs[rr * LDB + mg1 * 8 + 4];
                float4 o0, o1;
                o0.x = s[i][0] + b0.x; o0.y = s[i][1] + b0.y;
                o0.z = s[i][2] + b0.z; o0.w = s[i][3] + b0.w;
                o1.x = s[i][4] + b1.x; o1.y = s[i][5] + b1.y;
                o1.z = s[i][6] + b1.z; o1.w = s[i][7] + b1.w;
                *(float4*)&sb[rr * LDB + mg1 * 8] = o0;
                *(float4*)&sb[rr * LDB + mg1 * 8 + 4] = o1;
            }
        } else {
            // EB tile: 32 x 32 floats
            const int r = t2 >> 2, c8 = (t2 & 3) * 8;
            *(float4*)&EBs[r * LDB + c8] =
                *(const float4*)&g_eb[(long long)(nBase + r) * N_KEY + mBase + c8];
            *(float4*)&EBs[r * LDB + c8 + 4] =
                *(const float4*)&g_eb[(long long)(nBase + r) * N_KEY + mBase + c8 + 4];
        }
        __syncthreads();   // S2

        if (tid < 128) {
            // phase 2b: score softmax online update + cross term
            float* srow = Ss + h2 * (32 * LDB) + n2 * LDB;
            const float* ebr = EBs + n2 * LDB;
            float rmax = -INFINITY;
#pragma unroll
            for (int m4 = 0; m4 < 8; ++m4) {
                float4 v = *(const float4*)&srow[m4 * 4];
                rmax = fmaxf(rmax, fmaxf(fmaxf(v.x, v.y), fmaxf(v.z, v.w)));
            }
            const float Mn = fmaxf(Mh, rmax);
            const float alpha = fexp(Mh - Mn);
            float zs = 0.f, cs = 0.f;
#pragma unroll
            for (int m4 = 0; m4 < 8; ++m4) {
                float4 v = *(const float4*)&srow[m4 * 4];
                float4 e;
                e.x = fexp(v.x - Mn); e.y = fexp(v.y - Mn);
                e.z = fexp(v.z - Mn); e.w = fexp(v.w - Mn);
                *(float4*)&srow[m4 * 4] = e;
                zs += (e.x + e.y) + (e.z + e.w);
                float4 eb = *(const float4*)&ebr[m4 * 4];
                cs = fmaf(eb.x, e.x, cs); cs = fmaf(eb.y, e.y, cs);
                cs = fmaf(eb.z, e.z, cs); cs = fmaf(eb.w, e.w, cs);
            }
            Zh = Zh * alpha + zs;
            Ch = Ch * alpha + cs;
            Mh = Mn;
            Alph[tid] = alpha;
        } else {
            // V tile load
#pragma unroll
            for (int j = 0; j < 32; ++j) {
                int idx = t2 + j * 128;
                int r = idx >> 7, c = (idx & 127) << 2;
                *(float4*)&KVs[r * LDQ + c] = *(const float4*)&g_v[(long long)(mBase + r) * DMODEL + c];
            }
        }
        __syncthreads();   // S3

        // phase 3: ctx accumulate (all 256 threads, 8n x 8d micro)
        {
#pragma unroll
            for (int i = 0; i < 8; ++i) {
                const float al = Alph[h3 * 32 + n3 + i];
#pragma unroll
                for (int k = 0; k < 8; ++k) acc[i][k] *= al;
            }
            const float* prow = Ss + h3 * (32 * LDB) + n3 * LDB;
#pragma unroll 2
            for (int m0 = 0; m0 < BM; m0 += 4) {
                float pr[8][4];
#pragma unroll
                for (int i = 0; i < 8; ++i) {
                    float4 t = *(const float4*)&prow[i * LDB + m0];
                    pr[i][0] = t.x; pr[i][1] = t.y; pr[i][2] = t.z; pr[i][3] = t.w;
                }
                float vv[4][8];
#pragma unroll
                for (int mm = 0; mm < 4; ++mm) {
                    float4 a = *(const float4*)&KVs[(m0 + mm) * LDQ + d3];
                    float4 b = *(const float4*)&KVs[(m0 + mm) * LDQ + d3 + 4];
                    vv[mm][0] = a.x; vv[mm][1] = a.y; vv[mm][2] = a.z; vv[mm][3] = a.w;
                    vv[mm][4] = b.x; vv[mm][5] = b.y; vv[mm][6] = b.z; vv[mm][7] = b.w;
                }
#pragma unroll
                for (int mm = 0; mm < 4; ++mm)
#pragma unroll
                    for (int i = 0; i < 8; ++i)
#pragma unroll
                        for (int d = 0; d < 8; ++d)
                            acc[i][d] = fmaf(pr[i][mm], vv[mm][d], acc[i][d]);
            }
        }
        __syncthreads();   // S4
    }

    // epilogue
    if (tid < 128) { Zsh[tid] = Zh; CHs[tid] = Ch / Zh; }
    __syncthreads();
    if (tid < 32) {
        const int n = tid;
        float s = CHs[n] + CHs[32 + n] + CHs[64 + n] + CHs[96 + n];
        float v = g_valid[nBase + n] ? (0.25f * s / g_zb[nBase + n]) : 0.f;
        inf_out[nBase + n] = v;
    }
#pragma unroll
    for (int i = 0; i < 8; ++i) {
        float inv = 1.f / Zsh[h3 * 32 + n3 + i];
        float4 o0, o1;
        o0.x = acc[i][0] * inv; o0.y = acc[i][1] * inv;
        o0.z = acc[i][2] * inv; o0.w = acc[i][3] * inv;
        o1.x = acc[i][4] * inv; o1.y = acc[i][5] * inv;
        o1.z = acc[i][6] * inv; o1.w = acc[i][7] * inv;
        *(float4*)&g_ctx[(long long)(nBase + n3 + i) * DMODEL + d3] = o0;
        *(float4*)&g_ctx[(long long)(nBase + n3 + i) * DMODEL + d3 + 4] = o1;
    }
}

// ---------------------------------------------------------------------------
extern "C" void kernel_launch(void* const* d_in, const int* in_sizes, int n_in,
                              void* d_out, int out_size) {
    const float* a      = (const float*)d_in[0];
    const float* bv     = (const float*)d_in[1];
    const void*  mraw   = (const void*)d_in[2];
    const float* weight = (const float*)d_in[3];
    const float* ipw    = (const float*)d_in[4];
    const float* ipb    = (const float*)d_in[5];
    const float* ow     = (const float*)d_in[6];
    const float* ob     = (const float*)d_in[7];
    float* out = (float*)d_out;

    void *pctx, *pwt, *pbt, *pvalid;
    cudaGetSymbolAddress(&pctx, g_ctx);
    cudaGetSymbolAddress(&pwt, g_wt);
    cudaGetSymbolAddress(&pbt, g_bt);
    cudaGetSymbolAddress(&pvalid, g_valid);

    // normalize mask, then precompute bias softmax stats + EB
    mask_detect_kernel<<<1, 256>>>((const unsigned int*)mraw);
    mask_repack_kernel<<<(int)(((long long)N_ACT * N_KEY / 4 + 255) / 256), 256>>>(mraw);
    bias_prep_kernel<<<N_ACT, 256>>>(weight);

    build_wt_kernel<<<(DKH * DMODEL + 255) / 256, 256>>>(ow, ob);

    // fused QKV projections
    proj_kernel<<<dim3(12, 32), 256>>>(a, bv, ipw, ipb);

    const int smemBytes = (2 * 32 * LDQ + 4 * 32 * LDB + 2 * 32 * LDB + 3 * 128) * 4;
    cudaFuncSetAttribute(attn_kernel, cudaFuncAttributeMaxDynamicSharedMemorySize, smemBytes);
    attn_kernel<<<N_ACT / BN, 256, smemBytes>>>(weight, out + N_ACT * DKH);

    gemm_nt_kernel<<<dim3(2, 64), 256>>>((const float*)pctx, (const float*)pwt,
                                         (const float*)pbt, out, DKH, (const int*)pvalid);
}

// round 10
// speedup vs baseline: 2.2461x; 2.2461x over previous
#include <cuda_runtime.h>
#include <cuda_bf16.h>
#include <cstdint>
#include <math.h>

#define N_ACT 4096
#define N_KEY 4096
#define DMODEL 512
#define NHEAD 4
#define DKH 128
#define NEGV (-1e9f)
#define QSCALE 0.08838834764831845f
#define LDT 40   // bf16 elements per smem tile row (32 data + 8 pad)

// ---------------------------------------------------------------------------
// scratch (static device allocations — allowed)
// ---------------------------------------------------------------------------
__device__ __nv_bfloat16 g_ah[N_ACT * DMODEL],  g_al[N_ACT * DMODEL];
__device__ __nv_bfloat16 g_bvh[N_KEY * DMODEL], g_bvl[N_KEY * DMODEL];
__device__ __nv_bfloat16 g_wh[3 * DMODEL * DMODEL], g_wl[3 * DMODEL * DMODEL];
__device__ __nv_bfloat16 g_qh[N_ACT * DMODEL],  g_ql[N_ACT * DMODEL];
__device__ __nv_bfloat16 g_kh[N_KEY * DMODEL],  g_kl[N_KEY * DMODEL];
__device__ __nv_bfloat16 g_vth[DMODEL * N_KEY], g_vtl[DMODEL * N_KEY];
__device__ float g_s[(size_t)NHEAD * N_ACT * N_KEY];
__device__ __nv_bfloat16 g_ph[(size_t)NHEAD * N_ACT * N_KEY];
__device__ __nv_bfloat16 g_pl[(size_t)NHEAD * N_ACT * N_KEY];
__device__ float g_zinv[NHEAD * N_ACT];
__device__ float g_ctx[N_ACT * DMODEL];
__device__ float g_wt[DKH * DMODEL];
__device__ float g_bt[DKH];
__device__ int   g_valid[N_ACT];
__device__ unsigned char g_mask[(size_t)N_ACT * N_KEY];
__device__ int   g_mflag;

__device__ __forceinline__ float nanfix(float x) {
    if (isnan(x)) return 0.f;
    if (isinf(x)) return x > 0.f ? 1.f : -1.f;
    return x;
}

// Fast exp for x <= 0, FFMA-only. ~2e-6 rel error.
__device__ __forceinline__ float fexp(float x) {
    x = fminf(x, 0.f);
    x = fmaxf(x, -87.0f);
    const float LOG2E = 1.4426950408889634f;
    float t = fmaf(x, LOG2E, 12582912.f);
    float jf = t - 12582912.f;
    int ji = (__float_as_int(t) & 0x7FFFFF) - 0x400000;
    float r = fmaf(x, LOG2E, -jf);
    float g = r * 0.6931471805599453f;
    float p = fmaf(g, 0.0083333333f, 0.0416666666f);
    p = fmaf(p, g, 0.1666666666f);
    p = fmaf(p, g, 0.5f);
    p = fmaf(p, g, 1.0f);
    p = fmaf(p, g, 1.0f);
    return __int_as_float((ji + 127) << 23) * p;
}

// ---------------------------------------------------------------------------
// warp mma: m16n8k16 bf16 (baseline PTX, works on sm_103 non-'a' target)
// ---------------------------------------------------------------------------
__device__ __forceinline__ void mma_bf16(float c[4], const uint32_t a[4], const uint32_t b[2]) {
    asm volatile("mma.sync.aligned.m16n8k16.row.col.f32.bf16.bf16.f32 "
                 "{%0,%1,%2,%3}, {%4,%5,%6,%7}, {%8,%9}, {%0,%1,%2,%3};"
                 : "+f"(c[0]), "+f"(c[1]), "+f"(c[2]), "+f"(c[3])
                 : "r"(a[0]), "r"(a[1]), "r"(a[2]), "r"(a[3]), "r"(b[0]), "r"(b[1]));
}

// ---------------------------------------------------------------------------
// Shared block-GEMM mainloop. C[128m x 128n] += A[128 x K] * B[128 x K]^T
// (both A, B row-major with k contiguous). Split-bf16: 3 products.
// 256 threads, 8 warps (4m x 2n), warp tile 32x64. K in chunks of 32.
// acc layout per thread: [mb(2)][nb(8)][4] with the m16n8k16 D fragment map:
//   row = wm*32+mb*16+g (+8 for c2/c3), col = wn*64+nb*8+t4*2 (+1 for odd reg)
// ---------------------------------------------------------------------------
__device__ __forceinline__ void gemm_block_mainloop(
    float (&acc)[2][8][4],
    const __nv_bfloat16* __restrict__ Ah, const __nv_bfloat16* __restrict__ Al, long long lda,
    const __nv_bfloat16* __restrict__ Bh, const __nv_bfloat16* __restrict__ Bl, long long ldb,
    int nchunk, __nv_bfloat16* sm)
{
    const int tid = threadIdx.x;
    const int lane = tid & 31, warp = tid >> 5;
    const int wm = warp >> 1, wn = warp & 1;
    const int g = lane >> 2, t4 = lane & 3;
    __nv_bfloat16* sAh = sm;
    __nv_bfloat16* sAl = sm + 128 * LDT;
    __nv_bfloat16* sBh = sm + 2 * 128 * LDT;
    __nv_bfloat16* sBl = sm + 3 * 128 * LDT;
    const int lr = tid >> 2;            // 0..63 staging row
    const int lc = (tid & 3) * 8;       // 0,8,16,24

    uint4 rAh0, rAh1, rAl0, rAl1, rBh0, rBh1, rBl0, rBl1;

#define FETCH_CHUNK(c) do { \
    const long long co = (long long)(c) * 32 + lc; \
    rAh0 = *(const uint4*)&Ah[(long long)lr * lda + co]; \
    rAh1 = *(const uint4*)&Ah[(long long)(lr + 64) * lda + co]; \
    rAl0 = *(const uint4*)&Al[(long long)lr * lda + co]; \
    rAl1 = *(const uint4*)&Al[(long long)(lr + 64) * lda + co]; \
    rBh0 = *(const uint4*)&Bh[(long long)lr * ldb + co]; \
    rBh1 = *(const uint4*)&Bh[(long long)(lr + 64) * ldb + co]; \
    rBl0 = *(const uint4*)&Bl[(long long)lr * ldb + co]; \
    rBl1 = *(const uint4*)&Bl[(long long)(lr + 64) * ldb + co]; \
} while (0)

    FETCH_CHUNK(0);
    for (int c = 0; c < nchunk; ++c) {
        *(uint4*)&sAh[lr * LDT + lc] = rAh0;
        *(uint4*)&sAh[(lr + 64) * LDT + lc] = rAh1;
        *(uint4*)&sAl[lr * LDT + lc] = rAl0;
        *(uint4*)&sAl[(lr + 64) * LDT + lc] = rAl1;
        *(uint4*)&sBh[lr * LDT + lc] = rBh0;
        *(uint4*)&sBh[(lr + 64) * LDT + lc] = rBh1;
        *(uint4*)&sBl[lr * LDT + lc] = rBl0;
        *(uint4*)&sBl[(lr + 64) * LDT + lc] = rBl1;
        __syncthreads();
        if (c + 1 < nchunk) FETCH_CHUNK(c + 1);

#pragma unroll
        for (int kk = 0; kk < 2; ++kk) {
            const int k0 = kk * 16 + t4 * 2;
            uint32_t fah[2][4], fal[2][4];
#pragma unroll
            for (int mb = 0; mb < 2; ++mb) {
                const int m0 = wm * 32 + mb * 16 + g;
                fah[mb][0] = *(const uint32_t*)&sAh[m0 * LDT + k0];
                fah[mb][1] = *(const uint32_t*)&sAh[(m0 + 8) * LDT + k0];
                fah[mb][2] = *(const uint32_t*)&sAh[m0 * LDT + k0 + 8];
                fah[mb][3] = *(const uint32_t*)&sAh[(m0 + 8) * LDT + k0 + 8];
                fal[mb][0] = *(const uint32_t*)&sAl[m0 * LDT + k0];
                fal[mb][1] = *(const uint32_t*)&sAl[(m0 + 8) * LDT + k0];
                fal[mb][2] = *(const uint32_t*)&sAl[m0 * LDT + k0 + 8];
                fal[mb][3] = *(const uint32_t*)&sAl[(m0 + 8) * LDT + k0 + 8];
            }
            uint32_t fbh[8][2], fbl[8][2];
#pragma unroll
            for (int nb = 0; nb < 8; ++nb) {
                const int n0 = wn * 64 + nb * 8 + g;
                fbh[nb][0] = *(const uint32_t*)&sBh[n0 * LDT + k0];
                fbh[nb][1] = *(const uint32_t*)&sBh[n0 * LDT + k0 + 8];
                fbl[nb][0] = *(const uint32_t*)&sBl[n0 * LDT + k0];
                fbl[nb][1] = *(const uint32_t*)&sBl[n0 * LDT + k0 + 8];
            }
#pragma unroll
            for (int mb = 0; mb < 2; ++mb)
#pragma unroll
                for (int nb = 0; nb < 8; ++nb) {
                    mma_bf16(acc[mb][nb], fah[mb], fbh[nb]);
                    mma_bf16(acc[mb][nb], fah[mb], fbl[nb]);
                    mma_bf16(acc[mb][nb], fal[mb], fbh[nb]);
                }
        }
        __syncthreads();
    }
#undef FETCH_CHUNK
}

// ---------------------------------------------------------------------------
// mask dtype detect + repack
// ---------------------------------------------------------------------------
__global__ void mask_detect_kernel(const unsigned int* __restrict__ m) {
    __shared__ int cF, cHi;
    if (threadIdx.x == 0) { cF = 0; cHi = 0; }
    __syncthreads();
    int lf = 0, lh = 0;
    for (int i = threadIdx.x; i < 16384; i += 256) {
        unsigned int w = m[i];
        if (w == 0x3F800000u) lf++;
        else if ((w & 0xFFFFFF00u) != 0u) lh++;
    }
    atomicAdd(&cF, lf);
    atomicAdd(&cHi, lh);
    __syncthreads();
    if (threadIdx.x == 0) {
        if (cF > 16) g_mflag = 2;
        else if (cHi > 16) g_mflag = 0;
        else g_mflag = 1;
    }
}

__global__ void mask_repack_kernel(const void* __restrict__ mraw) {
    const long long i4 = (long long)blockIdx.x * 256 + threadIdx.x;
    if (i4 * 4 >= (long long)N_ACT * N_KEY) return;
    const int flag = g_mflag;
    uchar4 o;
    if (flag == 0) {
        uchar4 b = ((const uchar4*)mraw)[i4];
        o.x = b.x ? 1 : 0; o.y = b.y ? 1 : 0; o.z = b.z ? 1 : 0; o.w = b.w ? 1 : 0;
    } else if (flag == 1) {
        int4 b = ((const int4*)mraw)[i4];
        o.x = b.x ? 1 : 0; o.y = b.y ? 1 : 0; o.z = b.z ? 1 : 0; o.w = b.w ? 1 : 0;
    } else {
        float4 b = ((const float4*)mraw)[i4];
        o.x = (b.x != 0.f) ? 1 : 0; o.y = (b.y != 0.f) ? 1 : 0;
        o.z = (b.z != 0.f) ? 1 : 0; o.w = (b.w != 0.f) ? 1 : 0;
    }
    ((uchar4*)g_mask)[i4] = o;
}

// fp32 -> split bf16 (hi + lo)
__global__ void conv_split_kernel(const float* __restrict__ src,
                                  __nv_bfloat16* __restrict__ hi,
                                  __nv_bfloat16* __restrict__ lo,
                                  int n4, int fix) {
    int i = blockIdx.x * 256 + threadIdx.x;
    if (i >= n4) return;
    float4 v = ((const float4*)src)[i];
    if (fix) { v.x = nanfix(v.x); v.y = nanfix(v.y); v.z = nanfix(v.z); v.w = nanfix(v.w); }
    float a[4] = {v.x, v.y, v.z, v.w};
#pragma unroll
    for (int j = 0; j < 4; ++j) {
        __nv_bfloat16 h = __float2bfloat16(a[j]);
        hi[i * 4 + j] = h;
        lo[i * 4 + j] = __float2bfloat16(a[j] - __bfloat162float(h));
    }
}

__global__ void build_wt_kernel(const float* __restrict__ ow,
                                const float* __restrict__ ob) {
    int idx = blockIdx.x * 256 + threadIdx.x;
    if (idx < DKH * DMODEL) {
        int dk = idx >> 9, c = idx & 511;
        g_wt[idx] = 0.25f * (ow[dk * DMODEL + c] + ow[(dk + DKH) * DMODEL + c] +
                             ow[(dk + 2 * DKH) * DMODEL + c] + ow[(dk + 3 * DKH) * DMODEL + c]);
    }
    if (idx < DKH)
        g_bt[idx] = 0.25f * (ob[idx] + ob[idx + DKH] + ob[idx + 2 * DKH] + ob[idx + 3 * DKH]);
}

// ---------------------------------------------------------------------------
// QKV projection: grid (12, 32). C[n 128][o 128] = X @ W^T + b (scaled for Q).
// ---------------------------------------------------------------------------
__global__ __launch_bounds__(256) void proj_mma_kernel(const float* __restrict__ ipb) {
    __shared__ __align__(16) unsigned char smraw[4 * 128 * LDT * 2];
    __nv_bfloat16* sm = (__nv_bfloat16*)smraw;
    const int ot = blockIdx.x, nt = blockIdx.y;
    const int which = ot >> 2;
    const __nv_bfloat16* Xh = (which == 0) ? g_ah : g_bvh;
    const __nv_bfloat16* Xl = (which == 0) ? g_al : g_bvl;

    float acc[2][8][4];
#pragma unroll
    for (int i = 0; i < 2; ++i)
#pragma unroll
        for (int j = 0; j < 8; ++j)
#pragma unroll
            for (int r = 0; r < 4; ++r) acc[i][j][r] = 0.f;

    gemm_block_mainloop(acc,
        Xh + (long long)nt * 128 * DMODEL, Xl + (long long)nt * 128 * DMODEL, DMODEL,
        g_wh + (long long)ot * 128 * DMODEL, g_wl + (long long)ot * 128 * DMODEL, DMODEL,
        16, sm);

    const int lane = threadIdx.x & 31, warp = threadIdx.x >> 5;
    const int wm = warp >> 1, wn = warp & 1, g = lane >> 2, t4 = lane & 3;
    const float scale = (which == 0) ? QSCALE : 1.f;
#pragma unroll
    for (int mb = 0; mb < 2; ++mb)
#pragma unroll
        for (int nb = 0; nb < 8; ++nb)
#pragma unroll
            for (int half = 0; half < 2; ++half) {
                const long long n = (long long)nt * 128 + wm * 32 + mb * 16 + g + half * 8;
                const int og = ot * 128 + wn * 64 + nb * 8 + t4 * 2;
                float v0 = scale * (acc[mb][nb][half * 2 + 0] + ipb[og]);
                float v1 = scale * (acc[mb][nb][half * 2 + 1] + ipb[og + 1]);
                __nv_bfloat16 h0 = __float2bfloat16(v0);
                __nv_bfloat16 l0 = __float2bfloat16(v0 - __bfloat162float(h0));
                __nv_bfloat16 h1 = __float2bfloat16(v1);
                __nv_bfloat16 l1 = __float2bfloat16(v1 - __bfloat162float(h1));
                if (which == 0) {
                    g_qh[n * DMODEL + og] = h0; g_qh[n * DMODEL + og + 1] = h1;
                    g_ql[n * DMODEL + og] = l0; g_ql[n * DMODEL + og + 1] = l1;
                } else if (which == 1) {
                    const int c = og - 512;
                    g_kh[n * DMODEL + c] = h0; g_kh[n * DMODEL + c + 1] = h1;
                    g_kl[n * DMODEL + c] = l0; g_kl[n * DMODEL + c + 1] = l1;
                } else {
                    const long long d = og - 1024;
                    g_vth[d * N_KEY + n] = h0; g_vth[(d + 1) * N_KEY + n] = h1;
                    g_vtl[d * N_KEY + n] = l0; g_vtl[(d + 1) * N_KEY + n] = l1;
                }
            }
}

// ---------------------------------------------------------------------------
// Scores: grid (32 nt, 32 mt, 4 h). S = Q K^T + masked bias -> g_s (fp32)
// ---------------------------------------------------------------------------
__global__ __launch_bounds__(256) void score_mma_kernel(const float* __restrict__ weight) {
    __shared__ __align__(16) unsigned char smraw[4 * 128 * LDT * 2];
    __nv_bfloat16* sm = (__nv_bfloat16*)smraw;
    const int nt = blockIdx.x, mt = blockIdx.y, h = blockIdx.z;

    float acc[2][8][4];
#pragma unroll
    for (int i = 0; i < 2; ++i)
#pragma unroll
        for (int j = 0; j < 8; ++j)
#pragma unroll
            for (int r = 0; r < 4; ++r) acc[i][j][r] = 0.f;

    gemm_block_mainloop(acc,
        g_qh + (long long)nt * 128 * DMODEL + h * DKH,
        g_ql + (long long)nt * 128 * DMODEL + h * DKH, DMODEL,
        g_kh + (long long)mt * 128 * DMODEL + h * DKH,
        g_kl + (long long)mt * 128 * DMODEL + h * DKH, DMODEL,
        4, sm);

    const int lane = threadIdx.x & 31, warp = threadIdx.x >> 5;
    const int wm = warp >> 1, wn = warp & 1, g = lane >> 2, t4 = lane & 3;
#pragma unroll
    for (int mb = 0; mb < 2; ++mb)
#pragma unroll
        for (int nb = 0; nb < 8; ++nb)
#pragma unroll
            for (int half = 0; half < 2; ++half) {
                const long long n = (long long)nt * 128 + wm * 32 + mb * 16 + g + half * 8;
                const long long m = (long long)mt * 128 + wn * 64 + nb * 8 + t4 * 2;
                const float2 w = *(const float2*)&weight[n * N_KEY + m];
                const unsigned char mk0 = g_mask[n * N_KEY + m];
                const unsigned char mk1 = g_mask[n * N_KEY + m + 1];
                float2 o;
                o.x = acc[mb][nb][half * 2 + 0] + (mk0 ? nanfix(w.x) : NEGV);
                o.y = acc[mb][nb][half * 2 + 1] + (mk1 ? nanfix(w.y) : NEGV);
                *(float2*)&g_s[((size_t)h * N_ACT + n) * N_KEY + m] = o;
            }
}

// ---------------------------------------------------------------------------
// Softmax + influence: grid 4096 rows, 256 threads.
// ---------------------------------------------------------------------------
__global__ __launch_bounds__(256) void softmax_kernel(const float* __restrict__ weight,
                                                      float* __restrict__ inf_out) {
    __shared__ float eb[N_KEY];
    __shared__ float sr[N_KEY];
    __shared__ float red[256];
    __shared__ int rvalid;
    const int n = blockIdx.x, t = threadIdx.x;
    const long long base = (long long)n * N_KEY;
    if (t == 0) rvalid = 0;
    __syncthreads();

    float lmax = -INFINITY; int lval = 0;
#pragma unroll
    for (int j = 0; j < 4; ++j) {
        int m = j * 1024 + t * 4;
        float4 w = *(const float4*)&weight[base + m];
        uchar4 mk = *(const uchar4*)&g_mask[base + m];
        float b0 = mk.x ? nanfix(w.x) : NEGV;
        float b1 = mk.y ? nanfix(w.y) : NEGV;
        float b2 = mk.z ? nanfix(w.z) : NEGV;
        float b3 = mk.w ? nanfix(w.w) : NEGV;
        eb[m] = b0; eb[m + 1] = b1; eb[m + 2] = b2; eb[m + 3] = b3;
        lval |= (mk.x | mk.y | mk.z | mk.w);
        lmax = fmaxf(fmaxf(fmaxf(lmax, b0), fmaxf(b1, b2)), b3);
    }
    if (lval) atomicOr(&rvalid, 1);
    red[t] = lmax;
    __syncthreads();
    for (int s = 128; s > 0; s >>= 1) { if (t < s) red[t] = fmaxf(red[t], red[t + s]); __syncthreads(); }
    const float Mb = red[0];
    __syncthreads();
    float lz = 0.f;
#pragma unroll
    for (int j = 0; j < 4; ++j) {
        int m = j * 1024 + t * 4;
        float e0 = fexp(eb[m] - Mb), e1 = fexp(eb[m + 1] - Mb);
        float e2 = fexp(eb[m + 2] - Mb), e3 = fexp(eb[m + 3] - Mb);
        eb[m] = e0; eb[m + 1] = e1; eb[m + 2] = e2; eb[m + 3] = e3;
        lz += (e0 + e1) + (e2 + e3);
    }
    red[t] = lz;
    __syncthreads();
    for (int s = 128; s > 0; s >>= 1) { if (t < s) red[t] += red[t + s]; __syncthreads(); }
    const float Zb = red[0];
    __syncthreads();

    float inf_acc = 0.f;
    for (int h = 0; h < NHEAD; ++h) {
        const size_t hb = ((size_t)h * N_ACT + n) * N_KEY;
        float lm = -INFINITY;
#pragma unroll
        for (int j = 0; j < 4; ++j) {
            int m = j * 1024 + t * 4;
            float4 v = *(const float4*)&g_s[hb + m];
            *(float4*)&sr[m] = v;
            lm = fmaxf(fmaxf(fmaxf(lm, v.x), fmaxf(v.y, v.z)), v.w);
        }
        red[t] = lm;
        __syncthreads();
        for (int s = 128; s > 0; s >>= 1) { if (t < s) red[t] = fmaxf(red[t], red[t + s]); __syncthreads(); }
        const float Mh = red[0];
        __syncthreads();
        float zh = 0.f, ch = 0.f;
#pragma unroll
        for (int j = 0; j < 4; ++j) {
            int m = j * 1024 + t * 4;
            float p0 = fexp(sr[m] - Mh), p1 = fexp(sr[m + 1] - Mh);
            float p2 = fexp(sr[m + 2] - Mh), p3 = fexp(sr[m + 3] - Mh);
            __nv_bfloat16 h0 = __float2bfloat16(p0), h1 = __float2bfloat16(p1);
            __nv_bfloat16 h2 = __float2bfloat16(p2), h3 = __float2bfloat16(p3);
            g_ph[hb + m] = h0; g_ph[hb + m + 1] = h1;
            g_ph[hb + m + 2] = h2; g_ph[hb + m + 3] = h3;
            g_pl[hb + m]     = __float2bfloat16(p0 - __bfloat162float(h0));
            g_pl[hb + m + 1] = __float2bfloat16(p1 - __bfloat162float(h1));
            g_pl[hb + m + 2] = __float2bfloat16(p2 - __bfloat162float(h2));
            g_pl[hb + m + 3] = __float2bfloat16(p3 - __bfloat162float(h3));
            zh += (p0 + p1) + (p2 + p3);
            ch = fmaf(eb[m], p0, ch); ch = fmaf(eb[m + 1], p1, ch);
            ch = fmaf(eb[m + 2], p2, ch); ch = fmaf(eb[m + 3], p3, ch);
        }
        red[t] = zh;
        __syncthreads();
        for (int s = 128; s > 0; s >>= 1) { if (t < s) red[t] += red[t + s]; __syncthreads(); }
        const float Zh = red[0];
        __syncthreads();
        red[t] = ch;
        __syncthreads();
        for (int s = 128; s > 0; s >>= 1) { if (t < s) red[t] += red[t + s]; __syncthreads(); }
        const float Ch = red[0];
        __syncthreads();
        if (t == 0) g_zinv[h * N_ACT + n] = 1.f / Zh;
        inf_acc += Ch / Zh;
    }
    if (t == 0) {
        g_valid[n] = rvalid;
        inf_out[n] = rvalid ? (0.25f * inf_acc / Zb) : 0.f;
    }
}

// ---------------------------------------------------------------------------
// ctx: grid (32 nt, 4 h). C[n 128][d 128] = P @ V^T, scaled by 1/Zh.
// ---------------------------------------------------------------------------
__global__ __launch_bounds__(256) void ctx_mma_kernel() {
    __shared__ __align__(16) unsigned char smraw[4 * 128 * LDT * 2];
    __nv_bfloat16* sm = (__nv_bfloat16*)smraw;
    const int nt = blockIdx.x, h = blockIdx.y;

    float acc[2][8][4];
#pragma unroll
    for (int i = 0; i < 2; ++i)
#pragma unroll
        for (int j = 0; j < 8; ++j)
#pragma unroll
            for (int r = 0; r < 4; ++r) acc[i][j][r] = 0.f;

    gemm_block_mainloop(acc,
        g_ph + ((size_t)h * N_ACT + (size_t)nt * 128) * N_KEY,
        g_pl + ((size_t)h * N_ACT + (size_t)nt * 128) * N_KEY, N_KEY,
        g_vth + (long long)h * 128 * N_KEY,
        g_vtl + (long long)h * 128 * N_KEY, N_KEY,
        128, sm);

    const int lane = threadIdx.x & 31, warp = threadIdx.x >> 5;
    const int wm = warp >> 1, wn = warp & 1, g = lane >> 2, t4 = lane & 3;
#pragma unroll
    for (int mb = 0; mb < 2; ++mb)
#pragma unroll
        for (int half = 0; half < 2; ++half) {
            const long long n = (long long)nt * 128 + wm * 32 + mb * 16 + g + half * 8;
            const float zi = g_zinv[h * N_ACT + n];
#pragma unroll
            for (int nb = 0; nb < 8; ++nb) {
                const int d = wn * 64 + nb * 8 + t4 * 2;
                float2 o;
                o.x = acc[mb][nb][half * 2 + 0] * zi;
                o.y = acc[mb][nb][half * 2 + 1] * zi;
                *(float2*)&g_ctx[n * DMODEL + h * DKH + d] = o;
            }
        }
}

// ---------------------------------------------------------------------------
// Topic GEMM (FFMA, small): C[n][o] = ctx . wt[o] + bt[o], valid-gated.
// ---------------------------------------------------------------------------
__global__ __launch_bounds__(256) void gemm_nt_kernel(
    const float* __restrict__ X, const float* __restrict__ W,
    const float* __restrict__ bias, float* __restrict__ out,
    int ldo, const int* __restrict__ valid)
{
    __shared__ float Xs[64 * 36];
    __shared__ float Ws[64 * 36];
    const int tid = threadIdx.x;
    const int rowBase = blockIdx.y * 64;
    const int colBase = blockIdx.x * 64;
    const int og = tid & 15, ngr = tid >> 4;

    float acc[4][4];
#pragma unroll
    for (int i = 0; i < 4; ++i)
#pragma unroll
        for (int j = 0; j < 4; ++j) acc[i][j] = 0.f;

    for (int kk = 0; kk < 512; kk += 32) {
#pragma unroll
        for (int jj = 0; jj < 2; ++jj) {
            int idx = tid + jj * 256;
            int r = idx >> 3, c4 = (idx & 7) << 2;
            *(float4*)&Xs[r * 36 + c4] = *(const float4*)&X[(rowBase + r) * 512 + kk + c4];
            *(float4*)&Ws[r * 36 + c4] = *(const float4*)&W[(colBase + r) * 512 + kk + c4];
        }
        __syncthreads();
#pragma unroll
        for (int k4 = 0; k4 < 32; k4 += 4) {
            float4 xv[4], wv[4];
#pragma unroll
            for (int i = 0; i < 4; ++i) xv[i] = *(const float4*)&Xs[(ngr * 4 + i) * 36 + k4];
#pragma unroll
            for (int j = 0; j < 4; ++j) wv[j] = *(const float4*)&Ws[(og * 4 + j) * 36 + k4];
#pragma unroll
            for (int i = 0; i < 4; ++i)
#pragma unroll
                for (int j = 0; j < 4; ++j) {
                    acc[i][j] = fmaf(xv[i].x, wv[j].x, acc[i][j]);
                    acc[i][j] = fmaf(xv[i].y, wv[j].y, acc[i][j]);
                    acc[i][j] = fmaf(xv[i].z, wv[j].z, acc[i][j]);
                    acc[i][j] = fmaf(xv[i].w, wv[j].w, acc[i][j]);
                }
        }
        __syncthreads();
    }
#pragma unroll
    for (int i = 0; i < 4; ++i) {
        int n = rowBase + ngr * 4 + i;
        float vmul = valid[n] ? 1.f : 0.f;
#pragma unroll
        for (int j = 0; j < 4; ++j) {
            int o = colBase + og * 4 + j;
            out[n * ldo + o] = vmul * (acc[i][j] + bias[o]);
        }
    }
}

// ---------------------------------------------------------------------------
extern "C" void kernel_launch(void* const* d_in, const int* in_sizes, int n_in,
                              void* d_out, int out_size) {
    const float* a      = (const float*)d_in[0];
    const float* bv     = (const float*)d_in[1];
    const void*  mraw   = (const void*)d_in[2];
    const float* weight = (const float*)d_in[3];
    const float* ipw    = (const float*)d_in[4];
    const float* ipb    = (const float*)d_in[5];
    const float* ow     = (const float*)d_in[6];
    const float* ob     = (const float*)d_in[7];
    float* out = (float*)d_out;

    void *pctx, *pwt, *pbt, *pvalid;
    cudaGetSymbolAddress(&pctx, g_ctx);
    cudaGetSymbolAddress(&pwt, g_wt);
    cudaGetSymbolAddress(&pbt, g_bt);
    cudaGetSymbolAddress(&pvalid, g_valid);
    void *pah, *pal, *pbh, *pbl, *pwh, *pwl;
    cudaGetSymbolAddress(&pah, g_ah); cudaGetSymbolAddress(&pal, g_al);
    cudaGetSymbolAddress(&pbh, g_bvh); cudaGetSymbolAddress(&pbl, g_bvl);
    cudaGetSymbolAddress(&pwh, g_wh); cudaGetSymbolAddress(&pwl, g_wl);

    mask_detect_kernel<<<1, 256>>>((const unsigned int*)mraw);
    mask_repack_kernel<<<16384, 256>>>(mraw);

    conv_split_kernel<<<2048, 256>>>(a,  (__nv_bfloat16*)pah, (__nv_bfloat16*)pal, N_ACT * DMODEL / 4, 1);
    conv_split_kernel<<<2048, 256>>>(bv, (__nv_bfloat16*)pbh, (__nv_bfloat16*)pbl, N_KEY * DMODEL / 4, 1);
    conv_split_kernel<<<768, 256>>>(ipw, (__nv_bfloat16*)pwh, (__nv_bfloat16*)pwl, 3 * DMODEL * DMODEL / 4, 0);

    build_wt_kernel<<<(DKH * DMODEL + 255) / 256, 256>>>(ow, ob);

    proj_mma_kernel<<<dim3(12, 32), 256>>>(ipb);
    score_mma_kernel<<<dim3(32, 32, 4), 256>>>(weight);
    softmax_kernel<<<N_ACT, 256>>>(weight, out + N_ACT * DKH);
    ctx_mma_kernel<<<dim3(32, 4), 256>>>();

    gemm_nt_kernel<<<dim3(2, 64), 256>>>((const float*)pctx, (const float*)pwt,
                                         (const float*)pbt, out, DKH, (const int*)pvalid);
}

// round 11
// speedup vs baseline: 2.3096x; 1.0283x over previous
#include <cuda_runtime.h>
#include <cuda_bf16.h>
#include <cstdint>
#include <math.h>

#define N_ACT 4096
#define N_KEY 4096
#define DMODEL 512
#define NHEAD 4
#define DKH 128
#define NEGV (-1e9f)
#define QSCALE 0.08838834764831845f
#define LDT 40   // bf16 per smem tile row (32 data + 8 pad); 40*2=80B = 5*16B so uint4-safe

// ---------------------------------------------------------------------------
// scratch (static device allocations — allowed)
// ---------------------------------------------------------------------------
__device__ __nv_bfloat16 g_ah[N_ACT * DMODEL],  g_al[N_ACT * DMODEL];
__device__ __nv_bfloat16 g_bvh[N_KEY * DMODEL], g_bvl[N_KEY * DMODEL];
__device__ __nv_bfloat16 g_wh[3 * DMODEL * DMODEL], g_wl[3 * DMODEL * DMODEL];
__device__ __nv_bfloat16 g_qh[N_ACT * DMODEL],  g_ql[N_ACT * DMODEL];
__device__ __nv_bfloat16 g_kh[N_KEY * DMODEL],  g_kl[N_KEY * DMODEL];
__device__ __nv_bfloat16 g_vth[DMODEL * N_KEY], g_vtl[DMODEL * N_KEY];
__device__ float g_ctx[N_ACT * DMODEL];
__device__ float g_wt[DKH * DMODEL];
__device__ float g_bt[DKH];
__device__ int   g_valid[N_ACT];
__device__ float g_mb[N_ACT];
__device__ float g_zb[N_ACT];
__device__ float g_chz[NHEAD * N_ACT];
__device__ unsigned char g_mask[(size_t)N_ACT * N_KEY];
__device__ int   g_mflag;

__device__ __forceinline__ float nanfix(float x) {
    if (isnan(x)) return 0.f;
    if (isinf(x)) return x > 0.f ? 1.f : -1.f;
    return x;
}

// Fast exp for x <= 0, FFMA-only. ~2e-6 rel error.
__device__ __forceinline__ float fexp(float x) {
    x = fminf(x, 0.f);
    x = fmaxf(x, -87.0f);
    const float LOG2E = 1.4426950408889634f;
    float t = fmaf(x, LOG2E, 12582912.f);
    float jf = t - 12582912.f;
    int ji = (__float_as_int(t) & 0x7FFFFF) - 0x400000;
    float r = fmaf(x, LOG2E, -jf);
    float g = r * 0.6931471805599453f;
    float p = fmaf(g, 0.0083333333f, 0.0416666666f);
    p = fmaf(p, g, 0.1666666666f);
    p = fmaf(p, g, 0.5f);
    p = fmaf(p, g, 1.0f);
    p = fmaf(p, g, 1.0f);
    return __int_as_float((ji + 127) << 23) * p;
}

// ---------------------------------------------------------------------------
// warp mma: m16n8k16 bf16 (baseline PTX — compiles for plain sm_103 target)
// ---------------------------------------------------------------------------
__device__ __forceinline__ void mma_bf16(float c[4], const uint32_t a[4], const uint32_t b[2]) {
    asm volatile("mma.sync.aligned.m16n8k16.row.col.f32.bf16.bf16.f32 "
                 "{%0,%1,%2,%3}, {%4,%5,%6,%7}, {%8,%9}, {%0,%1,%2,%3};"
                 : "+f"(c[0]), "+f"(c[1]), "+f"(c[2]), "+f"(c[3])
                 : "r"(a[0]), "r"(a[1]), "r"(a[2]), "r"(a[3]), "r"(b[0]), "r"(b[1]));
}

// One 32-wide K chunk, 3-product split-bf16. A, B chunk tiles are [128][LDT] bf16.
// Fragment mapping identical to the R10 passing kernel.
__device__ __forceinline__ void mma_chunk3(
    float (&acc)[2][8][4],
    const __nv_bfloat16* __restrict__ Ah, const __nv_bfloat16* __restrict__ Al,
    const __nv_bfloat16* __restrict__ Bh, const __nv_bfloat16* __restrict__ Bl,
    int wm, int wn, int g, int t4)
{
#pragma unroll
    for (int kk = 0; kk < 2; ++kk) {
        const int k0 = kk * 16 + t4 * 2;
        uint32_t fah[2][4], fal[2][4];
#pragma unroll
        for (int mb = 0; mb < 2; ++mb) {
            const int m0 = wm * 32 + mb * 16 + g;
            fah[mb][0] = *(const uint32_t*)&Ah[m0 * LDT + k0];
            fah[mb][1] = *(const uint32_t*)&Ah[(m0 + 8) * LDT + k0];
            fah[mb][2] = *(const uint32_t*)&Ah[m0 * LDT + k0 + 8];
            fah[mb][3] = *(const uint32_t*)&Ah[(m0 + 8) * LDT + k0 + 8];
            fal[mb][0] = *(const uint32_t*)&Al[m0 * LDT + k0];
            fal[mb][1] = *(const uint32_t*)&Al[(m0 + 8) * LDT + k0];
            fal[mb][2] = *(const uint32_t*)&Al[m0 * LDT + k0 + 8];
            fal[mb][3] = *(const uint32_t*)&Al[(m0 + 8) * LDT + k0 + 8];
        }
#pragma unroll
        for (int nb = 0; nb < 8; ++nb) {
            const int n0 = wn * 64 + nb * 8 + g;
            uint32_t fbh[2], fbl[2];
            fbh[0] = *(const uint32_t*)&Bh[n0 * LDT + k0];
            fbh[1] = *(const uint32_t*)&Bh[n0 * LDT + k0 + 8];
            fbl[0] = *(const uint32_t*)&Bl[n0 * LDT + k0];
            fbl[1] = *(const uint32_t*)&Bl[n0 * LDT + k0 + 8];
#pragma unroll
            for (int mb = 0; mb < 2; ++mb) {
                mma_bf16(acc[mb][nb], fah[mb], fbh);
                mma_bf16(acc[mb][nb], fah[mb], fbl);
                mma_bf16(acc[mb][nb], fal[mb], fbh);
            }
        }
    }
}

// ---------------------------------------------------------------------------
// mask dtype detect + repack
// ---------------------------------------------------------------------------
__global__ void mask_detect_kernel(const unsigned int* __restrict__ m) {
    __shared__ int cF, cHi;
    if (threadIdx.x == 0) { cF = 0; cHi = 0; }
    __syncthreads();
    int lf = 0, lh = 0;
    for (int i = threadIdx.x; i < 16384; i += 256) {
        unsigned int w = m[i];
        if (w == 0x3F800000u) lf++;
        else if ((w & 0xFFFFFF00u) != 0u) lh++;
    }
    atomicAdd(&cF, lf);
    atomicAdd(&cHi, lh);
    __syncthreads();
    if (threadIdx.x == 0) {
        if (cF > 16) g_mflag = 2;
        else if (cHi > 16) g_mflag = 0;
        else g_mflag = 1;
    }
}

__global__ void mask_repack_kernel(const void* __restrict__ mraw) {
    const long long i4 = (long long)blockIdx.x * 256 + threadIdx.x;
    if (i4 * 4 >= (long long)N_ACT * N_KEY) return;
    const int flag = g_mflag;
    uchar4 o;
    if (flag == 0) {
        uchar4 b = ((const uchar4*)mraw)[i4];
        o.x = b.x ? 1 : 0; o.y = b.y ? 1 : 0; o.z = b.z ? 1 : 0; o.w = b.w ? 1 : 0;
    } else if (flag == 1) {
        int4 b = ((const int4*)mraw)[i4];
        o.x = b.x ? 1 : 0; o.y = b.y ? 1 : 0; o.z = b.z ? 1 : 0; o.w = b.w ? 1 : 0;
    } else {
        float4 b = ((const float4*)mraw)[i4];
        o.x = (b.x != 0.f) ? 1 : 0; o.y = (b.y != 0.f) ? 1 : 0;
        o.z = (b.z != 0.f) ? 1 : 0; o.w = (b.w != 0.f) ? 1 : 0;
    }
    ((uchar4*)g_mask)[i4] = o;
}

// fp32 -> split bf16 (hi + lo)
__global__ void conv_split_kernel(const float* __restrict__ src,
                                  __nv_bfloat16* __restrict__ hi,
                                  __nv_bfloat16* __restrict__ lo,
                                  int n4, int fix) {
    int i = blockIdx.x * 256 + threadIdx.x;
    if (i >= n4) return;
    float4 v = ((const float4*)src)[i];
    if (fix) { v.x = nanfix(v.x); v.y = nanfix(v.y); v.z = nanfix(v.z); v.w = nanfix(v.w); }
    float a[4] = {v.x, v.y, v.z, v.w};
#pragma unroll
    for (int j = 0; j < 4; ++j) {
        __nv_bfloat16 h = __float2bfloat16(a[j]);
        hi[i * 4 + j] = h;
        lo[i * 4 + j] = __float2bfloat16(a[j] - __bfloat162float(h));
    }
}

__global__ void build_wt_kernel(const float* __restrict__ ow,
                                const float* __restrict__ ob) {
    int idx = blockIdx.x * 256 + threadIdx.x;
    if (idx < DKH * DMODEL) {
        int dk = idx >> 9, c = idx & 511;
        g_wt[idx] = 0.25f * (ow[dk * DMODEL + c] + ow[(dk + DKH) * DMODEL + c] +
                             ow[(dk + 2 * DKH) * DMODEL + c] + ow[(dk + 3 * DKH) * DMODEL + c]);
    }
    if (idx < DKH)
        g_bt[idx] = 0.25f * (ob[idx] + ob[idx + DKH] + ob[idx + 2 * DKH] + ob[idx + 3 * DKH]);
}

// ---------------------------------------------------------------------------
// Bias stats pre-pass: per row n -> Mb, Zb, valid. (No EB storage.)
// ---------------------------------------------------------------------------
__global__ __launch_bounds__(256) void bias_stats_kernel(const float* __restrict__ weight) {
    __shared__ float red[256];
    __shared__ int sv;
    const int n = blockIdx.x, tid = threadIdx.x;
    if (tid == 0) sv = 0;
    __syncthreads();
    const long long base = (long long)n * N_KEY;
    float b[16];
    float mx = -INFINITY; int anym = 0;
#pragma unroll
    for (int j = 0; j < 4; ++j) {
        int m = tid * 4 + j * 1024;
        float4 w = *(const float4*)&weight[base + m];
        uchar4 mk = *(const uchar4*)&g_mask[base + m];
        float b0 = mk.x ? nanfix(w.x) : NEGV;
        float b1 = mk.y ? nanfix(w.y) : NEGV;
        float b2 = mk.z ? nanfix(w.z) : NEGV;
        float b3 = mk.w ? nanfix(w.w) : NEGV;
        b[j*4+0] = b0; b[j*4+1] = b1; b[j*4+2] = b2; b[j*4+3] = b3;
        anym |= (mk.x | mk.y | mk.z | mk.w);
        mx = fmaxf(fmaxf(fmaxf(mx, b0), fmaxf(b1, b2)), b3);
    }
    if (anym) atomicOr(&sv, 1);
    red[tid] = mx;
    __syncthreads();
    for (int s = 128; s > 0; s >>= 1) {
        if (tid < s) red[tid] = fmaxf(red[tid], red[tid + s]);
        __syncthreads();
    }
    float Mb = red[0];
    __syncthreads();
    float zs = 0.f;
#pragma unroll
    for (int j = 0; j < 16; ++j) zs += fexp(b[j] - Mb);
    red[tid] = zs;
    __syncthreads();
    for (int s = 128; s > 0; s >>= 1) {
        if (tid < s) red[tid] += red[tid + s];
        __syncthreads();
    }
    if (tid == 0) { g_mb[n] = Mb; g_zb[n] = red[0]; g_valid[n] = sv; }
}

// ---------------------------------------------------------------------------
// QKV projection: grid (12, 32), 256 threads (unchanged from R10, passing).
// ---------------------------------------------------------------------------
__global__ __launch_bounds__(256) void proj_mma_kernel(const float* __restrict__ ipb) {
    __shared__ __align__(16) unsigned char smraw[4 * 128 * LDT * 2];
    __nv_bfloat16* sm = (__nv_bfloat16*)smraw;
    __nv_bfloat16* sAh = sm;
    __nv_bfloat16* sAl = sm + 128 * LDT;
    __nv_bfloat16* sBh = sm + 2 * 128 * LDT;
    __nv_bfloat16* sBl = sm + 3 * 128 * LDT;
    const int ot = blockIdx.x, nt = blockIdx.y;
    const int which = ot >> 2;
    const __nv_bfloat16* Xh = (which == 0) ? g_ah : g_bvh;
    const __nv_bfloat16* Xl = (which == 0) ? g_al : g_bvl;
    const __nv_bfloat16* Wh = g_wh + (long long)ot * 128 * DMODEL;
    const __nv_bfloat16* Wl = g_wl + (long long)ot * 128 * DMODEL;

    const int tid = threadIdx.x;
    const int lane = tid & 31, warp = tid >> 5;
    const int wm = warp >> 1, wn = warp & 1;
    const int g = lane >> 2, t4 = lane & 3;
    const int lr = tid >> 2, lc = (tid & 3) * 8;

    float acc[2][8][4];
#pragma unroll
    for (int i = 0; i < 2; ++i)
#pragma unroll
        for (int j = 0; j < 8; ++j)
#pragma unroll
            for (int r = 0; r < 4; ++r) acc[i][j][r] = 0.f;

    for (int c = 0; c < 16; ++c) {
        const long long co = (long long)c * 32 + lc;
        *(uint4*)&sAh[lr * LDT + lc] = *(const uint4*)&Xh[((long long)nt * 128 + lr) * DMODEL + co];
        *(uint4*)&sAh[(lr + 64) * LDT + lc] = *(const uint4*)&Xh[((long long)nt * 128 + lr + 64) * DMODEL + co];
        *(uint4*)&sAl[lr * LDT + lc] = *(const uint4*)&Xl[((long long)nt * 128 + lr) * DMODEL + co];
        *(uint4*)&sAl[(lr + 64) * LDT + lc] = *(const uint4*)&Xl[((long long)nt * 128 + lr + 64) * DMODEL + co];
        *(uint4*)&sBh[lr * LDT + lc] = *(const uint4*)&Wh[(long long)lr * DMODEL + co];
        *(uint4*)&sBh[(lr + 64) * LDT + lc] = *(const uint4*)&Wh[(long long)(lr + 64) * DMODEL + co];
        *(uint4*)&sBl[lr * LDT + lc] = *(const uint4*)&Wl[(long long)lr * DMODEL + co];
        *(uint4*)&sBl[(lr + 64) * LDT + lc] = *(const uint4*)&Wl[(long long)(lr + 64) * DMODEL + co];
        __syncthreads();
        mma_chunk3(acc, sAh, sAl, sBh, sBl, wm, wn, g, t4);
        __syncthreads();
    }

    const float scale = (which == 0) ? QSCALE : 1.f;
#pragma unroll
    for (int mb = 0; mb < 2; ++mb)
#pragma unroll
        for (int nb = 0; nb < 8; ++nb)
#pragma unroll
            for (int half = 0; half < 2; ++half) {
                const long long n = (long long)nt * 128 + wm * 32 + mb * 16 + g + half * 8;
                const int og = ot * 128 + wn * 64 + nb * 8 + t4 * 2;
                float v0 = scale * (acc[mb][nb][half * 2 + 0] + ipb[og]);
                float v1 = scale * (acc[mb][nb][half * 2 + 1] + ipb[og + 1]);
                __nv_bfloat16 h0 = __float2bfloat16(v0);
                __nv_bfloat16 l0 = __float2bfloat16(v0 - __bfloat162float(h0));
                __nv_bfloat16 h1 = __float2bfloat16(v1);
                __nv_bfloat16 l1 = __float2bfloat16(v1 - __bfloat162float(h1));
                if (which == 0) {
                    g_qh[n * DMODEL + og] = h0; g_qh[n * DMODEL + og + 1] = h1;
                    g_ql[n * DMODEL + og] = l0; g_ql[n * DMODEL + og + 1] = l1;
                } else if (which == 1) {
                    const int c = og - 512;
                    g_kh[n * DMODEL + c] = h0; g_kh[n * DMODEL + c + 1] = h1;
                    g_kl[n * DMODEL + c] = l0; g_kl[n * DMODEL + c + 1] = l1;
                } else {
                    const long long d = og - 1024;
                    g_vth[d * N_KEY + n] = h0; g_vth[(d + 1) * N_KEY + n] = h1;
                    g_vtl[d * N_KEY + n] = l0; g_vtl[(d + 1) * N_KEY + n] = l1;
                }
            }
}

// ---------------------------------------------------------------------------
// FUSED flash attention: grid (32 nt, 4 h), 256 threads, 1 CTA/SM.
// smem (bf16 units): sQ hi/lo 4 chunks [4][128][LDT], sP hi/lo same,
//                    sKV hi/lo 1 chunk, then float sRed[128*2].
// fp32 bias overlay lives on top of the sP region between its uses.
// ---------------------------------------------------------------------------
#define SQ_OFF   0
#define SQL_OFF  (4 * 128 * LDT)
#define SP_OFF   (2 * 4 * 128 * LDT)
#define SPL_OFF  (3 * 4 * 128 * LDT)
#define SKV_OFF  (4 * 4 * 128 * LDT)
#define SKVL_OFF (4 * 4 * 128 * LDT + 128 * LDT)
#define SMEM_BF16_TOTAL (4 * 4 * 128 * LDT + 2 * 128 * LDT)
#define FUSED_SMEM_BYTES (SMEM_BF16_TOTAL * 2 + 128 * 2 * 4)

__global__ __launch_bounds__(256, 1) void fused_attn_kernel(const float* __restrict__ weight) {
    extern __shared__ __align__(16) unsigned char smem_raw[];
    __nv_bfloat16* sm = (__nv_bfloat16*)smem_raw;
    __nv_bfloat16* sQh = sm + SQ_OFF;
    __nv_bfloat16* sQl = sm + SQL_OFF;
    __nv_bfloat16* sPh = sm + SP_OFF;
    __nv_bfloat16* sPl = sm + SPL_OFF;
    __nv_bfloat16* sKh = sm + SKV_OFF;
    __nv_bfloat16* sKl = sm + SKVL_OFF;
    float* sBias = (float*)(sm + SP_OFF);            // overlay, 128*132 floats max
    float* sRed  = (float*)(sm + SMEM_BF16_TOTAL);   // 128*2 floats

    const int nt = blockIdx.x, h = blockIdx.y;
    const int tid = threadIdx.x;
    const int lane = tid & 31, warp = tid >> 5;
    const int wm = warp >> 1, wn = warp & 1;
    const int g = lane >> 2, t4 = lane & 3;
    const long long nBase = (long long)nt * 128;

    // stage Q (4 chunks, hi+lo): 2048 uint4 per array
    for (int u = tid; u < 2048; u += 256) {
        const int c = u >> 9;
        const int r = (u >> 2) & 127;
        const int cc = (u & 3) * 8;
        const long long gofs = (nBase + r) * DMODEL + h * DKH + c * 32 + cc;
        *(uint4*)&sQh[(c * 128 + r) * LDT + cc] = *(const uint4*)&g_qh[gofs];
        *(uint4*)&sQl[(c * 128 + r) * LDT + cc] = *(const uint4*)&g_ql[gofs];
    }

    float acc_o[2][8][4];
#pragma unroll
    for (int i = 0; i < 2; ++i)
#pragma unroll
        for (int j = 0; j < 8; ++j)
#pragma unroll
            for (int r = 0; r < 4; ++r) acc_o[i][j][r] = 0.f;

    float zh[4] = {0.f, 0.f, 0.f, 0.f};
    float ch[4] = {0.f, 0.f, 0.f, 0.f};
    float Mold[4] = {-INFINITY, -INFINITY, -INFINITY, -INFINITY};
    float Mbr[4];
#pragma unroll
    for (int mb = 0; mb < 2; ++mb)
#pragma unroll
        for (int half = 0; half < 2; ++half)
            Mbr[mb * 2 + half] = g_mb[nBase + wm * 32 + mb * 16 + half * 8 + g];

    __syncthreads();

    for (int mt = 0; mt < N_KEY / 128; ++mt) {
        const long long mBase = (long long)mt * 128;
        float acc_s[2][8][4];
#pragma unroll
        for (int i = 0; i < 2; ++i)
#pragma unroll
            for (int j = 0; j < 8; ++j)
#pragma unroll
                for (int r = 0; r < 4; ++r) acc_s[i][j][r] = 0.f;

        // ---- QK^T over 4 K-chunks ----
        for (int c = 0; c < 4; ++c) {
            for (int u = tid; u < 512; u += 256) {
                const int r = u >> 2, cc = (u & 3) * 8;
                const long long gofs = (mBase + r) * DMODEL + h * DKH + c * 32 + cc;
                *(uint4*)&sKh[r * LDT + cc] = *(const uint4*)&g_kh[gofs];
                *(uint4*)&sKl[r * LDT + cc] = *(const uint4*)&g_kl[gofs];
            }
            __syncthreads();
            mma_chunk3(acc_s, sQh + c * 128 * LDT, sQl + c * 128 * LDT, sKh, sKl, wm, wn, g, t4);
            __syncthreads();
        }

        // ---- bias add + tile row max (loop1) ----
#pragma unroll
        for (int mb = 0; mb < 2; ++mb)
#pragma unroll
            for (int half = 0; half < 2; ++half) {
                const int rl = wm * 32 + mb * 16 + half * 8 + g;
                const long long n = nBase + rl;
                float smax = -INFINITY;
#pragma unroll
                for (int nb = 0; nb < 8; ++nb) {
                    const int col = wn * 64 + nb * 8 + t4 * 2;
                    const long long m = mBase + col;
                    const float2 w = *(const float2*)&weight[n * N_KEY + m];
                    const unsigned short mk = *(const unsigned short*)&g_mask[n * N_KEY + m];
                    const float b0 = (mk & 0xFF) ? nanfix(w.x) : NEGV;
                    const float b1 = (mk >> 8)   ? nanfix(w.y) : NEGV;
                    sBias[rl * 132 + col] = b0;
                    sBias[rl * 132 + col + 1] = b1;
                    const float s0 = acc_s[mb][nb][half * 2 + 0] + b0;
                    const float s1 = acc_s[mb][nb][half * 2 + 1] + b1;
                    acc_s[mb][nb][half * 2 + 0] = s0;
                    acc_s[mb][nb][half * 2 + 1] = s1;
                    smax = fmaxf(smax, fmaxf(s0, s1));
                }
                smax = fmaxf(smax, __shfl_xor_sync(0xffffffffu, smax, 1));
                smax = fmaxf(smax, __shfl_xor_sync(0xffffffffu, smax, 2));
                if (t4 == 0) sRed[rl * 2 + wn] = smax;
            }
        __syncthreads();

        // ---- online softmax update (loop2) ----
#pragma unroll
        for (int mb = 0; mb < 2; ++mb)
#pragma unroll
            for (int half = 0; half < 2; ++half) {
                const int slot = mb * 2 + half;
                const int rl = wm * 32 + mb * 16 + half * 8 + g;
                const float Mtile = fmaxf(sRed[rl * 2], sRed[rl * 2 + 1]);
                const float Mnew = fmaxf(Mold[slot], Mtile);
                const float alpha = fexp(Mold[slot] - Mnew);
                Mold[slot] = Mnew;
                float z = zh[slot] * alpha;
                float cc = ch[slot] * alpha;
#pragma unroll
                for (int nb = 0; nb < 8; ++nb) {
                    const int col = wn * 64 + nb * 8 + t4 * 2;
#pragma unroll
                    for (int r = 0; r < 2; ++r) {
                        const float s = acc_s[mb][nb][half * 2 + r];
                        const float p = fexp(s - Mnew);
                        acc_s[mb][nb][half * 2 + r] = p;
                        z += p;
                        const float b = sBias[rl * 132 + col + r];
                        cc = fmaf(fexp(b - Mbr[slot]), p, cc);
                    }
                    acc_o[mb][nb][half * 2 + 0] *= alpha;
                    acc_o[mb][nb][half * 2 + 1] *= alpha;
                }
                zh[slot] = z;
                ch[slot] = cc;
            }
        __syncthreads();   // all bias reads done before P overwrites the overlay

        // ---- write P (split bf16) into smem chunk layout (loop3) ----
#pragma unroll
        for (int mb = 0; mb < 2; ++mb)
#pragma unroll
            for (int half = 0; half < 2; ++half) {
                const int rl = wm * 32 + mb * 16 + half * 8 + g;
#pragma unroll
                for (int nb = 0; nb < 8; ++nb) {
                    const int col = wn * 64 + nb * 8 + t4 * 2;
                    const int chunk = col >> 5, c32 = col & 31;
                    const float p0 = acc_s[mb][nb][half * 2 + 0];
                    const float p1 = acc_s[mb][nb][half * 2 + 1];
                    const __nv_bfloat16 h0 = __float2bfloat16(p0);
                    const __nv_bfloat16 h1 = __float2bfloat16(p1);
                    const __nv_bfloat16 l0 = __float2bfloat16(p0 - __bfloat162float(h0));
                    const __nv_bfloat16 l1 = __float2bfloat16(p1 - __bfloat162float(h1));
                    const uint32_t ph = (uint32_t)__bfloat16_as_ushort(h0) |
                                        ((uint32_t)__bfloat16_as_ushort(h1) << 16);
                    const uint32_t pl = (uint32_t)__bfloat16_as_ushort(l0) |
                                        ((uint32_t)__bfloat16_as_ushort(l1) << 16);
                    *(uint32_t*)&sPh[(chunk * 128 + rl) * LDT + c32] = ph;
                    *(uint32_t*)&sPl[(chunk * 128 + rl) * LDT + c32] = pl;
                }
            }

        // ---- ctx accumulate: P @ V^T over 4 m-chunks ----
        for (int c = 0; c < 4; ++c) {
            for (int u = tid; u < 512; u += 256) {
                const int r = u >> 2, cc2 = (u & 3) * 8;
                const long long gofs = (long long)(h * DKH + r) * N_KEY + mBase + c * 32 + cc2;
                *(uint4*)&sKh[r * LDT + cc2] = *(const uint4*)&g_vth[gofs];
                *(uint4*)&sKl[r * LDT + cc2] = *(const uint4*)&g_vtl[gofs];
            }
            __syncthreads();
            mma_chunk3(acc_o, sPh + c * 128 * LDT, sPl + c * 128 * LDT, sKh, sKl, wm, wn, g, t4);
            __syncthreads();
        }
    }

    // ---- final reductions of zh, ch across t4 and wn ----
    float zt[4], ct[4];
#pragma unroll
    for (int slot = 0; slot < 4; ++slot) {
        float z = zh[slot];
        z += __shfl_xor_sync(0xffffffffu, z, 1);
        z += __shfl_xor_sync(0xffffffffu, z, 2);
        zh[slot] = z;
        float c = ch[slot];
        c += __shfl_xor_sync(0xffffffffu, c, 1);
        c += __shfl_xor_sync(0xffffffffu, c, 2);
        ch[slot] = c;
    }
#pragma unroll
    for (int mb = 0; mb < 2; ++mb)
#pragma unroll
        for (int half = 0; half < 2; ++half) {
            const int rl = wm * 32 + mb * 16 + half * 8 + g;
            if (t4 == 0) sRed[rl * 2 + wn] = zh[mb * 2 + half];
        }
    __syncthreads();
#pragma unroll
    for (int mb = 0; mb < 2; ++mb)
#pragma unroll
        for (int half = 0; half < 2; ++half) {
            const int rl = wm * 32 + mb * 16 + half * 8 + g;
            zt[mb * 2 + half] = sRed[rl * 2] + sRed[rl * 2 + 1];
        }
    __syncthreads();
#pragma unroll
    for (int mb = 0; mb < 2; ++mb)
#pragma unroll
        for (int half = 0; half < 2; ++half) {
            const int rl = wm * 32 + mb * 16 + half * 8 + g;
            if (t4 == 0) sRed[rl * 2 + wn] = ch[mb * 2 + half];
        }
    __syncthreads();
#pragma unroll
    for (int mb = 0; mb < 2; ++mb)
#pragma unroll
        for (int half = 0; half < 2; ++half) {
            const int rl = wm * 32 + mb * 16 + half * 8 + g;
            ct[mb * 2 + half] = sRed[rl * 2] + sRed[rl * 2 + 1];
        }

    // ---- outputs ----
#pragma unroll
    for (int mb = 0; mb < 2; ++mb)
#pragma unroll
        for (int half = 0; half < 2; ++half) {
            const int slot = mb * 2 + half;
            const int rl = wm * 32 + mb * 16 + half * 8 + g;
            const long long n = nBase + rl;
            const float zi = 1.f / zt[slot];
            if (t4 == 0 && wn == 0) g_chz[h * N_ACT + n] = ct[slot] * zi;
#pragma unroll
            for (int nb = 0; nb < 8; ++nb) {
                const int d = wn * 64 + nb * 8 + t4 * 2;
                float2 o;
                o.x = acc_o[mb][nb][half * 2 + 0] * zi;
                o.y = acc_o[mb][nb][half * 2 + 1] * zi;
                *(float2*)&g_ctx[n * DMODEL + h * DKH + d] = o;
            }
        }
}

// ---------------------------------------------------------------------------
// influence finisher
// ---------------------------------------------------------------------------
__global__ void influence_kernel(float* __restrict__ inf_out) {
    const int n = blockIdx.x * 256 + threadIdx.x;
    if (n >= N_ACT) return;
    const float s = g_chz[n] + g_chz[N_ACT + n] + g_chz[2 * N_ACT + n] + g_chz[3 * N_ACT + n];
    inf_out[n] = g_valid[n] ? (0.25f * s / g_zb[n]) : 0.f;
}

// ---------------------------------------------------------------------------
// Topic GEMM (FFMA, small): C[n][o] = ctx . wt[o] + bt[o], valid-gated.
// ---------------------------------------------------------------------------
__global__ __launch_bounds__(256) void gemm_nt_kernel(
    const float* __restrict__ X, const float* __restrict__ W,
    const float* __restrict__ bias, float* __restrict__ out,
    int ldo, const int* __restrict__ valid)
{
    __shared__ float Xs[64 * 36];
    __shared__ float Ws[64 * 36];
    const int tid = threadIdx.x;
    const int rowBase = blockIdx.y * 64;
    const int colBase = blockIdx.x * 64;
    const int og = tid & 15, ngr = tid >> 4;

    float acc[4][4];
#pragma unroll
    for (int i = 0; i < 4; ++i)
#pragma unroll
        for (int j = 0; j < 4; ++j) acc[i][j] = 0.f;

    for (int kk = 0; kk < 512; kk += 32) {
#pragma unroll
        for (int jj = 0; jj < 2; ++jj) {
            int idx = tid + jj * 256;
            int r = idx >> 3, c4 = (idx & 7) << 2;
            *(float4*)&Xs[r * 36 + c4] = *(const float4*)&X[(rowBase + r) * 512 + kk + c4];
            *(float4*)&Ws[r * 36 + c4] = *(const float4*)&W[(colBase + r) * 512 + kk + c4];
        }
        __syncthreads();
#pragma unroll
        for (int k4 = 0; k4 < 32; k4 += 4) {
            float4 xv[4], wv[4];
#pragma unroll
            for (int i = 0; i < 4; ++i) xv[i] = *(const float4*)&Xs[(ngr * 4 + i) * 36 + k4];
#pragma unroll
            for (int j = 0; j < 4; ++j) wv[j] = *(const float4*)&Ws[(og * 4 + j) * 36 + k4];
#pragma unroll
            for (int i = 0; i < 4; ++i)
#pragma unroll
                for (int j = 0; j < 4; ++j) {
                    acc[i][j] = fmaf(xv[i].x, wv[j].x, acc[i][j]);
                    acc[i][j] = fmaf(xv[i].y, wv[j].y, acc[i][j]);
                    acc[i][j] = fmaf(xv[i].z, wv[j].z, acc[i][j]);
                    acc[i][j] = fmaf(xv[i].w, wv[j].w, acc[i][j]);
                }
        }
        __syncthreads();
    }
#pragma unroll
    for (int i = 0; i < 4; ++i) {
        int n = rowBase + ngr * 4 + i;
        float vmul = valid[n] ? 1.f : 0.f;
#pragma unroll
        for (int j = 0; j < 4; ++j) {
            int o = colBase + og * 4 + j;
            out[n * ldo + o] = vmul * (acc[i][j] + bias[o]);
        }
    }
}

// ---------------------------------------------------------------------------
extern "C" void kernel_launch(void* const* d_in, const int* in_sizes, int n_in,
                              void* d_out, int out_size) {
    const float* a      = (const float*)d_in[0];
    const float* bv     = (const float*)d_in[1];
    const void*  mraw   = (const void*)d_in[2];
    const float* weight = (const float*)d_in[3];
    const float* ipw    = (const float*)d_in[4];
    const float* ipb    = (const float*)d_in[5];
    const float* ow     = (const float*)d_in[6];
    const float* ob     = (const float*)d_in[7];
    float* out = (float*)d_out;

    void *pctx, *pwt, *pbt, *pvalid;
    cudaGetSymbolAddress(&pctx, g_ctx);
    cudaGetSymbolAddress(&pwt, g_wt);
    cudaGetSymbolAddress(&pbt, g_bt);
    cudaGetSymbolAddress(&pvalid, g_valid);
    void *pah, *pal, *pbh, *pbl, *pwh, *pwl;
    cudaGetSymbolAddress(&pah, g_ah); cudaGetSymbolAddress(&pal, g_al);
    cudaGetSymbolAddress(&pbh, g_bvh); cudaGetSymbolAddress(&pbl, g_bvl);
    cudaGetSymbolAddress(&pwh, g_wh); cudaGetSymbolAddress(&pwl, g_wl);

    cudaFuncSetAttribute(fused_attn_kernel, cudaFuncAttributeMaxDynamicSharedMemorySize,
                         FUSED_SMEM_BYTES);

    mask_detect_kernel<<<1, 256>>>((const unsigned int*)mraw);
    mask_repack_kernel<<<16384, 256>>>(mraw);

    conv_split_kernel<<<2048, 256>>>(a,  (__nv_bfloat16*)pah, (__nv_bfloat16*)pal, N_ACT * DMODEL / 4, 1);
    conv_split_kernel<<<2048, 256>>>(bv, (__nv_bfloat16*)pbh, (__nv_bfloat16*)pbl, N_KEY * DMODEL / 4, 1);
    conv_split_kernel<<<768, 256>>>(ipw, (__nv_bfloat16*)pwh, (__nv_bfloat16*)pwl, 3 * DMODEL * DMODEL / 4, 0);

    build_wt_kernel<<<(DKH * DMODEL + 255) / 256, 256>>>(ow, ob);

    proj_mma_kernel<<<dim3(12, 32), 256>>>(ipb);
    bias_stats_kernel<<<N_ACT, 256>>>(weight);

    fused_attn_kernel<<<dim3(32, 4), 256, FUSED_SMEM_BYTES>>>(weight);

    influence_kernel<<<16, 256>>>(out + N_ACT * DKH);

    gemm_nt_kernel<<<dim3(2, 64), 256>>>((const float*)pctx, (const float*)pwt,
                                         (const float*)pbt, out, DKH, (const int*)pvalid);
}

// round 13
// speedup vs baseline: 2.6435x; 1.1446x over previous
#include <cuda_runtime.h>
#include <cuda_bf16.h>
#include <cstdint>
#include <math.h>

#define N_ACT 4096
#define N_KEY 4096
#define DMODEL 512
#define NHEAD 4
#define DKH 128
#define NEGV (-1e9f)
#define QSCALE 0.08838834764831845f
#define LDT 40   // bf16 per smem tile row (32 data + 8 pad); 80B rows, 16B-aligned

// ---------------------------------------------------------------------------
// scratch (static device allocations — allowed)
// ---------------------------------------------------------------------------
__device__ __nv_bfloat16 g_ah[N_ACT * DMODEL],  g_al[N_ACT * DMODEL];
__device__ __nv_bfloat16 g_bvh[N_KEY * DMODEL], g_bvl[N_KEY * DMODEL];
__device__ __nv_bfloat16 g_wh[3 * DMODEL * DMODEL], g_wl[3 * DMODEL * DMODEL];
__device__ __nv_bfloat16 g_qh[N_ACT * DMODEL],  g_ql[N_ACT * DMODEL];
__device__ __nv_bfloat16 g_kh[N_KEY * DMODEL],  g_kl[N_KEY * DMODEL];
__device__ __nv_bfloat16 g_vth[DMODEL * N_KEY], g_vtl[DMODEL * N_KEY];
__device__ float g_ctx[N_ACT * DMODEL];
__device__ float g_wt[DKH * DMODEL];
__device__ float g_bt[DKH];
__device__ int   g_valid[N_ACT];
__device__ float g_mb[N_ACT];
__device__ float g_zb[N_ACT];
__device__ float g_chz[NHEAD * N_ACT];
__device__ unsigned char g_mask[(size_t)N_ACT * N_KEY];
__device__ int   g_mflag;

__device__ __forceinline__ float nanfix(float x) {
    if (isnan(x)) return 0.f;
    if (isinf(x)) return x > 0.f ? 1.f : -1.f;
    return x;
}

// Fast exp for x <= 0, FFMA-only. ~2e-6 rel error.
__device__ __forceinline__ float fexp(float x) {
    x = fminf(x, 0.f);
    x = fmaxf(x, -87.0f);
    const float LOG2E = 1.4426950408889634f;
    float t = fmaf(x, LOG2E, 12582912.f);
    float jf = t - 12582912.f;
    int ji = (__float_as_int(t) & 0x7FFFFF) - 0x400000;
    float r = fmaf(x, LOG2E, -jf);
    float g = r * 0.6931471805599453f;
    float p = fmaf(g, 0.0083333333f, 0.0416666666f);
    p = fmaf(p, g, 0.1666666666f);
    p = fmaf(p, g, 0.5f);
    p = fmaf(p, g, 1.0f);
    p = fmaf(p, g, 1.0f);
    return __int_as_float((ji + 127) << 23) * p;
}

__device__ __forceinline__ uint32_t smem_to_u32(const void* p) {
    uint32_t a;
    asm("{ .reg .u64 t; cvta.to.shared.u64 t, %1; cvt.u32.u64 %0, t; }" : "=r"(a) : "l"(p));
    return a;
}

// ---------------------------------------------------------------------------
// warp mma + ldmatrix (baseline PTX — compiles on the plain sm_103 target)
// ---------------------------------------------------------------------------
__device__ __forceinline__ void mma_bf16(float c[4], const uint32_t a[4], const uint32_t b[2]) {
    asm volatile("mma.sync.aligned.m16n8k16.row.col.f32.bf16.bf16.f32 "
                 "{%0,%1,%2,%3}, {%4,%5,%6,%7}, {%8,%9}, {%0,%1,%2,%3};"
                 : "+f"(c[0]), "+f"(c[1]), "+f"(c[2]), "+f"(c[3])
                 : "r"(a[0]), "r"(a[1]), "r"(a[2]), "r"(a[3]), "r"(b[0]), "r"(b[1]));
}

__device__ __forceinline__ void ldsm_x4(uint32_t r[4], uint32_t addr) {
    asm volatile("ldmatrix.sync.aligned.m8n8.x4.shared.b16 {%0,%1,%2,%3}, [%4];"
                 : "=r"(r[0]), "=r"(r[1]), "=r"(r[2]), "=r"(r[3]) : "r"(addr));
}

// One 32-wide K chunk, 3-product split-bf16, fragments via ldmatrix.
// A,B chunk tiles are [128][LDT] bf16 at shared addrs aH/aL/bH/bL.
// acc[mb][nb]: row = wm*32+mb*16+g (+8), col = wn*64+nb*8+t4*2 (+1) — same map
// as the passing R10/R11 kernels.
__device__ __forceinline__ void mma_chunk3(
    float (&acc)[2][8][4],
    uint32_t aH, uint32_t aL, uint32_t bH, uint32_t bL,
    int lane, int wm, int wn)
{
    const int la15 = lane & 15;
    const int lhi  = (lane >> 4) << 3;                   // A k-half select
    const int brow = ((lane >> 4) << 3) + (lane & 7);    // B row within 16-pair
    const int bko  = ((lane >> 3) & 1) << 3;             // B k-half select
#pragma unroll
    for (int kk = 0; kk < 2; ++kk) {
        const int kb = kk * 16;
        uint32_t fah[2][4], fal[2][4];
#pragma unroll
        for (int mb = 0; mb < 2; ++mb) {
            const uint32_t off = (uint32_t)((wm * 32 + mb * 16 + la15) * LDT + kb + lhi) * 2;
            ldsm_x4(fah[mb], aH + off);
            ldsm_x4(fal[mb], aL + off);
        }
#pragma unroll
        for (int nbp = 0; nbp < 4; ++nbp) {
            const uint32_t off = (uint32_t)((wn * 64 + nbp * 16 + brow) * LDT + kb + bko) * 2;
            uint32_t fbh[4], fbl[4];
            ldsm_x4(fbh, bH + off);
            ldsm_x4(fbl, bL + off);
#pragma unroll
            for (int mb = 0; mb < 2; ++mb) {
                mma_bf16(acc[mb][nbp * 2],     fah[mb], fbh);
                mma_bf16(acc[mb][nbp * 2],     fah[mb], fbl);
                mma_bf16(acc[mb][nbp * 2],     fal[mb], fbh);
                mma_bf16(acc[mb][nbp * 2 + 1], fah[mb], fbh + 2);
                mma_bf16(acc[mb][nbp * 2 + 1], fah[mb], fbl + 2);
                mma_bf16(acc[mb][nbp * 2 + 1], fal[mb], fbh + 2);
            }
        }
    }
}

// ---------------------------------------------------------------------------
// mask dtype detect + repack
// ---------------------------------------------------------------------------
__global__ void mask_detect_kernel(const unsigned int* __restrict__ m) {
    __shared__ int cF, cHi;
    if (threadIdx.x == 0) { cF = 0; cHi = 0; }
    __syncthreads();
    int lf = 0, lh = 0;
    for (int i = threadIdx.x; i < 16384; i += 256) {
        unsigned int w = m[i];
        if (w == 0x3F800000u) lf++;
        else if ((w & 0xFFFFFF00u) != 0u) lh++;
    }
    atomicAdd(&cF, lf);
    atomicAdd(&cHi, lh);
    __syncthreads();
    if (threadIdx.x == 0) {
        if (cF > 16) g_mflag = 2;
        else if (cHi > 16) g_mflag = 0;
        else g_mflag = 1;
    }
}

__global__ void mask_repack_kernel(const void* __restrict__ mraw) {
    const long long i4 = (long long)blockIdx.x * 256 + threadIdx.x;
    if (i4 * 4 >= (long long)N_ACT * N_KEY) return;
    const int flag = g_mflag;
    uchar4 o;
    if (flag == 0) {
        uchar4 b = ((const uchar4*)mraw)[i4];
        o.x = b.x ? 1 : 0; o.y = b.y ? 1 : 0; o.z = b.z ? 1 : 0; o.w = b.w ? 1 : 0;
    } else if (flag == 1) {
        int4 b = ((const int4*)mraw)[i4];
        o.x = b.x ? 1 : 0; o.y = b.y ? 1 : 0; o.z = b.z ? 1 : 0; o.w = b.w ? 1 : 0;
    } else {
        float4 b = ((const float4*)mraw)[i4];
        o.x = (b.x != 0.f) ? 1 : 0; o.y = (b.y != 0.f) ? 1 : 0;
        o.z = (b.z != 0.f) ? 1 : 0; o.w = (b.w != 0.f) ? 1 : 0;
    }
    ((uchar4*)g_mask)[i4] = o;
}

// fp32 -> split bf16 (hi + lo)
__global__ void conv_split_kernel(const float* __restrict__ src,
                                  __nv_bfloat16* __restrict__ hi,
                                  __nv_bfloat16* __restrict__ lo,
                                  int n4, int fix) {
    int i = blockIdx.x * 256 + threadIdx.x;
    if (i >= n4) return;
    float4 v = ((const float4*)src)[i];
    if (fix) { v.x = nanfix(v.x); v.y = nanfix(v.y); v.z = nanfix(v.z); v.w = nanfix(v.w); }
    float a[4] = {v.x, v.y, v.z, v.w};
#pragma unroll
    for (int j = 0; j < 4; ++j) {
        __nv_bfloat16 h = __float2bfloat16(a[j]);
        hi[i * 4 + j] = h;
        lo[i * 4 + j] = __float2bfloat16(a[j] - __bfloat162float(h));
    }
}

__global__ void build_wt_kernel(const float* __restrict__ ow,
                                const float* __restrict__ ob) {
    int idx = blockIdx.x * 256 + threadIdx.x;
    if (idx < DKH * DMODEL) {
        int dk = idx >> 9, c = idx & 511;
        g_wt[idx] = 0.25f * (ow[dk * DMODEL + c] + ow[(dk + DKH) * DMODEL + c] +
                             ow[(dk + 2 * DKH) * DMODEL + c] + ow[(dk + 3 * DKH) * DMODEL + c]);
    }
    if (idx < DKH)
        g_bt[idx] = 0.25f * (ob[idx] + ob[idx + DKH] + ob[idx + 2 * DKH] + ob[idx + 3 * DKH]);
}

// ---------------------------------------------------------------------------
// Bias stats pre-pass: per row n -> Mb, Zb, valid.
// ---------------------------------------------------------------------------
__global__ __launch_bounds__(256) void bias_stats_kernel(const float* __restrict__ weight) {
    __shared__ float red[256];
    __shared__ int sv;
    const int n = blockIdx.x, tid = threadIdx.x;
    if (tid == 0) sv = 0;
    __syncthreads();
    const long long base = (long long)n * N_KEY;
    float b[16];
    float mx = -INFINITY; int anym = 0;
#pragma unroll
    for (int j = 0; j < 4; ++j) {
        int m = tid * 4 + j * 1024;
        float4 w = *(const float4*)&weight[base + m];
        uchar4 mk = *(const uchar4*)&g_mask[base + m];
        float b0 = mk.x ? nanfix(w.x) : NEGV;
        float b1 = mk.y ? nanfix(w.y) : NEGV;
        float b2 = mk.z ? nanfix(w.z) : NEGV;
        float b3 = mk.w ? nanfix(w.w) : NEGV;
        b[j*4+0] = b0; b[j*4+1] = b1; b[j*4+2] = b2; b[j*4+3] = b3;
        anym |= (mk.x | mk.y | mk.z | mk.w);
        mx = fmaxf(fmaxf(fmaxf(mx, b0), fmaxf(b1, b2)), b3);
    }
    if (anym) atomicOr(&sv, 1);
    red[tid] = mx;
    __syncthreads();
    for (int s = 128; s > 0; s >>= 1) {
        if (tid < s) red[tid] = fmaxf(red[tid], red[tid + s]);
        __syncthreads();
    }
    float Mb = red[0];
    __syncthreads();
    float zs = 0.f;
#pragma unroll
    for (int j = 0; j < 16; ++j) zs += fexp(b[j] - Mb);
    red[tid] = zs;
    __syncthreads();
    for (int s = 128; s > 0; s >>= 1) {
        if (tid < s) red[tid] += red[tid + s];
        __syncthreads();
    }
    if (tid == 0) { g_mb[n] = Mb; g_zb[n] = red[0]; g_valid[n] = sv; }
}

// ---------------------------------------------------------------------------
// QKV projection: grid (12, 32), 256 threads, ldmatrix fragments.
// ---------------------------------------------------------------------------
__global__ __launch_bounds__(256) void proj_mma_kernel(const float* __restrict__ ipb) {
    __shared__ __align__(16) unsigned char smraw[4 * 128 * LDT * 2];
    __nv_bfloat16* sm = (__nv_bfloat16*)smraw;
    __nv_bfloat16* sAh = sm;
    __nv_bfloat16* sAl = sm + 128 * LDT;
    __nv_bfloat16* sBh = sm + 2 * 128 * LDT;
    __nv_bfloat16* sBl = sm + 3 * 128 * LDT;
    const int ot = blockIdx.x, nt = blockIdx.y;
    const int which = ot >> 2;
    const __nv_bfloat16* Xh = (which == 0) ? g_ah : g_bvh;
    const __nv_bfloat16* Xl = (which == 0) ? g_al : g_bvl;
    const __nv_bfloat16* Wh = g_wh + (long long)ot * 128 * DMODEL;
    const __nv_bfloat16* Wl = g_wl + (long long)ot * 128 * DMODEL;

    const int tid = threadIdx.x;
    const int lane = tid & 31, warp = tid >> 5;
    const int wm = warp >> 1, wn = warp & 1;
    const int g = lane >> 2, t4 = lane & 3;
    const int lr = tid >> 2, lc = (tid & 3) * 8;
    const uint32_t aHa = smem_to_u32(sAh), aLa = smem_to_u32(sAl);
    const uint32_t bHa = smem_to_u32(sBh), bLa = smem_to_u32(sBl);

    float acc[2][8][4];
#pragma unroll
    for (int i = 0; i < 2; ++i)
#pragma unroll
        for (int j = 0; j < 8; ++j)
#pragma unroll
            for (int r = 0; r < 4; ++r) acc[i][j][r] = 0.f;

    for (int c = 0; c < 16; ++c) {
        const long long co = (long long)c * 32 + lc;
        *(uint4*)&sAh[lr * LDT + lc] = *(const uint4*)&Xh[((long long)nt * 128 + lr) * DMODEL + co];
        *(uint4*)&sAh[(lr + 64) * LDT + lc] = *(const uint4*)&Xh[((long long)nt * 128 + lr + 64) * DMODEL + co];
        *(uint4*)&sAl[lr * LDT + lc] = *(const uint4*)&Xl[((long long)nt * 128 + lr) * DMODEL + co];
        *(uint4*)&sAl[(lr + 64) * LDT + lc] = *(const uint4*)&Xl[((long long)nt * 128 + lr + 64) * DMODEL + co];
        *(uint4*)&sBh[lr * LDT + lc] = *(const uint4*)&Wh[(long long)lr * DMODEL + co];
        *(uint4*)&sBh[(lr + 64) * LDT + lc] = *(const uint4*)&Wh[(long long)(lr + 64) * DMODEL + co];
        *(uint4*)&sBl[lr * LDT + lc] = *(const uint4*)&Wl[(long long)lr * DMODEL + co];
        *(uint4*)&sBl[(lr + 64) * LDT + lc] = *(const uint4*)&Wl[(long long)(lr + 64) * DMODEL + co];
        __syncthreads();
        mma_chunk3(acc, aHa, aLa, bHa, bLa, lane, wm, wn);
        __syncthreads();
    }

    const float scale = (which == 0) ? QSCALE : 1.f;
#pragma unroll
    for (int mb = 0; mb < 2; ++mb)
#pragma unroll
        for (int nb = 0; nb < 8; ++nb)
#pragma unroll
            for (int half = 0; half < 2; ++half) {
                const long long n = (long long)nt * 128 + wm * 32 + mb * 16 + g + half * 8;
                const int og = ot * 128 + wn * 64 + nb * 8 + t4 * 2;
                float v0 = scale * (acc[mb][nb][half * 2 + 0] + ipb[og]);
                float v1 = scale * (acc[mb][nb][half * 2 + 1] + ipb[og + 1]);
                __nv_bfloat16 h0 = __float2bfloat16(v0);
                __nv_bfloat16 l0 = __float2bfloat16(v0 - __bfloat162float(h0));
                __nv_bfloat16 h1 = __float2bfloat16(v1);
                __nv_bfloat16 l1 = __float2bfloat16(v1 - __bfloat162float(h1));
                if (which == 0) {
                    g_qh[n * DMODEL + og] = h0; g_qh[n * DMODEL + og + 1] = h1;
                    g_ql[n * DMODEL + og] = l0; g_ql[n * DMODEL + og + 1] = l1;
                } else if (which == 1) {
                    const int c = og - 512;
                    g_kh[n * DMODEL + c] = h0; g_kh[n * DMODEL + c + 1] = h1;
                    g_kl[n * DMODEL + c] = l0; g_kl[n * DMODEL + c + 1] = l1;
                } else {
                    const long long d = og - 1024;
                    g_vth[d * N_KEY + n] = h0; g_vth[(d + 1) * N_KEY + n] = h1;
                    g_vtl[d * N_KEY + n] = l0; g_vtl[(d + 1) * N_KEY + n] = l1;
                }
            }
}

// ---------------------------------------------------------------------------
// FUSED flash attention: grid (32 nt, 4 h), 256 threads, 1 CTA/SM.
// smem layout (bf16 units):
//   sQ hi [4][128][LDT] @0, sQ lo @4C, sP hi @8C, sP lo @12C,
//   sK hi buf0/1 @16C, sK lo buf0/1 @18C; fp32 sRed after;
//   fp32 bias overlay on the sP region between uses.
// ---------------------------------------------------------------------------
#define CHUNK_BF16 (128 * LDT)
#define SQ_OFF    0
#define SQL_OFF   (4 * CHUNK_BF16)
#define SP_OFF    (8 * CHUNK_BF16)
#define SPL_OFF   (12 * CHUNK_BF16)
#define SKH_OFF   (16 * CHUNK_BF16)
#define SKL_OFF   (18 * CHUNK_BF16)
#define SMEM_BF16_TOTAL (20 * CHUNK_BF16)
#define FUSED_SMEM_BYTES (SMEM_BF16_TOTAL * 2 + 128 * 2 * 4)

__global__ __launch_bounds__(256, 1) void fused_attn_kernel(const float* __restrict__ weight) {
    extern __shared__ __align__(16) unsigned char smem_raw[];
    __nv_bfloat16* sm = (__nv_bfloat16*)smem_raw;
    __nv_bfloat16* sQh = sm + SQ_OFF;
    __nv_bfloat16* sQl = sm + SQL_OFF;
    __nv_bfloat16* sPh = sm + SP_OFF;
    __nv_bfloat16* sPl = sm + SPL_OFF;
    float* sBias = (float*)(sm + SP_OFF);            // overlay
    float* sRed  = (float*)(sm + SMEM_BF16_TOTAL);   // 128*2 floats

    const uint32_t sQh_u = smem_to_u32(sQh), sQl_u = smem_to_u32(sQl);
    const uint32_t sPh_u = smem_to_u32(sPh), sPl_u = smem_to_u32(sPl);
    const uint32_t sKh_u = smem_to_u32(sm + SKH_OFF), sKl_u = smem_to_u32(sm + SKL_OFF);

    const int nt = blockIdx.x, h = blockIdx.y;
    const int tid = threadIdx.x;
    const int lane = tid & 31, warp = tid >> 5;
    const int wm = warp >> 1, wn = warp & 1;
    const int g = lane >> 2, t4 = lane & 3;
    const long long nBase = (long long)nt * 128;
    const int sr = tid >> 2;             // staging row 0..63
    const int sc = (tid & 3) * 8;        // staging col
    const int so = sr * LDT + sc;

    // stage Q (4 chunks, hi+lo)
    for (int u = tid; u < 2048; u += 256) {
        const int c = u >> 9;
        const int r = (u >> 2) & 127;
        const int cc = (u & 3) * 8;
        const long long gofs = (nBase + r) * DMODEL + h * DKH + c * 32 + cc;
        *(uint4*)&sQh[(c * 128 + r) * LDT + cc] = *(const uint4*)&g_qh[gofs];
        *(uint4*)&sQl[(c * 128 + r) * LDT + cc] = *(const uint4*)&g_ql[gofs];
    }

    float acc_o[2][8][4];
#pragma unroll
    for (int i = 0; i < 2; ++i)
#pragma unroll
        for (int j = 0; j < 8; ++j)
#pragma unroll
            for (int r = 0; r < 4; ++r) acc_o[i][j][r] = 0.f;

    float zh[4] = {0.f, 0.f, 0.f, 0.f};
    float ch[4] = {0.f, 0.f, 0.f, 0.f};
    float Mold[4] = {-INFINITY, -INFINITY, -INFINITY, -INFINITY};
    float Mbr[4];
#pragma unroll
    for (int mb = 0; mb < 2; ++mb)
#pragma unroll
        for (int half = 0; half < 2; ++half)
            Mbr[mb * 2 + half] = g_mb[nBase + wm * 32 + mb * 16 + half * 8 + g];

    __syncthreads();

    for (int mt = 0; mt < N_KEY / 128; ++mt) {
        const long long mBase = (long long)mt * 128;
        float acc_s[2][8][4];
#pragma unroll
        for (int i = 0; i < 2; ++i)
#pragma unroll
            for (int j = 0; j < 8; ++j)
#pragma unroll
                for (int r = 0; r < 4; ++r) acc_s[i][j][r] = 0.f;

        // ---- QK^T over 4 K-chunks, double-buffered staging, 1 sync/chunk ----
        {
            uint4 ph0, ph1, pl0, pl1;
            {
                const long long gk = (mBase + sr) * DMODEL + h * DKH + sc;
                ph0 = *(const uint4*)&g_kh[gk];
                ph1 = *(const uint4*)&g_kh[gk + 64 * DMODEL];
                pl0 = *(const uint4*)&g_kl[gk];
                pl1 = *(const uint4*)&g_kl[gk + 64 * DMODEL];
            }
            for (int c = 0; c < 4; ++c) {
                const int buf = (c & 1) * CHUNK_BF16;
                __nv_bfloat16* dKh = sm + SKH_OFF + buf;
                __nv_bfloat16* dKl = sm + SKL_OFF + buf;
                *(uint4*)&dKh[so] = ph0;
                *(uint4*)&dKh[so + 64 * LDT] = ph1;
                *(uint4*)&dKl[so] = pl0;
                *(uint4*)&dKl[so + 64 * LDT] = pl1;
                __syncthreads();
                if (c < 3) {
                    const long long gk = (mBase + sr) * DMODEL + h * DKH + (c + 1) * 32 + sc;
                    ph0 = *(const uint4*)&g_kh[gk];
                    ph1 = *(const uint4*)&g_kh[gk + 64 * DMODEL];
                    pl0 = *(const uint4*)&g_kl[gk];
                    pl1 = *(const uint4*)&g_kl[gk + 64 * DMODEL];
                }
                mma_chunk3(acc_s, sQh_u + (uint32_t)(c * CHUNK_BF16) * 2,
                           sQl_u + (uint32_t)(c * CHUNK_BF16) * 2,
                           sKh_u + (uint32_t)buf * 2, sKl_u + (uint32_t)buf * 2,
                           lane, wm, wn);
            }
        }

        // ---- bias add + tile row max ----
#pragma unroll
        for (int mb = 0; mb < 2; ++mb)
#pragma unroll
            for (int half = 0; half < 2; ++half) {
                const int rl = wm * 32 + mb * 16 + half * 8 + g;
                const long long n = nBase + rl;
                float smax = -INFINITY;
#pragma unroll
                for (int nb = 0; nb < 8; ++nb) {
                    const int col = wn * 64 + nb * 8 + t4 * 2;
                    const long long m = mBase + col;
                    const float2 w = *(const float2*)&weight[n * N_KEY + m];
                    const unsigned short mk = *(const unsigned short*)&g_mask[n * N_KEY + m];
                    const float b0 = (mk & 0xFF) ? nanfix(w.x) : NEGV;
                    const float b1 = (mk >> 8)   ? nanfix(w.y) : NEGV;
                    sBias[rl * 132 + col] = b0;
                    sBias[rl * 132 + col + 1] = b1;
                    const float s0 = acc_s[mb][nb][half * 2 + 0] + b0;
                    const float s1 = acc_s[mb][nb][half * 2 + 1] + b1;
                    acc_s[mb][nb][half * 2 + 0] = s0;
                    acc_s[mb][nb][half * 2 + 1] = s1;
                    smax = fmaxf(smax, fmaxf(s0, s1));
                }
                smax = fmaxf(smax, __shfl_xor_sync(0xffffffffu, smax, 1));
                smax = fmaxf(smax, __shfl_xor_sync(0xffffffffu, smax, 2));
                if (t4 == 0) sRed[rl * 2 + wn] = smax;
            }
        __syncthreads();

        // ---- online softmax update ----
#pragma unroll
        for (int mb = 0; mb < 2; ++mb)
#pragma unroll
            for (int half = 0; half < 2; ++half) {
                const int slot = mb * 2 + half;
                const int rl = wm * 32 + mb * 16 + half * 8 + g;
                const float Mtile = fmaxf(sRed[rl * 2], sRed[rl * 2 + 1]);
                const float Mnew = fmaxf(Mold[slot], Mtile);
                const float alpha = fexp(Mold[slot] - Mnew);
                Mold[slot] = Mnew;
                float z = zh[slot] * alpha;
                float cc = ch[slot] * alpha;
#pragma unroll
                for (int nb = 0; nb < 8; ++nb) {
                    const int col = wn * 64 + nb * 8 + t4 * 2;
#pragma unroll
                    for (int r = 0; r < 2; ++r) {
                        const float s = acc_s[mb][nb][half * 2 + r];
                        const float p = fexp(s - Mnew);
                        acc_s[mb][nb][half * 2 + r] = p;
                        z += p;
                        const float b = sBias[rl * 132 + col + r];
                        cc = fmaf(fexp(b - Mbr[slot]), p, cc);
                    }
                    acc_o[mb][nb][half * 2 + 0] *= alpha;
                    acc_o[mb][nb][half * 2 + 1] *= alpha;
                }
                zh[slot] = z;
                ch[slot] = cc;
            }
        __syncthreads();   // all bias reads done before P overwrites the overlay

        // ---- write P (split bf16) into smem chunk layout ----
#pragma unroll
        for (int mb = 0; mb < 2; ++mb)
#pragma unroll
            for (int half = 0; half < 2; ++half) {
                const int rl = wm * 32 + mb * 16 + half * 8 + g;
#pragma unroll
                for (int nb = 0; nb < 8; ++nb) {
                    const int col = wn * 64 + nb * 8 + t4 * 2;
                    const int chunk = col >> 5, c32 = col & 31;
                    const float p0 = acc_s[mb][nb][half * 2 + 0];
                    const float p1 = acc_s[mb][nb][half * 2 + 1];
                    const __nv_bfloat16 h0 = __float2bfloat16(p0);
                    const __nv_bfloat16 h1 = __float2bfloat16(p1);
                    const __nv_bfloat16 l0 = __float2bfloat16(p0 - __bfloat162float(h0));
                    const __nv_bfloat16 l1 = __float2bfloat16(p1 - __bfloat162float(h1));
                    const uint32_t ph = (uint32_t)__bfloat16_as_ushort(h0) |
                                        ((uint32_t)__bfloat16_as_ushort(h1) << 16);
                    const uint32_t pl = (uint32_t)__bfloat16_as_ushort(l0) |
                                        ((uint32_t)__bfloat16_as_ushort(l1) << 16);
                    *(uint32_t*)&sPh[(chunk * 128 + rl) * LDT + c32] = ph;
                    *(uint32_t*)&sPl[(chunk * 128 + rl) * LDT + c32] = pl;
                }
            }

        // ---- ctx accumulate: P @ V^T over 4 m-chunks, double-buffered ----
        {
            uint4 ph0, ph1, pl0, pl1;
            {
                const long long gv = (long long)(h * DKH + sr) * N_KEY + mBase + sc;
                ph0 = *(const uint4*)&g_vth[gv];
                ph1 = *(const uint4*)&g_vth[gv + 64 * N_KEY];
                pl0 = *(const uint4*)&g_vtl[gv];
                pl1 = *(const uint4*)&g_vtl[gv + 64 * N_KEY];
            }
            for (int c = 0; c < 4; ++c) {
                const int buf = (c & 1) * CHUNK_BF16;
                __nv_bfloat16* dKh = sm + SKH_OFF + buf;
                __nv_bfloat16* dKl = sm + SKL_OFF + buf;
                *(uint4*)&dKh[so] = ph0;
                *(uint4*)&dKh[so + 64 * LDT] = ph1;
                *(uint4*)&dKl[so] = pl0;
                *(uint4*)&dKl[so + 64 * LDT] = pl1;
                __syncthreads();
                if (c < 3) {
                    const long long gv = (long long)(h * DKH + sr) * N_KEY + mBase + (c + 1) * 32 + sc;
                    ph0 = *(const uint4*)&g_vth[gv];
                    ph1 = *(const uint4*)&g_vth[gv + 64 * N_KEY];
                    pl0 = *(const uint4*)&g_vtl[gv];
                    pl1 = *(const uint4*)&g_vtl[gv + 64 * N_KEY];
                }
                mma_chunk3(acc_o, sPh_u + (uint32_t)(c * CHUNK_BF16) * 2,
                           sPl_u + (uint32_t)(c * CHUNK_BF16) * 2,
                           sKh_u + (uint32_t)buf * 2, sKl_u + (uint32_t)buf * 2,
                           lane, wm, wn);
            }
        }
        __syncthreads();   // protect sP region (bias overlay next m-tile)
    }

    // ---- final reductions of zh, ch across t4 and wn ----
    float zt[4], ct[4];
#pragma unroll
    for (int slot = 0; slot < 4; ++slot) {
        float z = zh[slot];
        z += __shfl_xor_sync(0xffffffffu, z, 1);
        z += __shfl_xor_sync(0xffffffffu, z, 2);
        zh[slot] = z;
        float c = ch[slot];
        c += __shfl_xor_sync(0xffffffffu, c, 1);
        c += __shfl_xor_sync(0xffffffffu, c, 2);
        ch[slot] = c;
    }
#pragma unroll
    for (int mb = 0; mb < 2; ++mb)
#pragma unroll
        for (int half = 0; half < 2; ++half) {
            const int rl = wm * 32 + mb * 16 + half * 8 + g;
            if (t4 == 0) sRed[rl * 2 + wn] = zh[mb * 2 + half];
        }
    __syncthreads();
#pragma unroll
    for (int mb = 0; mb < 2; ++mb)
#pragma unroll
        for (int half = 0; half < 2; ++half) {
            const int rl = wm * 32 + mb * 16 + half * 8 + g;
            zt[mb * 2 + half] = sRed[rl * 2] + sRed[rl * 2 + 1];
        }
    __syncthreads();
#pragma unroll
    for (int mb = 0; mb < 2; ++mb)
#pragma unroll
        for (int half = 0; half < 2; ++half) {
            const int rl = wm * 32 + mb * 16 + half * 8 + g;
            if (t4 == 0) sRed[rl * 2 + wn] = ch[mb * 2 + half];
        }
    __syncthreads();
#pragma unroll
    for (int mb = 0; mb < 2; ++mb)
#pragma unroll
        for (int half = 0; half < 2; ++half) {
            const int rl = wm * 32 + mb * 16 + half * 8 + g;
            ct[mb * 2 + half] = sRed[rl * 2] + sRed[rl * 2 + 1];
        }

    // ---- outputs ----
#pragma unroll
    for (int mb = 0; mb < 2; ++mb)
#pragma unroll
        for (int half = 0; half < 2; ++half) {
            const int slot = mb * 2 + half;
            const int rl = wm * 32 + mb * 16 + half * 8 + g;
            const long long n = nBase + rl;
            const float zi = 1.f / zt[slot];
            if (t4 == 0 && wn == 0) g_chz[h * N_ACT + n] = ct[slot] * zi;
#pragma unroll
            for (int nb = 0; nb < 8; ++nb) {
                const int d = wn * 64 + nb * 8 + t4 * 2;
                float2 o;
                o.x = acc_o[mb][nb][half * 2 + 0] * zi;
                o.y = acc_o[mb][nb][half * 2 + 1] * zi;
                *(float2*)&g_ctx[n * DMODEL + h * DKH + d] = o;
            }
        }
}

// ---------------------------------------------------------------------------
// influence finisher
// ---------------------------------------------------------------------------
__global__ void influence_kernel(float* __restrict__ inf_out) {
    const int n = blockIdx.x * 256 + threadIdx.x;
    if (n >= N_ACT) return;
    const float s = g_chz[n] + g_chz[N_ACT + n] + g_chz[2 * N_ACT + n] + g_chz[3 * N_ACT + n];
    inf_out[n] = g_valid[n] ? (0.25f * s / g_zb[n]) : 0.f;
}

// ---------------------------------------------------------------------------
// Topic GEMM (FFMA, small): C[n][o] = ctx . wt[o] + bt[o], valid-gated.
// ---------------------------------------------------------------------------
__global__ __launch_bounds__(256) void gemm_nt_kernel(
    const float* __restrict__ X, const float* __restrict__ W,
    const float* __restrict__ bias, float* __restrict__ out,
    int ldo, const int* __restrict__ valid)
{
    __shared__ float Xs[64 * 36];
    __shared__ float Ws[64 * 36];
    const int tid = threadIdx.x;
    const int rowBase = blockIdx.y * 64;
    const int colBase = blockIdx.x * 64;
    const int og = tid & 15, ngr = tid >> 4;

    float acc[4][4];
#pragma unroll
    for (int i = 0; i < 4; ++i)
#pragma unroll
        for (int j = 0; j < 4; ++j) acc[i][j] = 0.f;

    for (int kk = 0; kk < 512; kk += 32) {
#pragma unroll
        for (int jj = 0; jj < 2; ++jj) {
            int idx = tid + jj * 256;
            int r = idx >> 3, c4 = (idx & 7) << 2;
            *(float4*)&Xs[r * 36 + c4] = *(const float4*)&X[(rowBase + r) * 512 + kk + c4];
            *(float4*)&Ws[r * 36 + c4] = *(const float4*)&W[(colBase + r) * 512 + kk + c4];
        }
        __syncthreads();
#pragma unroll
        for (int k4 = 0; k4 < 32; k4 += 4) {
            float4 xv[4], wv[4];
#pragma unroll
            for (int i = 0; i < 4; ++i) xv[i] = *(const float4*)&Xs[(ngr * 4 + i) * 36 + k4];
#pragma unroll
            for (int j = 0; j < 4; ++j) wv[j] = *(const float4*)&Ws[(og * 4 + j) * 36 + k4];
#pragma unroll
            for (int i = 0; i < 4; ++i)
#pragma unroll
                for (int j = 0; j < 4; ++j) {
                    acc[i][j] = fmaf(xv[i].x, wv[j].x, acc[i][j]);
                    acc[i][j] = fmaf(xv[i].y, wv[j].y, acc[i][j]);
                    acc[i][j] = fmaf(xv[i].z, wv[j].z, acc[i][j]);
                    acc[i][j] = fmaf(xv[i].w, wv[j].w, acc[i][j]);
                }
        }
        __syncthreads();
    }
#pragma unroll
    for (int i = 0; i < 4; ++i) {
        int n = rowBase + ngr * 4 + i;
        float vmul = valid[n] ? 1.f : 0.f;
#pragma unroll
        for (int j = 0; j < 4; ++j) {
            int o = colBase + og * 4 + j;
            out[n * ldo + o] = vmul * (acc[i][j] + bias[o]);
        }
    }
}

// ---------------------------------------------------------------------------
extern "C" void kernel_launch(void* const* d_in, const int* in_sizes, int n_in,
                              void* d_out, int out_size) {
    const float* a      = (const float*)d_in[0];
    const float* bv     = (const float*)d_in[1];
    const void*  mraw   = (const void*)d_in[2];
    const float* weight = (const float*)d_in[3];
    const float* ipw    = (const float*)d_in[4];
    const float* ipb    = (const float*)d_in[5];
    const float* ow     = (const float*)d_in[6];
    const float* ob     = (const float*)d_in[7];
    float* out = (float*)d_out;

    void *pctx, *pwt, *pbt, *pvalid;
    cudaGetSymbolAddress(&pctx, g_ctx);
    cudaGetSymbolAddress(&pwt, g_wt);
    cudaGetSymbolAddress(&pbt, g_bt);
    cudaGetSymbolAddress(&pvalid, g_valid);
    void *pah, *pal, *pbh, *pbl, *pwh, *pwl;
    cudaGetSymbolAddress(&pah, g_ah); cudaGetSymbolAddress(&pal, g_al);
    cudaGetSymbolAddress(&pbh, g_bvh); cudaGetSymbolAddress(&pbl, g_bvl);
    cudaGetSymbolAddress(&pwh, g_wh); cudaGetSymbolAddress(&pwl, g_wl);

    cudaFuncSetAttribute(fused_attn_kernel, cudaFuncAttributeMaxDynamicSharedMemorySize,
                         FUSED_SMEM_BYTES);

    mask_detect_kernel<<<1, 256>>>((const unsigned int*)mraw);
    mask_repack_kernel<<<16384, 256>>>(mraw);

    conv_split_kernel<<<2048, 256>>>(a,  (__nv_bfloat16*)pah, (__nv_bfloat16*)pal, N_ACT * DMODEL / 4, 1);
    conv_split_kernel<<<2048, 256>>>(bv, (__nv_bfloat16*)pbh, (__nv_bfloat16*)pbl, N_KEY * DMODEL / 4, 1);
    conv_split_kernel<<<768, 256>>>(ipw, (__nv_bfloat16*)pwh, (__nv_bfloat16*)pwl, 3 * DMODEL * DMODEL / 4, 0);

    build_wt_kernel<<<(DKH * DMODEL + 255) / 256, 256>>>(ow, ob);

    proj_mma_kernel<<<dim3(12, 32), 256>>>(ipb);
    bias_stats_kernel<<<N_ACT, 256>>>(weight);

    fused_attn_kernel<<<dim3(32, 4), 256, FUSED_SMEM_BYTES>>>(weight);

    influence_kernel<<<16, 256>>>(out + N_ACT * DKH);

    gemm_nt_kernel<<<dim3(2, 64), 256>>>((const float*)pctx, (const float*)pwt,
                                         (const float*)pbt, out, DKH, (const int*)pvalid);
}

// round 14
// speedup vs baseline: 3.2221x; 1.2189x over previous
#include <cuda_runtime.h>
#include <cuda_bf16.h>
#include <cstdint>
#include <math.h>

#define N_ACT 4096
#define N_KEY 4096
#define DMODEL 512
#define NHEAD 4
#define DKH 128
#define NEGV (-1e9f)
#define QSCALE 0.08838834764831845f
#define LDT 40   // bf16 per smem tile row (32 data + 8 pad); 80B rows, 16B-aligned

// ---------------------------------------------------------------------------
// scratch (static device allocations — allowed)
// ---------------------------------------------------------------------------
__device__ __nv_bfloat16 g_ah[N_ACT * DMODEL],  g_al[N_ACT * DMODEL];
__device__ __nv_bfloat16 g_bvh[N_KEY * DMODEL], g_bvl[N_KEY * DMODEL];
__device__ __nv_bfloat16 g_wh[3 * DMODEL * DMODEL], g_wl[3 * DMODEL * DMODEL];
__device__ __nv_bfloat16 g_qh[N_ACT * DMODEL],  g_ql[N_ACT * DMODEL];
__device__ __nv_bfloat16 g_kh[N_KEY * DMODEL],  g_kl[N_KEY * DMODEL];
__device__ __nv_bfloat16 g_vth[DMODEL * N_KEY], g_vtl[DMODEL * N_KEY];
__device__ float g_ctx[N_ACT * DMODEL];
__device__ float g_wt[DKH * DMODEL];
__device__ float g_bt[DKH];
__device__ int   g_valid[N_ACT];
__device__ float g_mb[N_ACT];
__device__ float g_zb[N_ACT];
__device__ float g_chz[NHEAD * N_ACT];
__device__ unsigned char g_mask[(size_t)N_ACT * N_KEY];
__device__ int   g_mflag;

__device__ __forceinline__ float nanfix(float x) {
    if (isnan(x)) return 0.f;
    if (isinf(x)) return x > 0.f ? 1.f : -1.f;
    return x;
}

// Fast exp for x <= 0, FFMA-only. ~2e-6 rel error.
__device__ __forceinline__ float fexp(float x) {
    x = fminf(x, 0.f);
    x = fmaxf(x, -87.0f);
    const float LOG2E = 1.4426950408889634f;
    float t = fmaf(x, LOG2E, 12582912.f);
    float jf = t - 12582912.f;
    int ji = (__float_as_int(t) & 0x7FFFFF) - 0x400000;
    float r = fmaf(x, LOG2E, -jf);
    float g = r * 0.6931471805599453f;
    float p = fmaf(g, 0.0083333333f, 0.0416666666f);
    p = fmaf(p, g, 0.1666666666f);
    p = fmaf(p, g, 0.5f);
    p = fmaf(p, g, 1.0f);
    p = fmaf(p, g, 1.0f);
    return __int_as_float((ji + 127) << 23) * p;
}

__device__ __forceinline__ uint32_t smem_to_u32(const void* p) {
    uint32_t a;
    asm("{ .reg .u64 t; cvta.to.shared.u64 t, %1; cvt.u32.u64 %0, t; }" : "=r"(a) : "l"(p));
    return a;
}

// ---------------------------------------------------------------------------
// warp mma + ldmatrix (baseline PTX — compiles on the plain sm_103 target)
// ---------------------------------------------------------------------------
__device__ __forceinline__ void mma_bf16(float c[4], const uint32_t a[4], const uint32_t b[2]) {
    asm volatile("mma.sync.aligned.m16n8k16.row.col.f32.bf16.bf16.f32 "
                 "{%0,%1,%2,%3}, {%4,%5,%6,%7}, {%8,%9}, {%0,%1,%2,%3};"
                 : "+f"(c[0]), "+f"(c[1]), "+f"(c[2]), "+f"(c[3])
                 : "r"(a[0]), "r"(a[1]), "r"(a[2]), "r"(a[3]), "r"(b[0]), "r"(b[1]));
}

__device__ __forceinline__ void ldsm_x4(uint32_t r[4], uint32_t addr) {
    asm volatile("ldmatrix.sync.aligned.m8n8.x4.shared.b16 {%0,%1,%2,%3}, [%4];"
                 : "=r"(r[0]), "=r"(r[1]), "=r"(r[2]), "=r"(r[3]) : "r"(addr));
}

// 128-row x 128-col warp-tiled chunk MMA, warp tile 32m x 64n (proj kernel, 8 warps)
__device__ __forceinline__ void mma_chunk3_64n(
    float (&acc)[2][8][4],
    uint32_t aH, uint32_t aL, uint32_t bH, uint32_t bL,
    int lane, int wm, int wn)
{
    const int la15 = lane & 15;
    const int lhi  = (lane >> 4) << 3;
    const int brow = ((lane >> 4) << 3) + (lane & 7);
    const int bko  = ((lane >> 3) & 1) << 3;
#pragma unroll
    for (int kk = 0; kk < 2; ++kk) {
        const int kb = kk * 16;
        uint32_t fah[2][4], fal[2][4];
#pragma unroll
        for (int mb = 0; mb < 2; ++mb) {
            const uint32_t off = (uint32_t)((wm * 32 + mb * 16 + la15) * LDT + kb + lhi) * 2;
            ldsm_x4(fah[mb], aH + off);
            ldsm_x4(fal[mb], aL + off);
        }
#pragma unroll
        for (int nbp = 0; nbp < 4; ++nbp) {
            const uint32_t off = (uint32_t)((wn * 64 + nbp * 16 + brow) * LDT + kb + bko) * 2;
            uint32_t fbh[4], fbl[4];
            ldsm_x4(fbh, bH + off);
            ldsm_x4(fbl, bL + off);
#pragma unroll
            for (int mb = 0; mb < 2; ++mb) {
                mma_bf16(acc[mb][nbp * 2],     fah[mb], fbh);
                mma_bf16(acc[mb][nbp * 2],     fah[mb], fbl);
                mma_bf16(acc[mb][nbp * 2],     fal[mb], fbh);
                mma_bf16(acc[mb][nbp * 2 + 1], fah[mb], fbh + 2);
                mma_bf16(acc[mb][nbp * 2 + 1], fah[mb], fbl + 2);
                mma_bf16(acc[mb][nbp * 2 + 1], fal[mb], fbh + 2);
            }
        }
    }
}

// warp tile 32m x 32n (fused kernel, 16 warps: wm 0..3, wn 0..3)
__device__ __forceinline__ void mma_chunk3_32n(
    float (&acc)[2][4][4],
    uint32_t aH, uint32_t aL, uint32_t bH, uint32_t bL,
    int lane, int wm, int wn)
{
    const int la15 = lane & 15;
    const int lhi  = (lane >> 4) << 3;
    const int brow = ((lane >> 4) << 3) + (lane & 7);
    const int bko  = ((lane >> 3) & 1) << 3;
#pragma unroll
    for (int kk = 0; kk < 2; ++kk) {
        const int kb = kk * 16;
        uint32_t fah[2][4], fal[2][4];
#pragma unroll
        for (int mb = 0; mb < 2; ++mb) {
            const uint32_t off = (uint32_t)((wm * 32 + mb * 16 + la15) * LDT + kb + lhi) * 2;
            ldsm_x4(fah[mb], aH + off);
            ldsm_x4(fal[mb], aL + off);
        }
#pragma unroll
        for (int nbp = 0; nbp < 2; ++nbp) {
            const uint32_t off = (uint32_t)((wn * 32 + nbp * 16 + brow) * LDT + kb + bko) * 2;
            uint32_t fbh[4], fbl[4];
            ldsm_x4(fbh, bH + off);
            ldsm_x4(fbl, bL + off);
#pragma unroll
            for (int mb = 0; mb < 2; ++mb) {
                mma_bf16(acc[mb][nbp * 2],     fah[mb], fbh);
                mma_bf16(acc[mb][nbp * 2],     fah[mb], fbl);
                mma_bf16(acc[mb][nbp * 2],     fal[mb], fbh);
                mma_bf16(acc[mb][nbp * 2 + 1], fah[mb], fbh + 2);
                mma_bf16(acc[mb][nbp * 2 + 1], fah[mb], fbl + 2);
                mma_bf16(acc[mb][nbp * 2 + 1], fal[mb], fbh + 2);
            }
        }
    }
}

// ---------------------------------------------------------------------------
// mask dtype detect + repack
// ---------------------------------------------------------------------------
__global__ void mask_detect_kernel(const unsigned int* __restrict__ m) {
    __shared__ int cF, cHi;
    if (threadIdx.x == 0) { cF = 0; cHi = 0; }
    __syncthreads();
    int lf = 0, lh = 0;
    for (int i = threadIdx.x; i < 16384; i += 256) {
        unsigned int w = m[i];
        if (w == 0x3F800000u) lf++;
        else if ((w & 0xFFFFFF00u) != 0u) lh++;
    }
    atomicAdd(&cF, lf);
    atomicAdd(&cHi, lh);
    __syncthreads();
    if (threadIdx.x == 0) {
        if (cF > 16) g_mflag = 2;
        else if (cHi > 16) g_mflag = 0;
        else g_mflag = 1;
    }
}

__global__ void mask_repack_kernel(const void* __restrict__ mraw) {
    const long long i4 = (long long)blockIdx.x * 256 + threadIdx.x;
    if (i4 * 4 >= (long long)N_ACT * N_KEY) return;
    const int flag = g_mflag;
    uchar4 o;
    if (flag == 0) {
        uchar4 b = ((const uchar4*)mraw)[i4];
        o.x = b.x ? 1 : 0; o.y = b.y ? 1 : 0; o.z = b.z ? 1 : 0; o.w = b.w ? 1 : 0;
    } else if (flag == 1) {
        int4 b = ((const int4*)mraw)[i4];
        o.x = b.x ? 1 : 0; o.y = b.y ? 1 : 0; o.z = b.z ? 1 : 0; o.w = b.w ? 1 : 0;
    } else {
        float4 b = ((const float4*)mraw)[i4];
        o.x = (b.x != 0.f) ? 1 : 0; o.y = (b.y != 0.f) ? 1 : 0;
        o.z = (b.z != 0.f) ? 1 : 0; o.w = (b.w != 0.f) ? 1 : 0;
    }
    ((uchar4*)g_mask)[i4] = o;
}

// fp32 -> split bf16 (hi + lo)
__global__ void conv_split_kernel(const float* __restrict__ src,
                                  __nv_bfloat16* __restrict__ hi,
                                  __nv_bfloat16* __restrict__ lo,
                                  int n4, int fix) {
    int i = blockIdx.x * 256 + threadIdx.x;
    if (i >= n4) return;
    float4 v = ((const float4*)src)[i];
    if (fix) { v.x = nanfix(v.x); v.y = nanfix(v.y); v.z = nanfix(v.z); v.w = nanfix(v.w); }
    float a[4] = {v.x, v.y, v.z, v.w};
#pragma unroll
    for (int j = 0; j < 4; ++j) {
        __nv_bfloat16 h = __float2bfloat16(a[j]);
        hi[i * 4 + j] = h;
        lo[i * 4 + j] = __float2bfloat16(a[j] - __bfloat162float(h));
    }
}

__global__ void build_wt_kernel(const float* __restrict__ ow,
                                const float* __restrict__ ob) {
    int idx = blockIdx.x * 256 + threadIdx.x;
    if (idx < DKH * DMODEL) {
        int dk = idx >> 9, c = idx & 511;
        g_wt[idx] = 0.25f * (ow[dk * DMODEL + c] + ow[(dk + DKH) * DMODEL + c] +
                             ow[(dk + 2 * DKH) * DMODEL + c] + ow[(dk + 3 * DKH) * DMODEL + c]);
    }
    if (idx < DKH)
        g_bt[idx] = 0.25f * (ob[idx] + ob[idx + DKH] + ob[idx + 2 * DKH] + ob[idx + 3 * DKH]);
}

// ---------------------------------------------------------------------------
// Bias stats pre-pass: per row n -> Mb, Zb, valid.
// ---------------------------------------------------------------------------
__global__ __launch_bounds__(256) void bias_stats_kernel(const float* __restrict__ weight) {
    __shared__ float red[256];
    __shared__ int sv;
    const int n = blockIdx.x, tid = threadIdx.x;
    if (tid == 0) sv = 0;
    __syncthreads();
    const long long base = (long long)n * N_KEY;
    float b[16];
    float mx = -INFINITY; int anym = 0;
#pragma unroll
    for (int j = 0; j < 4; ++j) {
        int m = tid * 4 + j * 1024;
        float4 w = *(const float4*)&weight[base + m];
        uchar4 mk = *(const uchar4*)&g_mask[base + m];
        float b0 = mk.x ? nanfix(w.x) : NEGV;
        float b1 = mk.y ? nanfix(w.y) : NEGV;
        float b2 = mk.z ? nanfix(w.z) : NEGV;
        float b3 = mk.w ? nanfix(w.w) : NEGV;
        b[j*4+0] = b0; b[j*4+1] = b1; b[j*4+2] = b2; b[j*4+3] = b3;
        anym |= (mk.x | mk.y | mk.z | mk.w);
        mx = fmaxf(fmaxf(fmaxf(mx, b0), fmaxf(b1, b2)), b3);
    }
    if (anym) atomicOr(&sv, 1);
    red[tid] = mx;
    __syncthreads();
    for (int s = 128; s > 0; s >>= 1) {
        if (tid < s) red[tid] = fmaxf(red[tid], red[tid + s]);
        __syncthreads();
    }
    float Mb = red[0];
    __syncthreads();
    float zs = 0.f;
#pragma unroll
    for (int j = 0; j < 16; ++j) zs += fexp(b[j] - Mb);
    red[tid] = zs;
    __syncthreads();
    for (int s = 128; s > 0; s >>= 1) {
        if (tid < s) red[tid] += red[tid + s];
        __syncthreads();
    }
    if (tid == 0) { g_mb[n] = Mb; g_zb[n] = red[0]; g_valid[n] = sv; }
}

// ---------------------------------------------------------------------------
// QKV projection: grid (12, 32), 256 threads, ldmatrix fragments (R13, passing).
// ---------------------------------------------------------------------------
__global__ __launch_bounds__(256) void proj_mma_kernel(const float* __restrict__ ipb) {
    __shared__ __align__(16) unsigned char smraw[4 * 128 * LDT * 2];
    __nv_bfloat16* sm = (__nv_bfloat16*)smraw;
    __nv_bfloat16* sAh = sm;
    __nv_bfloat16* sAl = sm + 128 * LDT;
    __nv_bfloat16* sBh = sm + 2 * 128 * LDT;
    __nv_bfloat16* sBl = sm + 3 * 128 * LDT;
    const int ot = blockIdx.x, nt = blockIdx.y;
    const int which = ot >> 2;
    const __nv_bfloat16* Xh = (which == 0) ? g_ah : g_bvh;
    const __nv_bfloat16* Xl = (which == 0) ? g_al : g_bvl;
    const __nv_bfloat16* Wh = g_wh + (long long)ot * 128 * DMODEL;
    const __nv_bfloat16* Wl = g_wl + (long long)ot * 128 * DMODEL;

    const int tid = threadIdx.x;
    const int lane = tid & 31, warp = tid >> 5;
    const int wm = warp >> 1, wn = warp & 1;
    const int g = lane >> 2, t4 = lane & 3;
    const int lr = tid >> 2, lc = (tid & 3) * 8;
    const uint32_t aHa = smem_to_u32(sAh), aLa = smem_to_u32(sAl);
    const uint32_t bHa = smem_to_u32(sBh), bLa = smem_to_u32(sBl);

    float acc[2][8][4];
#pragma unroll
    for (int i = 0; i < 2; ++i)
#pragma unroll
        for (int j = 0; j < 8; ++j)
#pragma unroll
            for (int r = 0; r < 4; ++r) acc[i][j][r] = 0.f;

    for (int c = 0; c < 16; ++c) {
        const long long co = (long long)c * 32 + lc;
        *(uint4*)&sAh[lr * LDT + lc] = *(const uint4*)&Xh[((long long)nt * 128 + lr) * DMODEL + co];
        *(uint4*)&sAh[(lr + 64) * LDT + lc] = *(const uint4*)&Xh[((long long)nt * 128 + lr + 64) * DMODEL + co];
        *(uint4*)&sAl[lr * LDT + lc] = *(const uint4*)&Xl[((long long)nt * 128 + lr) * DMODEL + co];
        *(uint4*)&sAl[(lr + 64) * LDT + lc] = *(const uint4*)&Xl[((long long)nt * 128 + lr + 64) * DMODEL + co];
        *(uint4*)&sBh[lr * LDT + lc] = *(const uint4*)&Wh[(long long)lr * DMODEL + co];
        *(uint4*)&sBh[(lr + 64) * LDT + lc] = *(const uint4*)&Wh[(long long)(lr + 64) * DMODEL + co];
        *(uint4*)&sBl[lr * LDT + lc] = *(const uint4*)&Wl[(long long)lr * DMODEL + co];
        *(uint4*)&sBl[(lr + 64) * LDT + lc] = *(const uint4*)&Wl[(long long)(lr + 64) * DMODEL + co];
        __syncthreads();
        mma_chunk3_64n(acc, aHa, aLa, bHa, bLa, lane, wm, wn);
        __syncthreads();
    }

    const float scale = (which == 0) ? QSCALE : 1.f;
#pragma unroll
    for (int mb = 0; mb < 2; ++mb)
#pragma unroll
        for (int nb = 0; nb < 8; ++nb)
#pragma unroll
            for (int half = 0; half < 2; ++half) {
                const long long n = (long long)nt * 128 + wm * 32 + mb * 16 + g + half * 8;
                const int og = ot * 128 + wn * 64 + nb * 8 + t4 * 2;
                float v0 = scale * (acc[mb][nb][half * 2 + 0] + ipb[og]);
                float v1 = scale * (acc[mb][nb][half * 2 + 1] + ipb[og + 1]);
                __nv_bfloat16 h0 = __float2bfloat16(v0);
                __nv_bfloat16 l0 = __float2bfloat16(v0 - __bfloat162float(h0));
                __nv_bfloat16 h1 = __float2bfloat16(v1);
                __nv_bfloat16 l1 = __float2bfloat16(v1 - __bfloat162float(h1));
                if (which == 0) {
                    g_qh[n * DMODEL + og] = h0; g_qh[n * DMODEL + og + 1] = h1;
                    g_ql[n * DMODEL + og] = l0; g_ql[n * DMODEL + og + 1] = l1;
                } else if (which == 1) {
                    const int c = og - 512;
                    g_kh[n * DMODEL + c] = h0; g_kh[n * DMODEL + c + 1] = h1;
                    g_kl[n * DMODEL + c] = l0; g_kl[n * DMODEL + c + 1] = l1;
                } else {
                    const long long d = og - 1024;
                    g_vth[d * N_KEY + n] = h0; g_vth[(d + 1) * N_KEY + n] = h1;
                    g_vtl[d * N_KEY + n] = l0; g_vtl[(d + 1) * N_KEY + n] = l1;
                }
            }
}

// ---------------------------------------------------------------------------
// FUSED flash attention: grid (32 nt, 4 h), 512 threads (16 warps, 4x4),
// warp tile 32m x 32n, 1 CTA/SM.
// ---------------------------------------------------------------------------
#define CHUNK_BF16 (128 * LDT)
#define SQ_OFF    0
#define SQL_OFF   (4 * CHUNK_BF16)
#define SP_OFF    (8 * CHUNK_BF16)
#define SPL_OFF   (12 * CHUNK_BF16)
#define SKH_OFF   (16 * CHUNK_BF16)
#define SKL_OFF   (18 * CHUNK_BF16)
#define SMEM_BF16_TOTAL (20 * CHUNK_BF16)
#define FUSED_SMEM_BYTES (SMEM_BF16_TOTAL * 2 + 128 * 4 * 4)

__global__ __launch_bounds__(512, 1) void fused_attn_kernel(const float* __restrict__ weight) {
    extern __shared__ __align__(16) unsigned char smem_raw[];
    __nv_bfloat16* sm = (__nv_bfloat16*)smem_raw;
    __nv_bfloat16* sQh = sm + SQ_OFF;
    __nv_bfloat16* sQl = sm + SQL_OFF;
    __nv_bfloat16* sPh = sm + SP_OFF;
    __nv_bfloat16* sPl = sm + SPL_OFF;
    float* sBias = (float*)(sm + SP_OFF);            // overlay
    float* sRed  = (float*)(sm + SMEM_BF16_TOTAL);   // 128*4 floats

    const uint32_t sQh_u = smem_to_u32(sQh), sQl_u = smem_to_u32(sQl);
    const uint32_t sPh_u = smem_to_u32(sPh), sPl_u = smem_to_u32(sPl);
    const uint32_t sKh_u = smem_to_u32(sm + SKH_OFF), sKl_u = smem_to_u32(sm + SKL_OFF);

    const int nt = blockIdx.x, h = blockIdx.y;
    const int tid = threadIdx.x;
    const int lane = tid & 31, warp = tid >> 5;
    const int wm = warp >> 2, wn = warp & 3;         // 4x4 warp grid
    const int g = lane >> 2, t4 = lane & 3;
    const long long nBase = (long long)nt * 128;
    const int sr = tid >> 2;             // staging row 0..127 (512 threads)
    const int sc = (tid & 3) * 8;        // staging col
    const int so = sr * LDT + sc;

    // stage Q (4 chunks, hi+lo): 2048 uint4 per array, 512 threads -> 4 iters
    for (int u = tid; u < 2048; u += 512) {
        const int c = u >> 9;
        const int r = (u >> 2) & 127;
        const int cc = (u & 3) * 8;
        const long long gofs = (nBase + r) * DMODEL + h * DKH + c * 32 + cc;
        *(uint4*)&sQh[(c * 128 + r) * LDT + cc] = *(const uint4*)&g_qh[gofs];
        *(uint4*)&sQl[(c * 128 + r) * LDT + cc] = *(const uint4*)&g_ql[gofs];
    }

    float acc_o[2][4][4];
#pragma unroll
    for (int i = 0; i < 2; ++i)
#pragma unroll
        for (int j = 0; j < 4; ++j)
#pragma unroll
            for (int r = 0; r < 4; ++r) acc_o[i][j][r] = 0.f;

    float zh[4] = {0.f, 0.f, 0.f, 0.f};
    float ch[4] = {0.f, 0.f, 0.f, 0.f};
    float Mold[4] = {-INFINITY, -INFINITY, -INFINITY, -INFINITY};
    float Mbr[4];
#pragma unroll
    for (int mb = 0; mb < 2; ++mb)
#pragma unroll
        for (int half = 0; half < 2; ++half)
            Mbr[mb * 2 + half] = g_mb[nBase + wm * 32 + mb * 16 + half * 8 + g];

    __syncthreads();

    for (int mt = 0; mt < N_KEY / 128; ++mt) {
        const long long mBase = (long long)mt * 128;
        float acc_s[2][4][4];
#pragma unroll
        for (int i = 0; i < 2; ++i)
#pragma unroll
            for (int j = 0; j < 4; ++j)
#pragma unroll
                for (int r = 0; r < 4; ++r) acc_s[i][j][r] = 0.f;

        // ---- QK^T over 4 K-chunks, double-buffered, 1 sync/chunk ----
        {
            uint4 ph0, pl0;
            {
                const long long gk = (mBase + sr) * DMODEL + h * DKH + sc;
                ph0 = *(const uint4*)&g_kh[gk];
                pl0 = *(const uint4*)&g_kl[gk];
            }
            for (int c = 0; c < 4; ++c) {
                const int buf = (c & 1) * CHUNK_BF16;
                *(uint4*)&sm[SKH_OFF + buf + so] = ph0;
                *(uint4*)&sm[SKL_OFF + buf + so] = pl0;
                __syncthreads();
                if (c < 3) {
                    const long long gk = (mBase + sr) * DMODEL + h * DKH + (c + 1) * 32 + sc;
                    ph0 = *(const uint4*)&g_kh[gk];
                    pl0 = *(const uint4*)&g_kl[gk];
                }
                mma_chunk3_32n(acc_s, sQh_u + (uint32_t)(c * CHUNK_BF16) * 2,
                               sQl_u + (uint32_t)(c * CHUNK_BF16) * 2,
                               sKh_u + (uint32_t)buf * 2, sKl_u + (uint32_t)buf * 2,
                               lane, wm, wn);
            }
        }

        // ---- bias add + tile row max ----
#pragma unroll
        for (int mb = 0; mb < 2; ++mb)
#pragma unroll
            for (int half = 0; half < 2; ++half) {
                const int rl = wm * 32 + mb * 16 + half * 8 + g;
                const long long n = nBase + rl;
                float smax = -INFINITY;
#pragma unroll
                for (int nb = 0; nb < 4; ++nb) {
                    const int col = wn * 32 + nb * 8 + t4 * 2;
                    const long long m = mBase + col;
                    const float2 w = *(const float2*)&weight[n * N_KEY + m];
                    const unsigned short mk = *(const unsigned short*)&g_mask[n * N_KEY + m];
                    const float b0 = (mk & 0xFF) ? nanfix(w.x) : NEGV;
                    const float b1 = (mk >> 8)   ? nanfix(w.y) : NEGV;
                    sBias[rl * 132 + col] = b0;
                    sBias[rl * 132 + col + 1] = b1;
                    const float s0 = acc_s[mb][nb][half * 2 + 0] + b0;
                    const float s1 = acc_s[mb][nb][half * 2 + 1] + b1;
                    acc_s[mb][nb][half * 2 + 0] = s0;
                    acc_s[mb][nb][half * 2 + 1] = s1;
                    smax = fmaxf(smax, fmaxf(s0, s1));
                }
                smax = fmaxf(smax, __shfl_xor_sync(0xffffffffu, smax, 1));
                smax = fmaxf(smax, __shfl_xor_sync(0xffffffffu, smax, 2));
                if (t4 == 0) sRed[rl * 4 + wn] = smax;
            }
        __syncthreads();

        // ---- online softmax update ----
#pragma unroll
        for (int mb = 0; mb < 2; ++mb)
#pragma unroll
            for (int half = 0; half < 2; ++half) {
                const int slot = mb * 2 + half;
                const int rl = wm * 32 + mb * 16 + half * 8 + g;
                const float Mtile = fmaxf(fmaxf(sRed[rl * 4], sRed[rl * 4 + 1]),
                                          fmaxf(sRed[rl * 4 + 2], sRed[rl * 4 + 3]));
                const float Mnew = fmaxf(Mold[slot], Mtile);
                const float alpha = fexp(Mold[slot] - Mnew);
                Mold[slot] = Mnew;
                float z = zh[slot] * alpha;
                float cc = ch[slot] * alpha;
#pragma unroll
                for (int nb = 0; nb < 4; ++nb) {
                    const int col = wn * 32 + nb * 8 + t4 * 2;
#pragma unroll
                    for (int r = 0; r < 2; ++r) {
                        const float s = acc_s[mb][nb][half * 2 + r];
                        const float p = fexp(s - Mnew);
                        acc_s[mb][nb][half * 2 + r] = p;
                        z += p;
                        const float b = sBias[rl * 132 + col + r];
                        cc = fmaf(fexp(b - Mbr[slot]), p, cc);
                    }
                    acc_o[mb][nb][half * 2 + 0] *= alpha;
                    acc_o[mb][nb][half * 2 + 1] *= alpha;
                }
                zh[slot] = z;
                ch[slot] = cc;
            }
        __syncthreads();   // all bias reads done before P overwrites the overlay

        // ---- write P (split bf16) into smem chunk layout ----
#pragma unroll
        for (int mb = 0; mb < 2; ++mb)
#pragma unroll
            for (int half = 0; half < 2; ++half) {
                const int rl = wm * 32 + mb * 16 + half * 8 + g;
#pragma unroll
                for (int nb = 0; nb < 4; ++nb) {
                    const int col = wn * 32 + nb * 8 + t4 * 2;
                    const int chunk = col >> 5, c32 = col & 31;
                    const float p0 = acc_s[mb][nb][half * 2 + 0];
                    const float p1 = acc_s[mb][nb][half * 2 + 1];
                    const __nv_bfloat16 h0 = __float2bfloat16(p0);
                    const __nv_bfloat16 h1 = __float2bfloat16(p1);
                    const __nv_bfloat16 l0 = __float2bfloat16(p0 - __bfloat162float(h0));
                    const __nv_bfloat16 l1 = __float2bfloat16(p1 - __bfloat162float(h1));
                    const uint32_t ph = (uint32_t)__bfloat16_as_ushort(h0) |
                                        ((uint32_t)__bfloat16_as_ushort(h1) << 16);
                    const uint32_t pl = (uint32_t)__bfloat16_as_ushort(l0) |
                                        ((uint32_t)__bfloat16_as_ushort(l1) << 16);
                    *(uint32_t*)&sPh[(chunk * 128 + rl) * LDT + c32] = ph;
                    *(uint32_t*)&sPl[(chunk * 128 + rl) * LDT + c32] = pl;
                }
            }

        // ---- ctx accumulate: P @ V^T over 4 m-chunks, double-buffered ----
        {
            uint4 ph0, pl0;
            {
                const long long gv = (long long)(h * DKH + sr) * N_KEY + mBase + sc;
                ph0 = *(const uint4*)&g_vth[gv];
                pl0 = *(const uint4*)&g_vtl[gv];
            }
            for (int c = 0; c < 4; ++c) {
                const int buf = (c & 1) * CHUNK_BF16;
                *(uint4*)&sm[SKH_OFF + buf + so] = ph0;
                *(uint4*)&sm[SKL_OFF + buf + so] = pl0;
                __syncthreads();
                if (c < 3) {
                    const long long gv = (long long)(h * DKH + sr) * N_KEY + mBase + (c + 1) * 32 + sc;
                    ph0 = *(const uint4*)&g_vth[gv];
                    pl0 = *(const uint4*)&g_vtl[gv];
                }
                mma_chunk3_32n(acc_o, sPh_u + (uint32_t)(c * CHUNK_BF16) * 2,
                               sPl_u + (uint32_t)(c * CHUNK_BF16) * 2,
                               sKh_u + (uint32_t)buf * 2, sKl_u + (uint32_t)buf * 2,
                               lane, wm, wn);
            }
        }
        __syncthreads();   // protect sP region (bias overlay next m-tile)
    }

    // ---- final reductions of zh, ch across t4 and wn ----
    float zt[4], ct[4];
#pragma unroll
    for (int slot = 0; slot < 4; ++slot) {
        float z = zh[slot];
        z += __shfl_xor_sync(0xffffffffu, z, 1);
        z += __shfl_xor_sync(0xffffffffu, z, 2);
        zh[slot] = z;
        float c = ch[slot];
        c += __shfl_xor_sync(0xffffffffu, c, 1);
        c += __shfl_xor_sync(0xffffffffu, c, 2);
        ch[slot] = c;
    }
#pragma unroll
    for (int mb = 0; mb < 2; ++mb)
#pragma unroll
        for (int half = 0; half < 2; ++half) {
            const int rl = wm * 32 + mb * 16 + half * 8 + g;
            if (t4 == 0) sRed[rl * 4 + wn] = zh[mb * 2 + half];
        }
    __syncthreads();
#pragma unroll
    for (int mb = 0; mb < 2; ++mb)
#pragma unroll
        for (int half = 0; half < 2; ++half) {
            const int rl = wm * 32 + mb * 16 + half * 8 + g;
            zt[mb * 2 + half] = (sRed[rl * 4] + sRed[rl * 4 + 1]) +
                                (sRed[rl * 4 + 2] + sRed[rl * 4 + 3]);
        }
    __syncthreads();
#pragma unroll
    for (int mb = 0; mb < 2; ++mb)
#pragma unroll
        for (int half = 0; half < 2; ++half) {
            const int rl = wm * 32 + mb * 16 + half * 8 + g;
            if (t4 == 0) sRed[rl * 4 + wn] = ch[mb * 2 + half];
        }
    __syncthreads();
#pragma unroll
    for (int mb = 0; mb < 2; ++mb)
#pragma unroll
        for (int half = 0; half < 2; ++half) {
            const int rl = wm * 32 + mb * 16 + half * 8 + g;
            ct[mb * 2 + half] = (sRed[rl * 4] + sRed[rl * 4 + 1]) +
                                (sRed[rl * 4 + 2] + sRed[rl * 4 + 3]);
        }

    // ---- outputs ----
#pragma unroll
    for (int mb = 0; mb < 2; ++mb)
#pragma unroll
        for (int half = 0; half < 2; ++half) {
            const int slot = mb * 2 + half;
            const int rl = wm * 32 + mb * 16 + half * 8 + g;
            const long long n = nBase + rl;
            const float zi = 1.f / zt[slot];
            if (t4 == 0 && wn == 0) g_chz[h * N_ACT + n] = ct[slot] * zi;
#pragma unroll
            for (int nb = 0; nb < 4; ++nb) {
                const int d = wn * 32 + nb * 8 + t4 * 2;
                float2 o;
                o.x = acc_o[mb][nb][half * 2 + 0] * zi;
                o.y = acc_o[mb][nb][half * 2 + 1] * zi;
                *(float2*)&g_ctx[n * DMODEL + h * DKH + d] = o;
            }
        }
}

// ---------------------------------------------------------------------------
// influence finisher
// ---------------------------------------------------------------------------
__global__ void influence_kernel(float* __restrict__ inf_out) {
    const int n = blockIdx.x * 256 + threadIdx.x;
    if (n >= N_ACT) return;
    const float s = g_chz[n] + g_chz[N_ACT + n] + g_chz[2 * N_ACT + n] + g_chz[3 * N_ACT + n];
    inf_out[n] = g_valid[n] ? (0.25f * s / g_zb[n]) : 0.f;
}

// ---------------------------------------------------------------------------
// Topic GEMM (FFMA, small): C[n][o] = ctx . wt[o] + bt[o], valid-gated.
// ---------------------------------------------------------------------------
__global__ __launch_bounds__(256) void gemm_nt_kernel(
    const float* __restrict__ X, const float* __restrict__ W,
    const float* __restrict__ bias, float* __restrict__ out,
    int ldo, const int* __restrict__ valid)
{
    __shared__ float Xs[64 * 36];
    __shared__ float Ws[64 * 36];
    const int tid = threadIdx.x;
    const int rowBase = blockIdx.y * 64;
    const int colBase = blockIdx.x * 64;
    const int og = tid & 15, ngr = tid >> 4;

    float acc[4][4];
#pragma unroll
    for (int i = 0; i < 4; ++i)
#pragma unroll
        for (int j = 0; j < 4; ++j) acc[i][j] = 0.f;

    for (int kk = 0; kk < 512; kk += 32) {
#pragma unroll
        for (int jj = 0; jj < 2; ++jj) {
            int idx = tid + jj * 256;
            int r = idx >> 3, c4 = (idx & 7) << 2;
            *(float4*)&Xs[r * 36 + c4] = *(const float4*)&X[(rowBase + r) * 512 + kk + c4];
            *(float4*)&Ws[r * 36 + c4] = *(const float4*)&W[(colBase + r) * 512 + kk + c4];
        }
        __syncthreads();
#pragma unroll
        for (int k4 = 0; k4 < 32; k4 += 4) {
            float4 xv[4], wv[4];
#pragma unroll
            for (int i = 0; i < 4; ++i) xv[i] = *(const float4*)&Xs[(ngr * 4 + i) * 36 + k4];
#pragma unroll
            for (int j = 0; j < 4; ++j) wv[j] = *(const float4*)&Ws[(og * 4 + j) * 36 + k4];
#pragma unroll
            for (int i = 0; i < 4; ++i)
#pragma unroll
                for (int j = 0; j < 4; ++j) {
                    acc[i][j] = fmaf(xv[i].x, wv[j].x, acc[i][j]);
                    acc[i][j] = fmaf(xv[i].y, wv[j].y, acc[i][j]);
                    acc[i][j] = fmaf(xv[i].z, wv[j].z, acc[i][j]);
                    acc[i][j] = fmaf(xv[i].w, wv[j].w, acc[i][j]);
                }
        }
        __syncthreads();
    }
#pragma unroll
    for (int i = 0; i < 4; ++i) {
        int n = rowBase + ngr * 4 + i;
        float vmul = valid[n] ? 1.f : 0.f;
#pragma unroll
        for (int j = 0; j < 4; ++j) {
            int o = colBase + og * 4 + j;
            out[n * ldo + o] = vmul * (acc[i][j] + bias[o]);
        }
    }
}

// ---------------------------------------------------------------------------
extern "C" void kernel_launch(void* const* d_in, const int* in_sizes, int n_in,
                              void* d_out, int out_size) {
    const float* a      = (const float*)d_in[0];
    const float* bv     = (const float*)d_in[1];
    const void*  mraw   = (const void*)d_in[2];
    const float* weight = (const float*)d_in[3];
    const float* ipw    = (const float*)d_in[4];
    const float* ipb    = (const float*)d_in[5];
    const float* ow     = (const float*)d_in[6];
    const float* ob     = (const float*)d_in[7];
    float* out = (float*)d_out;

    void *pctx, *pwt, *pbt, *pvalid;
    cudaGetSymbolAddress(&pctx, g_ctx);
    cudaGetSymbolAddress(&pwt, g_wt);
    cudaGetSymbolAddress(&pbt, g_bt);
    cudaGetSymbolAddress(&pvalid, g_valid);
    void *pah, *pal, *pbh, *pbl, *pwh, *pwl;
    cudaGetSymbolAddress(&pah, g_ah); cudaGetSymbolAddress(&pal, g_al);
    cudaGetSymbolAddress(&pbh, g_bvh); cudaGetSymbolAddress(&pbl, g_bvl);
    cudaGetSymbolAddress(&pwh, g_wh); cudaGetSymbolAddress(&pwl, g_wl);

    cudaFuncSetAttribute(fused_attn_kernel, cudaFuncAttributeMaxDynamicSharedMemorySize,
                         FUSED_SMEM_BYTES);

    mask_detect_kernel<<<1, 256>>>((const unsigned int*)mraw);
    mask_repack_kernel<<<16384, 256>>>(mraw);

    conv_split_kernel<<<2048, 256>>>(a,  (__nv_bfloat16*)pah, (__nv_bfloat16*)pal, N_ACT * DMODEL / 4, 1);
    conv_split_kernel<<<2048, 256>>>(bv, (__nv_bfloat16*)pbh, (__nv_bfloat16*)pbl, N_KEY * DMODEL / 4, 1);
    conv_split_kernel<<<768, 256>>>(ipw, (__nv_bfloat16*)pwh, (__nv_bfloat16*)pwl, 3 * DMODEL * DMODEL / 4, 0);

    build_wt_kernel<<<(DKH * DMODEL + 255) / 256, 256>>>(ow, ob);

    proj_mma_kernel<<<dim3(12, 32), 256>>>(ipb);
    bias_stats_kernel<<<N_ACT, 256>>>(weight);

    fused_attn_kernel<<<dim3(32, 4), 512, FUSED_SMEM_BYTES>>>(weight);

    influence_kernel<<<16, 256>>>(out + N_ACT * DKH);

    gemm_nt_kernel<<<dim3(2, 64), 256>>>((const float*)pctx, (const float*)pwt,
                                         (const float*)pbt, out, DKH, (const int*)pvalid);
}

// round 15
// speedup vs baseline: 3.3025x; 1.0249x over previous
#include <cuda_runtime.h>
#include <cuda_bf16.h>
#include <cstdint>
#include <math.h>

#define N_ACT 4096
#define N_KEY 4096
#define DMODEL 512
#define NHEAD 4
#define DKH 128
#define NEGV (-1e9f)
#define QSCALE 0.08838834764831845f
#define LDT 40   // bf16 per smem tile row (32 data + 8 pad); 80B rows, 16B-aligned

// ---------------------------------------------------------------------------
// scratch (static device allocations — allowed)
// ---------------------------------------------------------------------------
__device__ __nv_bfloat16 g_ah[N_ACT * DMODEL],  g_al[N_ACT * DMODEL];
__device__ __nv_bfloat16 g_bvh[N_KEY * DMODEL], g_bvl[N_KEY * DMODEL];
__device__ __nv_bfloat16 g_wh[3 * DMODEL * DMODEL], g_wl[3 * DMODEL * DMODEL];
__device__ __nv_bfloat16 g_qh[N_ACT * DMODEL],  g_ql[N_ACT * DMODEL];
__device__ __nv_bfloat16 g_kh[N_KEY * DMODEL],  g_kl[N_KEY * DMODEL];
__device__ __nv_bfloat16 g_vth[DMODEL * N_KEY], g_vtl[DMODEL * N_KEY];
__device__ float g_ctx[N_ACT * DMODEL];
__device__ float g_wt[DKH * DMODEL];
__device__ float g_bt[DKH];
__device__ int   g_valid[N_ACT];
__device__ float g_mb[N_ACT];
__device__ float g_zb[N_ACT];
__device__ float g_chz[NHEAD * N_ACT];
__device__ unsigned char g_mask[(size_t)N_ACT * N_KEY];
__device__ int   g_mflag;

__device__ __forceinline__ float nanfix(float x) {
    if (isnan(x)) return 0.f;
    if (isinf(x)) return x > 0.f ? 1.f : -1.f;
    return x;
}

// Fast exp for x <= 0, FFMA-only. ~2e-6 rel error.
__device__ __forceinline__ float fexp(float x) {
    x = fminf(x, 0.f);
    x = fmaxf(x, -87.0f);
    const float LOG2E = 1.4426950408889634f;
    float t = fmaf(x, LOG2E, 12582912.f);
    float jf = t - 12582912.f;
    int ji = (__float_as_int(t) & 0x7FFFFF) - 0x400000;
    float r = fmaf(x, LOG2E, -jf);
    float g = r * 0.6931471805599453f;
    float p = fmaf(g, 0.0083333333f, 0.0416666666f);
    p = fmaf(p, g, 0.1666666666f);
    p = fmaf(p, g, 0.5f);
    p = fmaf(p, g, 1.0f);
    p = fmaf(p, g, 1.0f);
    return __int_as_float((ji + 127) << 23) * p;
}

__device__ __forceinline__ uint32_t smem_to_u32(const void* p) {
    uint32_t a;
    asm("{ .reg .u64 t; cvta.to.shared.u64 t, %1; cvt.u32.u64 %0, t; }" : "=r"(a) : "l"(p));
    return a;
}

// ---------------------------------------------------------------------------
// warp mma + ldmatrix (baseline PTX — compiles on the plain sm_103 target)
// ---------------------------------------------------------------------------
__device__ __forceinline__ void mma_bf16(float c[4], const uint32_t a[4], const uint32_t b[2]) {
    asm volatile("mma.sync.aligned.m16n8k16.row.col.f32.bf16.bf16.f32 "
                 "{%0,%1,%2,%3}, {%4,%5,%6,%7}, {%8,%9}, {%0,%1,%2,%3};"
                 : "+f"(c[0]), "+f"(c[1]), "+f"(c[2]), "+f"(c[3])
                 : "r"(a[0]), "r"(a[1]), "r"(a[2]), "r"(a[3]), "r"(b[0]), "r"(b[1]));
}

__device__ __forceinline__ void ldsm_x4(uint32_t r[4], uint32_t addr) {
    asm volatile("ldmatrix.sync.aligned.m8n8.x4.shared.b16 {%0,%1,%2,%3}, [%4];"
                 : "=r"(r[0]), "=r"(r[1]), "=r"(r[2]), "=r"(r[3]) : "r"(addr));
}

// warp tile 32m x 64n (proj kernel, 8 warps)
__device__ __forceinline__ void mma_chunk3_64n(
    float (&acc)[2][8][4],
    uint32_t aH, uint32_t aL, uint32_t bH, uint32_t bL,
    int lane, int wm, int wn)
{
    const int la15 = lane & 15;
    const int lhi  = (lane >> 4) << 3;
    const int brow = ((lane >> 4) << 3) + (lane & 7);
    const int bko  = ((lane >> 3) & 1) << 3;
#pragma unroll
    for (int kk = 0; kk < 2; ++kk) {
        const int kb = kk * 16;
        uint32_t fah[2][4], fal[2][4];
#pragma unroll
        for (int mb = 0; mb < 2; ++mb) {
            const uint32_t off = (uint32_t)((wm * 32 + mb * 16 + la15) * LDT + kb + lhi) * 2;
            ldsm_x4(fah[mb], aH + off);
            ldsm_x4(fal[mb], aL + off);
        }
#pragma unroll
        for (int nbp = 0; nbp < 4; ++nbp) {
            const uint32_t off = (uint32_t)((wn * 64 + nbp * 16 + brow) * LDT + kb + bko) * 2;
            uint32_t fbh[4], fbl[4];
            ldsm_x4(fbh, bH + off);
            ldsm_x4(fbl, bL + off);
#pragma unroll
            for (int mb = 0; mb < 2; ++mb) {
                mma_bf16(acc[mb][nbp * 2],     fah[mb], fbh);
                mma_bf16(acc[mb][nbp * 2],     fah[mb], fbl);
                mma_bf16(acc[mb][nbp * 2],     fal[mb], fbh);
                mma_bf16(acc[mb][nbp * 2 + 1], fah[mb], fbh + 2);
                mma_bf16(acc[mb][nbp * 2 + 1], fah[mb], fbl + 2);
                mma_bf16(acc[mb][nbp * 2 + 1], fal[mb], fbh + 2);
            }
        }
    }
}

// warp tile 32m x 32n (fused kernel, 16 warps: wm 0..3, wn 0..3)
__device__ __forceinline__ void mma_chunk3_32n(
    float (&acc)[2][4][4],
    uint32_t aH, uint32_t aL, uint32_t bH, uint32_t bL,
    int lane, int wm, int wn)
{
    const int la15 = lane & 15;
    const int lhi  = (lane >> 4) << 3;
    const int brow = ((lane >> 4) << 3) + (lane & 7);
    const int bko  = ((lane >> 3) & 1) << 3;
#pragma unroll
    for (int kk = 0; kk < 2; ++kk) {
        const int kb = kk * 16;
        uint32_t fah[2][4], fal[2][4];
#pragma unroll
        for (int mb = 0; mb < 2; ++mb) {
            const uint32_t off = (uint32_t)((wm * 32 + mb * 16 + la15) * LDT + kb + lhi) * 2;
            ldsm_x4(fah[mb], aH + off);
            ldsm_x4(fal[mb], aL + off);
        }
#pragma unroll
        for (int nbp = 0; nbp < 2; ++nbp) {
            const uint32_t off = (uint32_t)((wn * 32 + nbp * 16 + brow) * LDT + kb + bko) * 2;
            uint32_t fbh[4], fbl[4];
            ldsm_x4(fbh, bH + off);
            ldsm_x4(fbl, bL + off);
#pragma unroll
            for (int mb = 0; mb < 2; ++mb) {
                mma_bf16(acc[mb][nbp * 2],     fah[mb], fbh);
                mma_bf16(acc[mb][nbp * 2],     fah[mb], fbl);
                mma_bf16(acc[mb][nbp * 2],     fal[mb], fbh);
                mma_bf16(acc[mb][nbp * 2 + 1], fah[mb], fbh + 2);
                mma_bf16(acc[mb][nbp * 2 + 1], fah[mb], fbl + 2);
                mma_bf16(acc[mb][nbp * 2 + 1], fal[mb], fbh + 2);
            }
        }
    }
}

// ---------------------------------------------------------------------------
// mask dtype detect + repack
// ---------------------------------------------------------------------------
__global__ void mask_detect_kernel(const unsigned int* __restrict__ m) {
    __shared__ int cF, cHi;
    if (threadIdx.x == 0) { cF = 0; cHi = 0; }
    __syncthreads();
    int lf = 0, lh = 0;
    for (int i = threadIdx.x; i < 16384; i += 256) {
        unsigned int w = m[i];
        if (w == 0x3F800000u) lf++;
        else if ((w & 0xFFFFFF00u) != 0u) lh++;
    }
    atomicAdd(&cF, lf);
    atomicAdd(&cHi, lh);
    __syncthreads();
    if (threadIdx.x == 0) {
        if (cF > 16) g_mflag = 2;
        else if (cHi > 16) g_mflag = 0;
        else g_mflag = 1;
    }
}

__global__ void mask_repack_kernel(const void* __restrict__ mraw) {
    const long long i4 = (long long)blockIdx.x * 256 + threadIdx.x;
    if (i4 * 4 >= (long long)N_ACT * N_KEY) return;
    const int flag = g_mflag;
    uchar4 o;
    if (flag == 0) {
        uchar4 b = ((const uchar4*)mraw)[i4];
        o.x = b.x ? 1 : 0; o.y = b.y ? 1 : 0; o.z = b.z ? 1 : 0; o.w = b.w ? 1 : 0;
    } else if (flag == 1) {
        int4 b = ((const int4*)mraw)[i4];
        o.x = b.x ? 1 : 0; o.y = b.y ? 1 : 0; o.z = b.z ? 1 : 0; o.w = b.w ? 1 : 0;
    } else {
        float4 b = ((const float4*)mraw)[i4];
        o.x = (b.x != 0.f) ? 1 : 0; o.y = (b.y != 0.f) ? 1 : 0;
        o.z = (b.z != 0.f) ? 1 : 0; o.w = (b.w != 0.f) ? 1 : 0;
    }
    ((uchar4*)g_mask)[i4] = o;
}

// fp32 -> split bf16 (hi + lo)
__global__ void conv_split_kernel(const float* __restrict__ src,
                                  __nv_bfloat16* __restrict__ hi,
                                  __nv_bfloat16* __restrict__ lo,
                                  int n4, int fix) {
    int i = blockIdx.x * 256 + threadIdx.x;
    if (i >= n4) return;
    float4 v = ((const float4*)src)[i];
    if (fix) { v.x = nanfix(v.x); v.y = nanfix(v.y); v.z = nanfix(v.z); v.w = nanfix(v.w); }
    float a[4] = {v.x, v.y, v.z, v.w};
#pragma unroll
    for (int j = 0; j < 4; ++j) {
        __nv_bfloat16 h = __float2bfloat16(a[j]);
        hi[i * 4 + j] = h;
        lo[i * 4 + j] = __float2bfloat16(a[j] - __bfloat162float(h));
    }
}

__global__ void build_wt_kernel(const float* __restrict__ ow,
                                const float* __restrict__ ob) {
    int idx = blockIdx.x * 256 + threadIdx.x;
    if (idx < DKH * DMODEL) {
        int dk = idx >> 9, c = idx & 511;
        g_wt[idx] = 0.25f * (ow[dk * DMODEL + c] + ow[(dk + DKH) * DMODEL + c] +
                             ow[(dk + 2 * DKH) * DMODEL + c] + ow[(dk + 3 * DKH) * DMODEL + c]);
    }
    if (idx < DKH)
        g_bt[idx] = 0.25f * (ob[idx] + ob[idx + DKH] + ob[idx + 2 * DKH] + ob[idx + 3 * DKH]);
}

// ---------------------------------------------------------------------------
// Bias stats pre-pass: per row n -> Mb, Zb, valid.
// ---------------------------------------------------------------------------
__global__ __launch_bounds__(256) void bias_stats_kernel(const float* __restrict__ weight) {
    __shared__ float red[256];
    __shared__ int sv;
    const int n = blockIdx.x, tid = threadIdx.x;
    if (tid == 0) sv = 0;
    __syncthreads();
    const long long base = (long long)n * N_KEY;
    float b[16];
    float mx = -INFINITY; int anym = 0;
#pragma unroll
    for (int j = 0; j < 4; ++j) {
        int m = tid * 4 + j * 1024;
        float4 w = *(const float4*)&weight[base + m];
        uchar4 mk = *(const uchar4*)&g_mask[base + m];
        float b0 = mk.x ? nanfix(w.x) : NEGV;
        float b1 = mk.y ? nanfix(w.y) : NEGV;
        float b2 = mk.z ? nanfix(w.z) : NEGV;
        float b3 = mk.w ? nanfix(w.w) : NEGV;
        b[j*4+0] = b0; b[j*4+1] = b1; b[j*4+2] = b2; b[j*4+3] = b3;
        anym |= (mk.x | mk.y | mk.z | mk.w);
        mx = fmaxf(fmaxf(fmaxf(mx, b0), fmaxf(b1, b2)), b3);
    }
    if (anym) atomicOr(&sv, 1);
    red[tid] = mx;
    __syncthreads();
    for (int s = 128; s > 0; s >>= 1) {
        if (tid < s) red[tid] = fmaxf(red[tid], red[tid + s]);
        __syncthreads();
    }
    float Mb = red[0];
    __syncthreads();
    float zs = 0.f;
#pragma unroll
    for (int j = 0; j < 16; ++j) zs += fexp(b[j] - Mb);
    red[tid] = zs;
    __syncthreads();
    for (int s = 128; s > 0; s >>= 1) {
        if (tid < s) red[tid] += red[tid + s];
        __syncthreads();
    }
    if (tid == 0) { g_mb[n] = Mb; g_zb[n] = red[0]; g_valid[n] = sv; }
}

// ---------------------------------------------------------------------------
// QKV projection: grid (12, 32), 256 threads, ldmatrix fragments (passing).
// ---------------------------------------------------------------------------
__global__ __launch_bounds__(256) void proj_mma_kernel(const float* __restrict__ ipb) {
    __shared__ __align__(16) unsigned char smraw[4 * 128 * LDT * 2];
    __nv_bfloat16* sm = (__nv_bfloat16*)smraw;
    __nv_bfloat16* sAh = sm;
    __nv_bfloat16* sAl = sm + 128 * LDT;
    __nv_bfloat16* sBh = sm + 2 * 128 * LDT;
    __nv_bfloat16* sBl = sm + 3 * 128 * LDT;
    const int ot = blockIdx.x, nt = blockIdx.y;
    const int which = ot >> 2;
    const __nv_bfloat16* Xh = (which == 0) ? g_ah : g_bvh;
    const __nv_bfloat16* Xl = (which == 0) ? g_al : g_bvl;
    const __nv_bfloat16* Wh = g_wh + (long long)ot * 128 * DMODEL;
    const __nv_bfloat16* Wl = g_wl + (long long)ot * 128 * DMODEL;

    const int tid = threadIdx.x;
    const int lane = tid & 31, warp = tid >> 5;
    const int wm = warp >> 1, wn = warp & 1;
    const int g = lane >> 2, t4 = lane & 3;
    const int lr = tid >> 2, lc = (tid & 3) * 8;
    const uint32_t aHa = smem_to_u32(sAh), aLa = smem_to_u32(sAl);
    const uint32_t bHa = smem_to_u32(sBh), bLa = smem_to_u32(sBl);

    float acc[2][8][4];
#pragma unroll
    for (int i = 0; i < 2; ++i)
#pragma unroll
        for (int j = 0; j < 8; ++j)
#pragma unroll
            for (int r = 0; r < 4; ++r) acc[i][j][r] = 0.f;

    for (int c = 0; c < 16; ++c) {
        const long long co = (long long)c * 32 + lc;
        *(uint4*)&sAh[lr * LDT + lc] = *(const uint4*)&Xh[((long long)nt * 128 + lr) * DMODEL + co];
        *(uint4*)&sAh[(lr + 64) * LDT + lc] = *(const uint4*)&Xh[((long long)nt * 128 + lr + 64) * DMODEL + co];
        *(uint4*)&sAl[lr * LDT + lc] = *(const uint4*)&Xl[((long long)nt * 128 + lr) * DMODEL + co];
        *(uint4*)&sAl[(lr + 64) * LDT + lc] = *(const uint4*)&Xl[((long long)nt * 128 + lr + 64) * DMODEL + co];
        *(uint4*)&sBh[lr * LDT + lc] = *(const uint4*)&Wh[(long long)lr * DMODEL + co];
        *(uint4*)&sBh[(lr + 64) * LDT + lc] = *(const uint4*)&Wh[(long long)(lr + 64) * DMODEL + co];
        *(uint4*)&sBl[lr * LDT + lc] = *(const uint4*)&Wl[(long long)lr * DMODEL + co];
        *(uint4*)&sBl[(lr + 64) * LDT + lc] = *(const uint4*)&Wl[(long long)(lr + 64) * DMODEL + co];
        __syncthreads();
        mma_chunk3_64n(acc, aHa, aLa, bHa, bLa, lane, wm, wn);
        __syncthreads();
    }

    const float scale = (which == 0) ? QSCALE : 1.f;
#pragma unroll
    for (int mb = 0; mb < 2; ++mb)
#pragma unroll
        for (int nb = 0; nb < 8; ++nb)
#pragma unroll
            for (int half = 0; half < 2; ++half) {
                const long long n = (long long)nt * 128 + wm * 32 + mb * 16 + g + half * 8;
                const int og = ot * 128 + wn * 64 + nb * 8 + t4 * 2;
                float v0 = scale * (acc[mb][nb][half * 2 + 0] + ipb[og]);
                float v1 = scale * (acc[mb][nb][half * 2 + 1] + ipb[og + 1]);
                __nv_bfloat16 h0 = __float2bfloat16(v0);
                __nv_bfloat16 l0 = __float2bfloat16(v0 - __bfloat162float(h0));
                __nv_bfloat16 h1 = __float2bfloat16(v1);
                __nv_bfloat16 l1 = __float2bfloat16(v1 - __bfloat162float(h1));
                if (which == 0) {
                    g_qh[n * DMODEL + og] = h0; g_qh[n * DMODEL + og + 1] = h1;
                    g_ql[n * DMODEL + og] = l0; g_ql[n * DMODEL + og + 1] = l1;
                } else if (which == 1) {
                    const int c = og - 512;
                    g_kh[n * DMODEL + c] = h0; g_kh[n * DMODEL + c + 1] = h1;
                    g_kl[n * DMODEL + c] = l0; g_kl[n * DMODEL + c + 1] = l1;
                } else {
                    const long long d = og - 1024;
                    g_vth[d * N_KEY + n] = h0; g_vth[(d + 1) * N_KEY + n] = h1;
                    g_vtl[d * N_KEY + n] = l0; g_vtl[(d + 1) * N_KEY + n] = l1;
                }
            }
}

// ---------------------------------------------------------------------------
// FUSED flash attention: grid (32 nt, 4 h), 512 threads (16 warps, 4x4),
// warp tile 32m x 32n, 1 CTA/SM. All phase-boundary global loads prefetched.
// ---------------------------------------------------------------------------
#define CHUNK_BF16 (128 * LDT)
#define SQ_OFF    0
#define SQL_OFF   (4 * CHUNK_BF16)
#define SP_OFF    (8 * CHUNK_BF16)
#define SPL_OFF   (12 * CHUNK_BF16)
#define SKH_OFF   (16 * CHUNK_BF16)
#define SKL_OFF   (18 * CHUNK_BF16)
#define SMEM_BF16_TOTAL (20 * CHUNK_BF16)
#define FUSED_SMEM_BYTES (SMEM_BF16_TOTAL * 2 + 128 * 4 * 4)

__global__ __launch_bounds__(512, 1) void fused_attn_kernel(const float* __restrict__ weight) {
    extern __shared__ __align__(16) unsigned char smem_raw[];
    __nv_bfloat16* sm = (__nv_bfloat16*)smem_raw;
    __nv_bfloat16* sQh = sm + SQ_OFF;
    __nv_bfloat16* sQl = sm + SQL_OFF;
    __nv_bfloat16* sPh = sm + SP_OFF;
    __nv_bfloat16* sPl = sm + SPL_OFF;
    float* sBias = (float*)(sm + SP_OFF);            // overlay on sP region
    float* sRed  = (float*)(sm + SMEM_BF16_TOTAL);   // 128*4 floats

    const uint32_t sQh_u = smem_to_u32(sQh), sQl_u = smem_to_u32(sQl);
    const uint32_t sPh_u = smem_to_u32(sPh), sPl_u = smem_to_u32(sPl);
    const uint32_t sKh_u = smem_to_u32(sm + SKH_OFF), sKl_u = smem_to_u32(sm + SKL_OFF);

    const int nt = blockIdx.x, h = blockIdx.y;
    const int tid = threadIdx.x;
    const int lane = tid & 31, warp = tid >> 5;
    const int wm = warp >> 2, wn = warp & 3;         // 4x4 warp grid
    const int g = lane >> 2, t4 = lane & 3;
    const long long nBase = (long long)nt * 128;
    const int sr = tid >> 2;             // staging row 0..127 (512 threads)
    const int sc = (tid & 3) * 8;        // staging col
    const int so = sr * LDT + sc;
    const long long browg = (nBase + sr) * (long long)N_KEY;   // bias row base

    // stage Q (4 chunks, hi+lo)
    for (int u = tid; u < 2048; u += 512) {
        const int c = u >> 9;
        const int r = (u >> 2) & 127;
        const int cc = (u & 3) * 8;
        const long long gofs = (nBase + r) * DMODEL + h * DKH + c * 32 + cc;
        *(uint4*)&sQh[(c * 128 + r) * LDT + cc] = *(const uint4*)&g_qh[gofs];
        *(uint4*)&sQl[(c * 128 + r) * LDT + cc] = *(const uint4*)&g_ql[gofs];
    }

    float acc_o[2][4][4];
#pragma unroll
    for (int i = 0; i < 2; ++i)
#pragma unroll
        for (int j = 0; j < 4; ++j)
#pragma unroll
            for (int r = 0; r < 4; ++r) acc_o[i][j][r] = 0.f;

    float zh[4] = {0.f, 0.f, 0.f, 0.f};
    float ch[4] = {0.f, 0.f, 0.f, 0.f};
    float Mold[4] = {-INFINITY, -INFINITY, -INFINITY, -INFINITY};
    float Mbr[4];
#pragma unroll
    for (int mb = 0; mb < 2; ++mb)
#pragma unroll
        for (int half = 0; half < 2; ++half)
            Mbr[mb * 2 + half] = g_mb[nBase + wm * 32 + mb * 16 + half * 8 + g];

    // prefetch K chunk0 of m-tile 0
    uint4 kh0, kl0;
    {
        const long long gk = (long long)sr * DMODEL + h * DKH + sc;
        kh0 = *(const uint4*)&g_kh[gk];
        kl0 = *(const uint4*)&g_kl[gk];
    }

    __syncthreads();

    for (int mt = 0; mt < N_KEY / 128; ++mt) {
        const long long mBase = (long long)mt * 128;
        float acc_s[2][4][4];
#pragma unroll
        for (int i = 0; i < 2; ++i)
#pragma unroll
            for (int j = 0; j < 4; ++j)
#pragma unroll
                for (int r = 0; r < 4; ++r) acc_s[i][j][r] = 0.f;

        // ---- QK^T over 4 K-chunks + bias tile prefetch into sBias ----
        {
            uint4 ph0 = kh0, pl0 = kl0;
            for (int c = 0; c < 4; ++c) {
                const int buf = (c & 1) * CHUNK_BF16;
                *(uint4*)&sm[SKH_OFF + buf + so] = ph0;
                *(uint4*)&sm[SKL_OFF + buf + so] = pl0;
                // bias slice for columns [c*32, c*32+32)
                {
                    const long long bcol = mBase + c * 32 + sc;
                    float4 w0 = *(const float4*)&weight[browg + bcol];
                    float4 w1 = *(const float4*)&weight[browg + bcol + 4];
                    uchar4 m0 = *(const uchar4*)&g_mask[browg + bcol];
                    uchar4 m1 = *(const uchar4*)&g_mask[browg + bcol + 4];
                    float4 b0, b1;
                    b0.x = m0.x ? nanfix(w0.x) : NEGV;
                    b0.y = m0.y ? nanfix(w0.y) : NEGV;
                    b0.z = m0.z ? nanfix(w0.z) : NEGV;
                    b0.w = m0.w ? nanfix(w0.w) : NEGV;
                    b1.x = m1.x ? nanfix(w1.x) : NEGV;
                    b1.y = m1.y ? nanfix(w1.y) : NEGV;
                    b1.z = m1.z ? nanfix(w1.z) : NEGV;
                    b1.w = m1.w ? nanfix(w1.w) : NEGV;
                    *(float4*)&sBias[sr * 132 + c * 32 + sc] = b0;
                    *(float4*)&sBias[sr * 132 + c * 32 + sc + 4] = b1;
                }
                __syncthreads();
                if (c < 3) {
                    const long long gk = (mBase + sr) * DMODEL + h * DKH + (c + 1) * 32 + sc;
                    ph0 = *(const uint4*)&g_kh[gk];
                    pl0 = *(const uint4*)&g_kl[gk];
                }
                mma_chunk3_32n(acc_s, sQh_u + (uint32_t)(c * CHUNK_BF16) * 2,
                               sQl_u + (uint32_t)(c * CHUNK_BF16) * 2,
                               sKh_u + (uint32_t)buf * 2, sKl_u + (uint32_t)buf * 2,
                               lane, wm, wn);
            }
        }

        // prefetch V chunk0 (hidden under the softmax phases)
        uint4 vh0, vl0;
        {
            const long long gv = (long long)(h * DKH + sr) * N_KEY + mBase + sc;
            vh0 = *(const uint4*)&g_vth[gv];
            vl0 = *(const uint4*)&g_vtl[gv];
        }

        // ---- bias add (from sBias) + tile row max ----
#pragma unroll
        for (int mb = 0; mb < 2; ++mb)
#pragma unroll
            for (int half = 0; half < 2; ++half) {
                const int rl = wm * 32 + mb * 16 + half * 8 + g;
                float smax = -INFINITY;
#pragma unroll
                for (int nb = 0; nb < 4; ++nb) {
                    const int col = wn * 32 + nb * 8 + t4 * 2;
                    const float b0 = sBias[rl * 132 + col];
                    const float b1 = sBias[rl * 132 + col + 1];
                    const float s0 = acc_s[mb][nb][half * 2 + 0] + b0;
                    const float s1 = acc_s[mb][nb][half * 2 + 1] + b1;
                    acc_s[mb][nb][half * 2 + 0] = s0;
                    acc_s[mb][nb][half * 2 + 1] = s1;
                    smax = fmaxf(smax, fmaxf(s0, s1));
                }
                smax = fmaxf(smax, __shfl_xor_sync(0xffffffffu, smax, 1));
                smax = fmaxf(smax, __shfl_xor_sync(0xffffffffu, smax, 2));
                if (t4 == 0) sRed[rl * 4 + wn] = smax;
            }
        __syncthreads();

        // ---- online softmax update ----
#pragma unroll
        for (int mb = 0; mb < 2; ++mb)
#pragma unroll
            for (int half = 0; half < 2; ++half) {
                const int slot = mb * 2 + half;
                const int rl = wm * 32 + mb * 16 + half * 8 + g;
                const float Mtile = fmaxf(fmaxf(sRed[rl * 4], sRed[rl * 4 + 1]),
                                          fmaxf(sRed[rl * 4 + 2], sRed[rl * 4 + 3]));
                const float Mnew = fmaxf(Mold[slot], Mtile);
                const float alpha = fexp(Mold[slot] - Mnew);
                Mold[slot] = Mnew;
                float z = zh[slot] * alpha;
                float cc = ch[slot] * alpha;
#pragma unroll
                for (int nb = 0; nb < 4; ++nb) {
                    const int col = wn * 32 + nb * 8 + t4 * 2;
#pragma unroll
                    for (int r = 0; r < 2; ++r) {
                        const float s = acc_s[mb][nb][half * 2 + r];
                        const float p = fexp(s - Mnew);
                        acc_s[mb][nb][half * 2 + r] = p;
                        z += p;
                        const float b = sBias[rl * 132 + col + r];
                        cc = fmaf(fexp(b - Mbr[slot]), p, cc);
                    }
                    acc_o[mb][nb][half * 2 + 0] *= alpha;
                    acc_o[mb][nb][half * 2 + 1] *= alpha;
                }
                zh[slot] = z;
                ch[slot] = cc;
            }
        __syncthreads();   // all bias reads done before P overwrites the overlay

        // ---- write P (split bf16) into smem chunk layout ----
#pragma unroll
        for (int mb = 0; mb < 2; ++mb)
#pragma unroll
            for (int half = 0; half < 2; ++half) {
                const int rl = wm * 32 + mb * 16 + half * 8 + g;
#pragma unroll
                for (int nb = 0; nb < 4; ++nb) {
                    const int col = wn * 32 + nb * 8 + t4 * 2;
                    const int chunk = col >> 5, c32 = col & 31;
                    const float p0 = acc_s[mb][nb][half * 2 + 0];
                    const float p1 = acc_s[mb][nb][half * 2 + 1];
                    const __nv_bfloat16 h0 = __float2bfloat16(p0);
                    const __nv_bfloat16 h1 = __float2bfloat16(p1);
                    const __nv_bfloat16 l0 = __float2bfloat16(p0 - __bfloat162float(h0));
                    const __nv_bfloat16 l1 = __float2bfloat16(p1 - __bfloat162float(h1));
                    const uint32_t ph = (uint32_t)__bfloat16_as_ushort(h0) |
                                        ((uint32_t)__bfloat16_as_ushort(h1) << 16);
                    const uint32_t pl = (uint32_t)__bfloat16_as_ushort(l0) |
                                        ((uint32_t)__bfloat16_as_ushort(l1) << 16);
                    *(uint32_t*)&sPh[(chunk * 128 + rl) * LDT + c32] = ph;
                    *(uint32_t*)&sPl[(chunk * 128 + rl) * LDT + c32] = pl;
                }
            }

        // prefetch K chunk0 of next m-tile (hidden under the ctx phase)
        if (mt < N_KEY / 128 - 1) {
            const long long gk = (mBase + 128 + sr) * DMODEL + h * DKH + sc;
            kh0 = *(const uint4*)&g_kh[gk];
            kl0 = *(const uint4*)&g_kl[gk];
        }

        // ---- ctx accumulate: P @ V^T over 4 m-chunks, double-buffered ----
        {
            uint4 ph0 = vh0, pl0 = vl0;
            for (int c = 0; c < 4; ++c) {
                const int buf = (c & 1) * CHUNK_BF16;
                *(uint4*)&sm[SKH_OFF + buf + so] = ph0;
                *(uint4*)&sm[SKL_OFF + buf + so] = pl0;
                __syncthreads();
                if (c < 3) {
                    const long long gv = (long long)(h * DKH + sr) * N_KEY + mBase + (c + 1) * 32 + sc;
                    ph0 = *(const uint4*)&g_vth[gv];
                    pl0 = *(const uint4*)&g_vtl[gv];
                }
                mma_chunk3_32n(acc_o, sPh_u + (uint32_t)(c * CHUNK_BF16) * 2,
                               sPl_u + (uint32_t)(c * CHUNK_BF16) * 2,
                               sKh_u + (uint32_t)buf * 2, sKl_u + (uint32_t)buf * 2,
                               lane, wm, wn);
            }
        }
        __syncthreads();   // protect sP region (bias overlay next m-tile)
    }

    // ---- final reductions of zh, ch across t4 and wn ----
    float zt[4], ct[4];
#pragma unroll
    for (int slot = 0; slot < 4; ++slot) {
        float z = zh[slot];
        z += __shfl_xor_sync(0xffffffffu, z, 1);
        z += __shfl_xor_sync(0xffffffffu, z, 2);
        zh[slot] = z;
        float c = ch[slot];
        c += __shfl_xor_sync(0xffffffffu, c, 1);
        c += __shfl_xor_sync(0xffffffffu, c, 2);
        ch[slot] = c;
    }
#pragma unroll
    for (int mb = 0; mb < 2; ++mb)
#pragma unroll
        for (int half = 0; half < 2; ++half) {
            const int rl = wm * 32 + mb * 16 + half * 8 + g;
            if (t4 == 0) sRed[rl * 4 + wn] = zh[mb * 2 + half];
        }
    __syncthreads();
#pragma unroll
    for (int mb = 0; mb < 2; ++mb)
#pragma unroll
        for (int half = 0; half < 2; ++half) {
            const int rl = wm * 32 + mb * 16 + half * 8 + g;
            zt[mb * 2 + half] = (sRed[rl * 4] + sRed[rl * 4 + 1]) +
                                (sRed[rl * 4 + 2] + sRed[rl * 4 + 3]);
        }
    __syncthreads();
#pragma unroll
    for (int mb = 0; mb < 2; ++mb)
#pragma unroll
        for (int half = 0; half < 2; ++half) {
            const int rl = wm * 32 + mb * 16 + half * 8 + g;
            if (t4 == 0) sRed[rl * 4 + wn] = ch[mb * 2 + half];
        }
    __syncthreads();
#pragma unroll
    for (int mb = 0; mb < 2; ++mb)
#pragma unroll
        for (int half = 0; half < 2; ++half) {
            const int rl = wm * 32 + mb * 16 + half * 8 + g;
            ct[mb * 2 + half] = (sRed[rl * 4] + sRed[rl * 4 + 1]) +
                                (sRed[rl * 4 + 2] + sRed[rl * 4 + 3]);
        }

    // ---- outputs ----
#pragma unroll
    for (int mb = 0; mb < 2; ++mb)
#pragma unroll
        for (int half = 0; half < 2; ++half) {
            const int slot = mb * 2 + half;
            const int rl = wm * 32 + mb * 16 + half * 8 + g;
            const long long n = nBase + rl;
            const float zi = 1.f / zt[slot];
            if (t4 == 0 && wn == 0) g_chz[h * N_ACT + n] = ct[slot] * zi;
#pragma unroll
            for (int nb = 0; nb < 4; ++nb) {
                const int d = wn * 32 + nb * 8 + t4 * 2;
                float2 o;
                o.x = acc_o[mb][nb][half * 2 + 0] * zi;
                o.y = acc_o[mb][nb][half * 2 + 1] * zi;
                *(float2*)&g_ctx[n * DMODEL + h * DKH + d] = o;
            }
        }
}

// ---------------------------------------------------------------------------
// influence finisher
// ---------------------------------------------------------------------------
__global__ void influence_kernel(float* __restrict__ inf_out) {
    const int n = blockIdx.x * 256 + threadIdx.x;
    if (n >= N_ACT) return;
    const float s = g_chz[n] + g_chz[N_ACT + n] + g_chz[2 * N_ACT + n] + g_chz[3 * N_ACT + n];
    inf_out[n] = g_valid[n] ? (0.25f * s / g_zb[n]) : 0.f;
}

// ---------------------------------------------------------------------------
// Topic GEMM (FFMA, small): C[n][o] = ctx . wt[o] + bt[o], valid-gated.
// ---------------------------------------------------------------------------
__global__ __launch_bounds__(256) void gemm_nt_kernel(
    const float* __restrict__ X, const float* __restrict__ W,
    const float* __restrict__ bias, float* __restrict__ out,
    int ldo, const int* __restrict__ valid)
{
    __shared__ float Xs[64 * 36];
    __shared__ float Ws[64 * 36];
    const int tid = threadIdx.x;
    const int rowBase = blockIdx.y * 64;
    const int colBase = blockIdx.x * 64;
    const int og = tid & 15, ngr = tid >> 4;

    float acc[4][4];
#pragma unroll
    for (int i = 0; i < 4; ++i)
#pragma unroll
        for (int j = 0; j < 4; ++j) acc[i][j] = 0.f;

    for (int kk = 0; kk < 512; kk += 32) {
#pragma unroll
        for (int jj = 0; jj < 2; ++jj) {
            int idx = tid + jj * 256;
            int r = idx >> 3, c4 = (idx & 7) << 2;
            *(float4*)&Xs[r * 36 + c4] = *(const float4*)&X[(rowBase + r) * 512 + kk + c4];
            *(float4*)&Ws[r * 36 + c4] = *(const float4*)&W[(colBase + r) * 512 + kk + c4];
        }
        __syncthreads();
#pragma unroll
        for (int k4 = 0; k4 < 32; k4 += 4) {
            float4 xv[4], wv[4];
#pragma unroll
            for (int i = 0; i < 4; ++i) xv[i] = *(const float4*)&Xs[(ngr * 4 + i) * 36 + k4];
#pragma unroll
            for (int j = 0; j < 4; ++j) wv[j] = *(const float4*)&Ws[(og * 4 + j) * 36 + k4];
#pragma unroll
            for (int i = 0; i < 4; ++i)
#pragma unroll
                for (int j = 0; j < 4; ++j) {
                    acc[i][j] = fmaf(xv[i].x, wv[j].x, acc[i][j]);
                    acc[i][j] = fmaf(xv[i].y, wv[j].y, acc[i][j]);
                    acc[i][j] = fmaf(xv[i].z, wv[j].z, acc[i][j]);
                    acc[i][j] = fmaf(xv[i].w, wv[j].w, acc[i][j]);
                }
        }
        __syncthreads();
    }
#pragma unroll
    for (int i = 0; i < 4; ++i) {
        int n = rowBase + ngr * 4 + i;
        float vmul = valid[n] ? 1.f : 0.f;
#pragma unroll
        for (int j = 0; j < 4; ++j) {
            int o = colBase + og * 4 + j;
            out[n * ldo + o] = vmul * (acc[i][j] + bias[o]);
        }
    }
}

// ---------------------------------------------------------------------------
extern "C" void kernel_launch(void* const* d_in, const int* in_sizes, int n_in,
                              void* d_out, int out_size) {
    const float* a      = (const float*)d_in[0];
    const float* bv     = (const float*)d_in[1];
    const void*  mraw   = (const void*)d_in[2];
    const float* weight = (const float*)d_in[3];
    const float* ipw    = (const float*)d_in[4];
    const float* ipb    = (const float*)d_in[5];
    const float* ow     = (const float*)d_in[6];
    const float* ob     = (const float*)d_in[7];
    float* out = (float*)d_out;

    void *pctx, *pwt, *pbt, *pvalid;
    cudaGetSymbolAddress(&pctx, g_ctx);
    cudaGetSymbolAddress(&pwt, g_wt);
    cudaGetSymbolAddress(&pbt, g_bt);
    cudaGetSymbolAddress(&pvalid, g_valid);
    void *pah, *pal, *pbh, *pbl, *pwh, *pwl;
    cudaGetSymbolAddress(&pah, g_ah); cudaGetSymbolAddress(&pal, g_al);
    cudaGetSymbolAddress(&pbh, g_bvh); cudaGetSymbolAddress(&pbl, g_bvl);
    cudaGetSymbolAddress(&pwh, g_wh); cudaGetSymbolAddress(&pwl, g_wl);

    cudaFuncSetAttribute(fused_attn_kernel, cudaFuncAttributeMaxDynamicSharedMemorySize,
                         FUSED_SMEM_BYTES);

    mask_detect_kernel<<<1, 256>>>((const unsigned int*)mraw);
    mask_repack_kernel<<<16384, 256>>>(mraw);

    conv_split_kernel<<<2048, 256>>>(a,  (__nv_bfloat16*)pah, (__nv_bfloat16*)pal, N_ACT * DMODEL / 4, 1);
    conv_split_kernel<<<2048, 256>>>(bv, (__nv_bfloat16*)pbh, (__nv_bfloat16*)pbl, N_KEY * DMODEL / 4, 1);
    conv_split_kernel<<<768, 256>>>(ipw, (__nv_bfloat16*)pwh, (__nv_bfloat16*)pwl, 3 * DMODEL * DMODEL / 4, 0);

    build_wt_kernel<<<(DKH * DMODEL + 255) / 256, 256>>>(ow, ob);

    proj_mma_kernel<<<dim3(12, 32), 256>>>(ipb);
    bias_stats_kernel<<<N_ACT, 256>>>(weight);

    fused_attn_kernel<<<dim3(32, 4), 512, FUSED_SMEM_BYTES>>>(weight);

    influence_kernel<<<16, 256>>>(out + N_ACT * DKH);

    gemm_nt_kernel<<<dim3(2, 64), 256>>>((const float*)pctx, (const float*)pwt,
                                         (const float*)pbt, out, DKH, (const int*)pvalid);
}

// round 16
// speedup vs baseline: 3.5753x; 1.0826x over previous
#include <cuda_runtime.h>
#include <cuda_bf16.h>
#include <cstdint>
#include <math.h>

#define N_ACT 4096
#define N_KEY 4096
#define DMODEL 512
#define NHEAD 4
#define DKH 128
#define NEGV (-1e9f)
#define QSCALE 0.08838834764831845f
#define LDT 40   // bf16 per smem tile row (32 data + 8 pad); 80B rows, 16B-aligned

// ---------------------------------------------------------------------------
// scratch (static device allocations — allowed)
// ---------------------------------------------------------------------------
__device__ __nv_bfloat16 g_ah[N_ACT * DMODEL],  g_al[N_ACT * DMODEL];
__device__ __nv_bfloat16 g_bvh[N_KEY * DMODEL], g_bvl[N_KEY * DMODEL];
__device__ __nv_bfloat16 g_wh[3 * DMODEL * DMODEL], g_wl[3 * DMODEL * DMODEL];
__device__ __nv_bfloat16 g_qh[N_ACT * DMODEL],  g_ql[N_ACT * DMODEL];
__device__ __nv_bfloat16 g_kh[N_KEY * DMODEL],  g_kl[N_KEY * DMODEL];
__device__ __nv_bfloat16 g_vth[DMODEL * N_KEY], g_vtl[DMODEL * N_KEY];
__device__ float g_ctx[N_ACT * DMODEL];
__device__ float g_wt[DKH * DMODEL];
__device__ float g_bt[DKH];
__device__ int   g_valid[N_ACT];
__device__ float g_mb[N_ACT];
__device__ float g_zb[N_ACT];
__device__ float g_chz[NHEAD * N_ACT];
__device__ unsigned char g_mask[(size_t)N_ACT * N_KEY];
__device__ int   g_mflag;

__device__ __forceinline__ float nanfix(float x) {
    if (isnan(x)) return 0.f;
    if (isinf(x)) return x > 0.f ? 1.f : -1.f;
    return x;
}

// Fast exp for x <= 0 via MUFU.EX2 (runs on the MUFU pipe, off the FMA pipe).
// ex2.approx rel err ~2^-22. ex2(-inf) = 0 reproduces the alpha=0 / masked cases.
__device__ __forceinline__ float fexp(float x) {
    float r;
    asm("ex2.approx.ftz.f32 %0, %1;" : "=f"(r) : "f"(x * 1.4426950408889634f));
    return r;
}

__device__ __forceinline__ uint32_t smem_to_u32(const void* p) {
    uint32_t a;
    asm("{ .reg .u64 t; cvta.to.shared.u64 t, %1; cvt.u32.u64 %0, t; }" : "=r"(a) : "l"(p));
    return a;
}

// ---------------------------------------------------------------------------
// warp mma + ldmatrix (baseline PTX — compiles on the plain sm_103 target)
// ---------------------------------------------------------------------------
__device__ __forceinline__ void mma_bf16(float c[4], const uint32_t a[4], const uint32_t b[2]) {
    asm volatile("mma.sync.aligned.m16n8k16.row.col.f32.bf16.bf16.f32 "
                 "{%0,%1,%2,%3}, {%4,%5,%6,%7}, {%8,%9}, {%0,%1,%2,%3};"
                 : "+f"(c[0]), "+f"(c[1]), "+f"(c[2]), "+f"(c[3])
                 : "r"(a[0]), "r"(a[1]), "r"(a[2]), "r"(a[3]), "r"(b[0]), "r"(b[1]));
}

__device__ __forceinline__ void ldsm_x4(uint32_t r[4], uint32_t addr) {
    asm volatile("ldmatrix.sync.aligned.m8n8.x4.shared.b16 {%0,%1,%2,%3}, [%4];"
                 : "=r"(r[0]), "=r"(r[1]), "=r"(r[2]), "=r"(r[3]) : "r"(addr));
}

// warp tile 32m x 64n (proj kernel, 8 warps)
__device__ __forceinline__ void mma_chunk3_64n(
    float (&acc)[2][8][4],
    uint32_t aH, uint32_t aL, uint32_t bH, uint32_t bL,
    int lane, int wm, int wn)
{
    const int la15 = lane & 15;
    const int lhi  = (lane >> 4) << 3;
    const int brow = ((lane >> 4) << 3) + (lane & 7);
    const int bko  = ((lane >> 3) & 1) << 3;
#pragma unroll
    for (int kk = 0; kk < 2; ++kk) {
        const int kb = kk * 16;
        uint32_t fah[2][4], fal[2][4];
#pragma unroll
        for (int mb = 0; mb < 2; ++mb) {
            const uint32_t off = (uint32_t)((wm * 32 + mb * 16 + la15) * LDT + kb + lhi) * 2;
            ldsm_x4(fah[mb], aH + off);
            ldsm_x4(fal[mb], aL + off);
        }
#pragma unroll
        for (int nbp = 0; nbp < 4; ++nbp) {
            const uint32_t off = (uint32_t)((wn * 64 + nbp * 16 + brow) * LDT + kb + bko) * 2;
            uint32_t fbh[4], fbl[4];
            ldsm_x4(fbh, bH + off);
            ldsm_x4(fbl, bL + off);
#pragma unroll
            for (int mb = 0; mb < 2; ++mb) {
                mma_bf16(acc[mb][nbp * 2],     fah[mb], fbh);
                mma_bf16(acc[mb][nbp * 2],     fah[mb], fbl);
                mma_bf16(acc[mb][nbp * 2],     fal[mb], fbh);
                mma_bf16(acc[mb][nbp * 2 + 1], fah[mb], fbh + 2);
                mma_bf16(acc[mb][nbp * 2 + 1], fah[mb], fbl + 2);
                mma_bf16(acc[mb][nbp * 2 + 1], fal[mb], fbh + 2);
            }
        }
    }
}

// warp tile 32m x 32n (fused kernel, 16 warps: wm 0..3, wn 0..3)
__device__ __forceinline__ void mma_chunk3_32n(
    float (&acc)[2][4][4],
    uint32_t aH, uint32_t aL, uint32_t bH, uint32_t bL,
    int lane, int wm, int wn)
{
    const int la15 = lane & 15;
    const int lhi  = (lane >> 4) << 3;
    const int brow = ((lane >> 4) << 3) + (lane & 7);
    const int bko  = ((lane >> 3) & 1) << 3;
#pragma unroll
    for (int kk = 0; kk < 2; ++kk) {
        const int kb = kk * 16;
        uint32_t fah[2][4], fal[2][4];
#pragma unroll
        for (int mb = 0; mb < 2; ++mb) {
            const uint32_t off = (uint32_t)((wm * 32 + mb * 16 + la15) * LDT + kb + lhi) * 2;
            ldsm_x4(fah[mb], aH + off);
            ldsm_x4(fal[mb], aL + off);
        }
#pragma unroll
        for (int nbp = 0; nbp < 2; ++nbp) {
            const uint32_t off = (uint32_t)((wn * 32 + nbp * 16 + brow) * LDT + kb + bko) * 2;
            uint32_t fbh[4], fbl[4];
            ldsm_x4(fbh, bH + off);
            ldsm_x4(fbl, bL + off);
#pragma unroll
            for (int mb = 0; mb < 2; ++mb) {
                mma_bf16(acc[mb][nbp * 2],     fah[mb], fbh);
                mma_bf16(acc[mb][nbp * 2],     fah[mb], fbl);
                mma_bf16(acc[mb][nbp * 2],     fal[mb], fbh);
                mma_bf16(acc[mb][nbp * 2 + 1], fah[mb], fbh + 2);
                mma_bf16(acc[mb][nbp * 2 + 1], fah[mb], fbl + 2);
                mma_bf16(acc[mb][nbp * 2 + 1], fal[mb], fbh + 2);
            }
        }
    }
}

// ---------------------------------------------------------------------------
// mask dtype detect + repack
// ---------------------------------------------------------------------------
__global__ void mask_detect_kernel(const unsigned int* __restrict__ m) {
    __shared__ int cF, cHi;
    if (threadIdx.x == 0) { cF = 0; cHi = 0; }
    __syncthreads();
    int lf = 0, lh = 0;
    for (int i = threadIdx.x; i < 16384; i += 256) {
        unsigned int w = m[i];
        if (w == 0x3F800000u) lf++;
        else if ((w & 0xFFFFFF00u) != 0u) lh++;
    }
    atomicAdd(&cF, lf);
    atomicAdd(&cHi, lh);
    __syncthreads();
    if (threadIdx.x == 0) {
        if (cF > 16) g_mflag = 2;
        else if (cHi > 16) g_mflag = 0;
        else g_mflag = 1;
    }
}

__global__ void mask_repack_kernel(const void* __restrict__ mraw) {
    const long long i4 = (long long)blockIdx.x * 256 + threadIdx.x;
    if (i4 * 4 >= (long long)N_ACT * N_KEY) return;
    const int flag = g_mflag;
    uchar4 o;
    if (flag == 0) {
        uchar4 b = ((const uchar4*)mraw)[i4];
        o.x = b.x ? 1 : 0; o.y = b.y ? 1 : 0; o.z = b.z ? 1 : 0; o.w = b.w ? 1 : 0;
    } else if (flag == 1) {
        int4 b = ((const int4*)mraw)[i4];
        o.x = b.x ? 1 : 0; o.y = b.y ? 1 : 0; o.z = b.z ? 1 : 0; o.w = b.w ? 1 : 0;
    } else {
        float4 b = ((const float4*)mraw)[i4];
        o.x = (b.x != 0.f) ? 1 : 0; o.y = (b.y != 0.f) ? 1 : 0;
        o.z = (b.z != 0.f) ? 1 : 0; o.w = (b.w != 0.f) ? 1 : 0;
    }
    ((uchar4*)g_mask)[i4] = o;
}

// fp32 -> split bf16 (hi + lo)
__global__ void conv_split_kernel(const float* __restrict__ src,
                                  __nv_bfloat16* __restrict__ hi,
                                  __nv_bfloat16* __restrict__ lo,
                                  int n4, int fix) {
    int i = blockIdx.x * 256 + threadIdx.x;
    if (i >= n4) return;
    float4 v = ((const float4*)src)[i];
    if (fix) { v.x = nanfix(v.x); v.y = nanfix(v.y); v.z = nanfix(v.z); v.w = nanfix(v.w); }
    float a[4] = {v.x, v.y, v.z, v.w};
#pragma unroll
    for (int j = 0; j < 4; ++j) {
        __nv_bfloat16 h = __float2bfloat16(a[j]);
        hi[i * 4 + j] = h;
        lo[i * 4 + j] = __float2bfloat16(a[j] - __bfloat162float(h));
    }
}

__global__ void build_wt_kernel(const float* __restrict__ ow,
                                const float* __restrict__ ob) {
    int idx = blockIdx.x * 256 + threadIdx.x;
    if (idx < DKH * DMODEL) {
        int dk = idx >> 9, c = idx & 511;
        g_wt[idx] = 0.25f * (ow[dk * DMODEL + c] + ow[(dk + DKH) * DMODEL + c] +
                             ow[(dk + 2 * DKH) * DMODEL + c] + ow[(dk + 3 * DKH) * DMODEL + c]);
    }
    if (idx < DKH)
        g_bt[idx] = 0.25f * (ob[idx] + ob[idx + DKH] + ob[idx + 2 * DKH] + ob[idx + 3 * DKH]);
}

// ---------------------------------------------------------------------------
// Bias stats pre-pass: per row n -> Mb, Zb, valid.
// ---------------------------------------------------------------------------
__global__ __launch_bounds__(256) void bias_stats_kernel(const float* __restrict__ weight) {
    __shared__ float red[256];
    __shared__ int sv;
    const int n = blockIdx.x, tid = threadIdx.x;
    if (tid == 0) sv = 0;
    __syncthreads();
    const long long base = (long long)n * N_KEY;
    float b[16];
    float mx = -INFINITY; int anym = 0;
#pragma unroll
    for (int j = 0; j < 4; ++j) {
        int m = tid * 4 + j * 1024;
        float4 w = *(const float4*)&weight[base + m];
        uchar4 mk = *(const uchar4*)&g_mask[base + m];
        float b0 = mk.x ? nanfix(w.x) : NEGV;
        float b1 = mk.y ? nanfix(w.y) : NEGV;
        float b2 = mk.z ? nanfix(w.z) : NEGV;
        float b3 = mk.w ? nanfix(w.w) : NEGV;
        b[j*4+0] = b0; b[j*4+1] = b1; b[j*4+2] = b2; b[j*4+3] = b3;
        anym |= (mk.x | mk.y | mk.z | mk.w);
        mx = fmaxf(fmaxf(fmaxf(mx, b0), fmaxf(b1, b2)), b3);
    }
    if (anym) atomicOr(&sv, 1);
    red[tid] = mx;
    __syncthreads();
    for (int s = 128; s > 0; s >>= 1) {
        if (tid < s) red[tid] = fmaxf(red[tid], red[tid + s]);
        __syncthreads();
    }
    float Mb = red[0];
    __syncthreads();
    float zs = 0.f;
#pragma unroll
    for (int j = 0; j < 16; ++j) zs += fexp(b[j] - Mb);
    red[tid] = zs;
    __syncthreads();
    for (int s = 128; s > 0; s >>= 1) {
        if (tid < s) red[tid] += red[tid + s];
        __syncthreads();
    }
    if (tid == 0) { g_mb[n] = Mb; g_zb[n] = red[0]; g_valid[n] = sv; }
}

// ---------------------------------------------------------------------------
// QKV projection: grid (12, 32), 256 threads, ldmatrix fragments (passing).
// ---------------------------------------------------------------------------
__global__ __launch_bounds__(256) void proj_mma_kernel(const float* __restrict__ ipb) {
    __shared__ __align__(16) unsigned char smraw[4 * 128 * LDT * 2];
    __nv_bfloat16* sm = (__nv_bfloat16*)smraw;
    __nv_bfloat16* sAh = sm;
    __nv_bfloat16* sAl = sm + 128 * LDT;
    __nv_bfloat16* sBh = sm + 2 * 128 * LDT;
    __nv_bfloat16* sBl = sm + 3 * 128 * LDT;
    const int ot = blockIdx.x, nt = blockIdx.y;
    const int which = ot >> 2;
    const __nv_bfloat16* Xh = (which == 0) ? g_ah : g_bvh;
    const __nv_bfloat16* Xl = (which == 0) ? g_al : g_bvl;
    const __nv_bfloat16* Wh = g_wh + (long long)ot * 128 * DMODEL;
    const __nv_bfloat16* Wl = g_wl + (long long)ot * 128 * DMODEL;

    const int tid = threadIdx.x;
    const int lane = tid & 31, warp = tid >> 5;
    const int wm = warp >> 1, wn = warp & 1;
    const int g = lane >> 2, t4 = lane & 3;
    const int lr = tid >> 2, lc = (tid & 3) * 8;
    const uint32_t aHa = smem_to_u32(sAh), aLa = smem_to_u32(sAl);
    const uint32_t bHa = smem_to_u32(sBh), bLa = smem_to_u32(sBl);

    float acc[2][8][4];
#pragma unroll
    for (int i = 0; i < 2; ++i)
#pragma unroll
        for (int j = 0; j < 8; ++j)
#pragma unroll
            for (int r = 0; r < 4; ++r) acc[i][j][r] = 0.f;

    for (int c = 0; c < 16; ++c) {
        const long long co = (long long)c * 32 + lc;
        *(uint4*)&sAh[lr * LDT + lc] = *(const uint4*)&Xh[((long long)nt * 128 + lr) * DMODEL + co];
        *(uint4*)&sAh[(lr + 64) * LDT + lc] = *(const uint4*)&Xh[((long long)nt * 128 + lr + 64) * DMODEL + co];
        *(uint4*)&sAl[lr * LDT + lc] = *(const uint4*)&Xl[((long long)nt * 128 + lr) * DMODEL + co];
        *(uint4*)&sAl[(lr + 64) * LDT + lc] = *(const uint4*)&Xl[((long long)nt * 128 + lr + 64) * DMODEL + co];
        *(uint4*)&sBh[lr * LDT + lc] = *(const uint4*)&Wh[(long long)lr * DMODEL + co];
        *(uint4*)&sBh[(lr + 64) * LDT + lc] = *(const uint4*)&Wh[(long long)(lr + 64) * DMODEL + co];
        *(uint4*)&sBl[lr * LDT + lc] = *(const uint4*)&Wl[(long long)lr * DMODEL + co];
        *(uint4*)&sBl[(lr + 64) * LDT + lc] = *(const uint4*)&Wl[(long long)(lr + 64) * DMODEL + co];
        __syncthreads();
        mma_chunk3_64n(acc, aHa, aLa, bHa, bLa, lane, wm, wn);
        __syncthreads();
    }

    const float scale = (which == 0) ? QSCALE : 1.f;
#pragma unroll
    for (int mb = 0; mb < 2; ++mb)
#pragma unroll
        for (int nb = 0; nb < 8; ++nb)
#pragma unroll
            for (int half = 0; half < 2; ++half) {
                const long long n = (long long)nt * 128 + wm * 32 + mb * 16 + g + half * 8;
                const int og = ot * 128 + wn * 64 + nb * 8 + t4 * 2;
                float v0 = scale * (acc[mb][nb][half * 2 + 0] + ipb[og]);
                float v1 = scale * (acc[mb][nb][half * 2 + 1] + ipb[og + 1]);
                __nv_bfloat16 h0 = __float2bfloat16(v0);
                __nv_bfloat16 l0 = __float2bfloat16(v0 - __bfloat162float(h0));
                __nv_bfloat16 h1 = __float2bfloat16(v1);
                __nv_bfloat16 l1 = __float2bfloat16(v1 - __bfloat162float(h1));
                if (which == 0) {
                    g_qh[n * DMODEL + og] = h0; g_qh[n * DMODEL + og + 1] = h1;
                    g_ql[n * DMODEL + og] = l0; g_ql[n * DMODEL + og + 1] = l1;
                } else if (which == 1) {
                    const int c = og - 512;
                    g_kh[n * DMODEL + c] = h0; g_kh[n * DMODEL + c + 1] = h1;
                    g_kl[n * DMODEL + c] = l0; g_kl[n * DMODEL + c + 1] = l1;
                } else {
                    const long long d = og - 1024;
                    g_vth[d * N_KEY + n] = h0; g_vth[(d + 1) * N_KEY + n] = h1;
                    g_vtl[d * N_KEY + n] = l0; g_vtl[(d + 1) * N_KEY + n] = l1;
                }
            }
}

// ---------------------------------------------------------------------------
// FUSED flash attention: grid (32 nt, 4 h), 512 threads (16 warps, 4x4),
// warp tile 32m x 32n, 1 CTA/SM. Phase-boundary loads prefetched; MUFU exp.
// ---------------------------------------------------------------------------
#define CHUNK_BF16 (128 * LDT)
#define SQ_OFF    0
#define SQL_OFF   (4 * CHUNK_BF16)
#define SP_OFF    (8 * CHUNK_BF16)
#define SPL_OFF   (12 * CHUNK_BF16)
#define SKH_OFF   (16 * CHUNK_BF16)
#define SKL_OFF   (18 * CHUNK_BF16)
#define SMEM_BF16_TOTAL (20 * CHUNK_BF16)
#define FUSED_SMEM_BYTES (SMEM_BF16_TOTAL * 2 + 128 * 4 * 4)

__global__ __launch_bounds__(512, 1) void fused_attn_kernel(const float* __restrict__ weight) {
    extern __shared__ __align__(16) unsigned char smem_raw[];
    __nv_bfloat16* sm = (__nv_bfloat16*)smem_raw;
    __nv_bfloat16* sQh = sm + SQ_OFF;
    __nv_bfloat16* sQl = sm + SQL_OFF;
    __nv_bfloat16* sPh = sm + SP_OFF;
    __nv_bfloat16* sPl = sm + SPL_OFF;
    float* sBias = (float*)(sm + SP_OFF);            // overlay on sP region
    float* sRed  = (float*)(sm + SMEM_BF16_TOTAL);   // 128*4 floats

    const uint32_t sQh_u = smem_to_u32(sQh), sQl_u = smem_to_u32(sQl);
    const uint32_t sPh_u = smem_to_u32(sPh), sPl_u = smem_to_u32(sPl);
    const uint32_t sKh_u = smem_to_u32(sm + SKH_OFF), sKl_u = smem_to_u32(sm + SKL_OFF);

    const int nt = blockIdx.x, h = blockIdx.y;
    const int tid = threadIdx.x;
    const int lane = tid & 31, warp = tid >> 5;
    const int wm = warp >> 2, wn = warp & 3;         // 4x4 warp grid
    const int g = lane >> 2, t4 = lane & 3;
    const long long nBase = (long long)nt * 128;
    const int sr = tid >> 2;             // staging row 0..127 (512 threads)
    const int sc = (tid & 3) * 8;        // staging col
    const int so = sr * LDT + sc;
    const long long browg = (nBase + sr) * (long long)N_KEY;   // bias row base

    // stage Q (4 chunks, hi+lo)
    for (int u = tid; u < 2048; u += 512) {
        const int c = u >> 9;
        const int r = (u >> 2) & 127;
        const int cc = (u & 3) * 8;
        const long long gofs = (nBase + r) * DMODEL + h * DKH + c * 32 + cc;
        *(uint4*)&sQh[(c * 128 + r) * LDT + cc] = *(const uint4*)&g_qh[gofs];
        *(uint4*)&sQl[(c * 128 + r) * LDT + cc] = *(const uint4*)&g_ql[gofs];
    }

    float acc_o[2][4][4];
#pragma unroll
    for (int i = 0; i < 2; ++i)
#pragma unroll
        for (int j = 0; j < 4; ++j)
#pragma unroll
            for (int r = 0; r < 4; ++r) acc_o[i][j][r] = 0.f;

    float zh[4] = {0.f, 0.f, 0.f, 0.f};
    float ch[4] = {0.f, 0.f, 0.f, 0.f};
    float Mold[4] = {-INFINITY, -INFINITY, -INFINITY, -INFINITY};
    float Mbr[4];
#pragma unroll
    for (int mb = 0; mb < 2; ++mb)
#pragma unroll
        for (int half = 0; half < 2; ++half)
            Mbr[mb * 2 + half] = g_mb[nBase + wm * 32 + mb * 16 + half * 8 + g];

    // prefetch K chunk0 of m-tile 0
    uint4 kh0, kl0;
    {
        const long long gk = (long long)sr * DMODEL + h * DKH + sc;
        kh0 = *(const uint4*)&g_kh[gk];
        kl0 = *(const uint4*)&g_kl[gk];
    }

    __syncthreads();

    for (int mt = 0; mt < N_KEY / 128; ++mt) {
        const long long mBase = (long long)mt * 128;
        float acc_s[2][4][4];
#pragma unroll
        for (int i = 0; i < 2; ++i)
#pragma unroll
            for (int j = 0; j < 4; ++j)
#pragma unroll
                for (int r = 0; r < 4; ++r) acc_s[i][j][r] = 0.f;

        // ---- QK^T over 4 K-chunks + bias tile prefetch into sBias ----
        {
            uint4 ph0 = kh0, pl0 = kl0;
            for (int c = 0; c < 4; ++c) {
                const int buf = (c & 1) * CHUNK_BF16;
                *(uint4*)&sm[SKH_OFF + buf + so] = ph0;
                *(uint4*)&sm[SKL_OFF + buf + so] = pl0;
                // bias slice for columns [c*32, c*32+32)
                {
                    const long long bcol = mBase + c * 32 + sc;
                    float4 w0 = *(const float4*)&weight[browg + bcol];
                    float4 w1 = *(const float4*)&weight[browg + bcol + 4];
                    uchar4 m0 = *(const uchar4*)&g_mask[browg + bcol];
                    uchar4 m1 = *(const uchar4*)&g_mask[browg + bcol + 4];
                    float4 b0, b1;
                    b0.x = m0.x ? nanfix(w0.x) : NEGV;
                    b0.y = m0.y ? nanfix(w0.y) : NEGV;
                    b0.z = m0.z ? nanfix(w0.z) : NEGV;
                    b0.w = m0.w ? nanfix(w0.w) : NEGV;
                    b1.x = m1.x ? nanfix(w1.x) : NEGV;
                    b1.y = m1.y ? nanfix(w1.y) : NEGV;
                    b1.z = m1.z ? nanfix(w1.z) : NEGV;
                    b1.w = m1.w ? nanfix(w1.w) : NEGV;
                    *(float4*)&sBias[sr * 132 + c * 32 + sc] = b0;
                    *(float4*)&sBias[sr * 132 + c * 32 + sc + 4] = b1;
                }
                __syncthreads();
                if (c < 3) {
                    const long long gk = (mBase + sr) * DMODEL + h * DKH + (c + 1) * 32 + sc;
                    ph0 = *(const uint4*)&g_kh[gk];
                    pl0 = *(const uint4*)&g_kl[gk];
                }
                mma_chunk3_32n(acc_s, sQh_u + (uint32_t)(c * CHUNK_BF16) * 2,
                               sQl_u + (uint32_t)(c * CHUNK_BF16) * 2,
                               sKh_u + (uint32_t)buf * 2, sKl_u + (uint32_t)buf * 2,
                               lane, wm, wn);
            }
        }

        // prefetch V chunk0 (hidden under the softmax phases)
        uint4 vh0, vl0;
        {
            const long long gv = (long long)(h * DKH + sr) * N_KEY + mBase + sc;
            vh0 = *(const uint4*)&g_vth[gv];
            vl0 = *(const uint4*)&g_vtl[gv];
        }

        // ---- bias add (from sBias) + tile row max ----
#pragma unroll
        for (int mb = 0; mb < 2; ++mb)
#pragma unroll
            for (int half = 0; half < 2; ++half) {
                const int rl = wm * 32 + mb * 16 + half * 8 + g;
                float smax = -INFINITY;
#pragma unroll
                for (int nb = 0; nb < 4; ++nb) {
                    const int col = wn * 32 + nb * 8 + t4 * 2;
                    const float b0 = sBias[rl * 132 + col];
                    const float b1 = sBias[rl * 132 + col + 1];
                    const float s0 = acc_s[mb][nb][half * 2 + 0] + b0;
                    const float s1 = acc_s[mb][nb][half * 2 + 1] + b1;
                    acc_s[mb][nb][half * 2 + 0] = s0;
                    acc_s[mb][nb][half * 2 + 1] = s1;
                    smax = fmaxf(smax, fmaxf(s0, s1));
                }
                smax = fmaxf(smax, __shfl_xor_sync(0xffffffffu, smax, 1));
                smax = fmaxf(smax, __shfl_xor_sync(0xffffffffu, smax, 2));
                if (t4 == 0) sRed[rl * 4 + wn] = smax;
            }
        __syncthreads();

        // ---- online softmax update (MUFU exp) ----
#pragma unroll
        for (int mb = 0; mb < 2; ++mb)
#pragma unroll
            for (int half = 0; half < 2; ++half) {
                const int slot = mb * 2 + half;
                const int rl = wm * 32 + mb * 16 + half * 8 + g;
                const float Mtile = fmaxf(fmaxf(sRed[rl * 4], sRed[rl * 4 + 1]),
                                          fmaxf(sRed[rl * 4 + 2], sRed[rl * 4 + 3]));
                const float Mnew = fmaxf(Mold[slot], Mtile);
                const float alpha = fexp(Mold[slot] - Mnew);
                Mold[slot] = Mnew;
                float z = zh[slot] * alpha;
                float cc = ch[slot] * alpha;
#pragma unroll
                for (int nb = 0; nb < 4; ++nb) {
                    const int col = wn * 32 + nb * 8 + t4 * 2;
#pragma unroll
                    for (int r = 0; r < 2; ++r) {
                        const float s = acc_s[mb][nb][half * 2 + r];
                        const float p = fexp(s - Mnew);
                        acc_s[mb][nb][half * 2 + r] = p;
                        z += p;
                        const float b = sBias[rl * 132 + col + r];
                        cc = fmaf(fexp(b - Mbr[slot]), p, cc);
                    }
                    acc_o[mb][nb][half * 2 + 0] *= alpha;
                    acc_o[mb][nb][half * 2 + 1] *= alpha;
                }
                zh[slot] = z;
                ch[slot] = cc;
            }
        __syncthreads();   // all bias reads done before P overwrites the overlay

        // ---- write P (split bf16) into smem chunk layout ----
#pragma unroll
        for (int mb = 0; mb < 2; ++mb)
#pragma unroll
            for (int half = 0; half < 2; ++half) {
                const int rl = wm * 32 + mb * 16 + half * 8 + g;
#pragma unroll
                for (int nb = 0; nb < 4; ++nb) {
                    const int col = wn * 32 + nb * 8 + t4 * 2;
                    const int chunk = col >> 5, c32 = col & 31;
                    const float p0 = acc_s[mb][nb][half * 2 + 0];
                    const float p1 = acc_s[mb][nb][half * 2 + 1];
                    const __nv_bfloat16 h0 = __float2bfloat16(p0);
                    const __nv_bfloat16 h1 = __float2bfloat16(p1);
                    const __nv_bfloat16 l0 = __float2bfloat16(p0 - __bfloat162float(h0));
                    const __nv_bfloat16 l1 = __float2bfloat16(p1 - __bfloat162float(h1));
                    const uint32_t ph = (uint32_t)__bfloat16_as_ushort(h0) |
                                        ((uint32_t)__bfloat16_as_ushort(h1) << 16);
                    const uint32_t pl = (uint32_t)__bfloat16_as_ushort(l0) |
                                        ((uint32_t)__bfloat16_as_ushort(l1) << 16);
                    *(uint32_t*)&sPh[(chunk * 128 + rl) * LDT + c32] = ph;
                    *(uint32_t*)&sPl[(chunk * 128 + rl) * LDT + c32] = pl;
                }
            }

        // prefetch K chunk0 of next m-tile (hidden under the ctx phase)
        if (mt < N_KEY / 128 - 1) {
            const long long gk = (mBase + 128 + sr) * DMODEL + h * DKH + sc;
            kh0 = *(const uint4*)&g_kh[gk];
            kl0 = *(const uint4*)&g_kl[gk];
        }

        // ---- ctx accumulate: P @ V^T over 4 m-chunks, double-buffered ----
        {
            uint4 ph0 = vh0, pl0 = vl0;
            for (int c = 0; c < 4; ++c) {
                const int buf = (c & 1) * CHUNK_BF16;
                *(uint4*)&sm[SKH_OFF + buf + so] = ph0;
                *(uint4*)&sm[SKL_OFF + buf + so] = pl0;
                __syncthreads();
                if (c < 3) {
                    const long long gv = (long long)(h * DKH + sr) * N_KEY + mBase + (c + 1) * 32 + sc;
                    ph0 = *(const uint4*)&g_vth[gv];
                    pl0 = *(const uint4*)&g_vtl[gv];
                }
                mma_chunk3_32n(acc_o, sPh_u + (uint32_t)(c * CHUNK_BF16) * 2,
                               sPl_u + (uint32_t)(c * CHUNK_BF16) * 2,
                               sKh_u + (uint32_t)buf * 2, sKl_u + (uint32_t)buf * 2,
                               lane, wm, wn);
            }
        }
        __syncthreads();   // protect sP region (bias overlay next m-tile)
    }

    // ---- final reductions of zh, ch across t4 and wn ----
    float zt[4], ct[4];
#pragma unroll
    for (int slot = 0; slot < 4; ++slot) {
        float z = zh[slot];
        z += __shfl_xor_sync(0xffffffffu, z, 1);
        z += __shfl_xor_sync(0xffffffffu, z, 2);
        zh[slot] = z;
        float c = ch[slot];
        c += __shfl_xor_sync(0xffffffffu, c, 1);
        c += __shfl_xor_sync(0xffffffffu, c, 2);
        ch[slot] = c;
    }
#pragma unroll
    for (int mb = 0; mb < 2; ++mb)
#pragma unroll
        for (int half = 0; half < 2; ++half) {
            const int rl = wm * 32 + mb * 16 + half * 8 + g;
            if (t4 == 0) sRed[rl * 4 + wn] = zh[mb * 2 + half];
        }
    __syncthreads();
#pragma unroll
    for (int mb = 0; mb < 2; ++mb)
#pragma unroll
        for (int half = 0; half < 2; ++half) {
            const int rl = wm * 32 + mb * 16 + half * 8 + g;
            zt[mb * 2 + half] = (sRed[rl * 4] + sRed[rl * 4 + 1]) +
                                (sRed[rl * 4 + 2] + sRed[rl * 4 + 3]);
        }
    __syncthreads();
#pragma unroll
    for (int mb = 0; mb < 2; ++mb)
#pragma unroll
        for (int half = 0; half < 2; ++half) {
            const int rl = wm * 32 + mb * 16 + half * 8 + g;
            if (t4 == 0) sRed[rl * 4 + wn] = ch[mb * 2 + half];
        }
    __syncthreads();
#pragma unroll
    for (int mb = 0; mb < 2; ++mb)
#pragma unroll
        for (int half = 0; half < 2; ++half) {
            const int rl = wm * 32 + mb * 16 + half * 8 + g;
            ct[mb * 2 + half] = (sRed[rl * 4] + sRed[rl * 4 + 1]) +
                                (sRed[rl * 4 + 2] + sRed[rl * 4 + 3]);
        }

    // ---- outputs ----
#pragma unroll
    for (int mb = 0; mb < 2; ++mb)
#pragma unroll
        for (int half = 0; half < 2; ++half) {
            const int slot = mb * 2 + half;
            const int rl = wm * 32 + mb * 16 + half * 8 + g;
            const long long n = nBase + rl;
            const float zi = 1.f / zt[slot];
            if (t4 == 0 && wn == 0) g_chz[h * N_ACT + n] = ct[slot] * zi;
#pragma unroll
            for (int nb = 0; nb < 4; ++nb) {
                const int d = wn * 32 + nb * 8 + t4 * 2;
                float2 o;
                o.x = acc_o[mb][nb][half * 2 + 0] * zi;
                o.y = acc_o[mb][nb][half * 2 + 1] * zi;
                *(float2*)&g_ctx[n * DMODEL + h * DKH + d] = o;
            }
        }
}

// ---------------------------------------------------------------------------
// influence finisher
// ---------------------------------------------------------------------------
__global__ void influence_kernel(float* __restrict__ inf_out) {
    const int n = blockIdx.x * 256 + threadIdx.x;
    if (n >= N_ACT) return;
    const float s = g_chz[n] + g_chz[N_ACT + n] + g_chz[2 * N_ACT + n] + g_chz[3 * N_ACT + n];
    inf_out[n] = g_valid[n] ? (0.25f * s / g_zb[n]) : 0.f;
}

// ---------------------------------------------------------------------------
// Topic GEMM (FFMA, small): C[n][o] = ctx . wt[o] + bt[o], valid-gated.
// ---------------------------------------------------------------------------
__global__ __launch_bounds__(256) void gemm_nt_kernel(
    const float* __restrict__ X, const float* __restrict__ W,
    const float* __restrict__ bias, float* __restrict__ out,
    int ldo, const int* __restrict__ valid)
{
    __shared__ float Xs[64 * 36];
    __shared__ float Ws[64 * 36];
    const int tid = threadIdx.x;
    const int rowBase = blockIdx.y * 64;
    const int colBase = blockIdx.x * 64;
    const int og = tid & 15, ngr = tid >> 4;

    float acc[4][4];
#pragma unroll
    for (int i = 0; i < 4; ++i)
#pragma unroll
        for (int j = 0; j < 4; ++j) acc[i][j] = 0.f;

    for (int kk = 0; kk < 512; kk += 32) {
#pragma unroll
        for (int jj = 0; jj < 2; ++jj) {
            int idx = tid + jj * 256;
            int r = idx >> 3, c4 = (idx & 7) << 2;
            *(float4*)&Xs[r * 36 + c4] = *(const float4*)&X[(rowBase + r) * 512 + kk + c4];
            *(float4*)&Ws[r * 36 + c4] = *(const float4*)&W[(colBase + r) * 512 + kk + c4];
        }
        __syncthreads();
#pragma unroll
        for (int k4 = 0; k4 < 32; k4 += 4) {
            float4 xv[4], wv[4];
#pragma unroll
            for (int i = 0; i < 4; ++i) xv[i] = *(const float4*)&Xs[(ngr * 4 + i) * 36 + k4];
#pragma unroll
            for (int j = 0; j < 4; ++j) wv[j] = *(const float4*)&Ws[(og * 4 + j) * 36 + k4];
#pragma unroll
            for (int i = 0; i < 4; ++i)
#pragma unroll
                for (int j = 0; j < 4; ++j) {
                    acc[i][j] = fmaf(xv[i].x, wv[j].x, acc[i][j]);
                    acc[i][j] = fmaf(xv[i].y, wv[j].y, acc[i][j]);
                    acc[i][j] = fmaf(xv[i].z, wv[j].z, acc[i][j]);
                    acc[i][j] = fmaf(xv[i].w, wv[j].w, acc[i][j]);
                }
        }
        __syncthreads();
    }
#pragma unroll
    for (int i = 0; i < 4; ++i) {
        int n = rowBase + ngr * 4 + i;
        float vmul = valid[n] ? 1.f : 0.f;
#pragma unroll
        for (int j = 0; j < 4; ++j) {
            int o = colBase + og * 4 + j;
            out[n * ldo + o] = vmul * (acc[i][j] + bias[o]);
        }
    }
}

// ---------------------------------------------------------------------------
extern "C" void kernel_launch(void* const* d_in, const int* in_sizes, int n_in,
                              void* d_out, int out_size) {
    const float* a      = (const float*)d_in[0];
    const float* bv     = (const float*)d_in[1];
    const void*  mraw   = (const void*)d_in[2];
    const float* weight = (const float*)d_in[3];
    const float* ipw    = (const float*)d_in[4];
    const float* ipb    = (const float*)d_in[5];
    const float* ow     = (const float*)d_in[6];
    const float* ob     = (const float*)d_in[7];
    float* out = (float*)d_out;

    void *pctx, *pwt, *pbt, *pvalid;
    cudaGetSymbolAddress(&pctx, g_ctx);
    cudaGetSymbolAddress(&pwt, g_wt);
    cudaGetSymbolAddress(&pbt, g_bt);
    cudaGetSymbolAddress(&pvalid, g_valid);
    void *pah, *pal, *pbh, *pbl, *pwh, *pwl;
    cudaGetSymbolAddress(&pah, g_ah); cudaGetSymbolAddress(&pal, g_al);
    cudaGetSymbolAddress(&pbh, g_bvh); cudaGetSymbolAddress(&pbl, g_bvl);
    cudaGetSymbolAddress(&pwh, g_wh); cudaGetSymbolAddress(&pwl, g_wl);

    cudaFuncSetAttribute(fused_attn_kernel, cudaFuncAttributeMaxDynamicSharedMemorySize,
                         FUSED_SMEM_BYTES);

    mask_detect_kernel<<<1, 256>>>((const unsigned int*)mraw);
    mask_repack_kernel<<<16384, 256>>>(mraw);

    conv_split_kernel<<<2048, 256>>>(a,  (__nv_bfloat16*)pah, (__nv_bfloat16*)pal, N_ACT * DMODEL / 4, 1);
    conv_split_kernel<<<2048, 256>>>(bv, (__nv_bfloat16*)pbh, (__nv_bfloat16*)pbl, N_KEY * DMODEL / 4, 1);
    conv_split_kernel<<<768, 256>>>(ipw, (__nv_bfloat16*)pwh, (__nv_bfloat16*)pwl, 3 * DMODEL * DMODEL / 4, 0);

    build_wt_kernel<<<(DKH * DMODEL + 255) / 256, 256>>>(ow, ob);

    proj_mma_kernel<<<dim3(12, 32), 256>>>(ipb);
    bias_stats_kernel<<<N_ACT, 256>>>(weight);

    fused_attn_kernel<<<dim3(32, 4), 512, FUSED_SMEM_BYTES>>>(weight);

    influence_kernel<<<16, 256>>>(out + N_ACT * DKH);

    gemm_nt_kernel<<<dim3(2, 64), 256>>>((const float*)pctx, (const float*)pwt,
                                         (const float*)pbt, out, DKH, (const int*)pvalid);
}

// round 17
// speedup vs baseline: 3.6141x; 1.0108x over previous
#include <cuda_runtime.h>
#include <cuda_bf16.h>
#include <cstdint>
#include <math.h>

#define N_ACT 4096
#define N_KEY 4096
#define DMODEL 512
#define NHEAD 4
#define DKH 128
#define NEGV (-1e9f)
#define QSCALE 0.08838834764831845f
#define LDT 40   // bf16 per smem tile row (32 data + 8 pad); 80B rows, 16B-aligned

#define BARW(id) asm volatile("bar.sync %0, %1;" :: "r"(id), "r"(128) : "memory")

// ---------------------------------------------------------------------------
// scratch (static device allocations — allowed)
// ---------------------------------------------------------------------------
__device__ __nv_bfloat16 g_ah[N_ACT * DMODEL],  g_al[N_ACT * DMODEL];
__device__ __nv_bfloat16 g_bvh[N_KEY * DMODEL], g_bvl[N_KEY * DMODEL];
__device__ __nv_bfloat16 g_wh[3 * DMODEL * DMODEL], g_wl[3 * DMODEL * DMODEL];
__device__ __nv_bfloat16 g_qh[N_ACT * DMODEL],  g_ql[N_ACT * DMODEL];
__device__ __nv_bfloat16 g_kh[N_KEY * DMODEL],  g_kl[N_KEY * DMODEL];
__device__ __nv_bfloat16 g_vth[DMODEL * N_KEY], g_vtl[DMODEL * N_KEY];
__device__ float g_ctx[N_ACT * DMODEL];
__device__ float g_wt[DKH * DMODEL];
__device__ float g_bt[DKH];
__device__ int   g_valid[N_ACT];
__device__ float g_mb[N_ACT];
__device__ float g_zb[N_ACT];
__device__ float g_chz[NHEAD * N_ACT];
__device__ unsigned char g_mask[(size_t)N_ACT * N_KEY];
__device__ int   g_mflag;

__device__ __forceinline__ float nanfix(float x) {
    if (isnan(x)) return 0.f;
    if (isinf(x)) return x > 0.f ? 1.f : -1.f;
    return x;
}

// Fast exp for x <= 0 via MUFU.EX2 (off the FMA pipe). ex2(-inf)=0.
__device__ __forceinline__ float fexp(float x) {
    float r;
    asm("ex2.approx.ftz.f32 %0, %1;" : "=f"(r) : "f"(x * 1.4426950408889634f));
    return r;
}

__device__ __forceinline__ uint32_t smem_to_u32(const void* p) {
    uint32_t a;
    asm("{ .reg .u64 t; cvta.to.shared.u64 t, %1; cvt.u32.u64 %0, t; }" : "=r"(a) : "l"(p));
    return a;
}

// ---------------------------------------------------------------------------
// warp mma + ldmatrix (baseline PTX — compiles on the plain sm_103 target)
// ---------------------------------------------------------------------------
__device__ __forceinline__ void mma_bf16(float c[4], const uint32_t a[4], const uint32_t b[2]) {
    asm volatile("mma.sync.aligned.m16n8k16.row.col.f32.bf16.bf16.f32 "
                 "{%0,%1,%2,%3}, {%4,%5,%6,%7}, {%8,%9}, {%0,%1,%2,%3};"
                 : "+f"(c[0]), "+f"(c[1]), "+f"(c[2]), "+f"(c[3])
                 : "r"(a[0]), "r"(a[1]), "r"(a[2]), "r"(a[3]), "r"(b[0]), "r"(b[1]));
}

__device__ __forceinline__ void ldsm_x4(uint32_t r[4], uint32_t addr) {
    asm volatile("ldmatrix.sync.aligned.m8n8.x4.shared.b16 {%0,%1,%2,%3}, [%4];"
                 : "=r"(r[0]), "=r"(r[1]), "=r"(r[2]), "=r"(r[3]) : "r"(addr));
}

// warp tile 32m x 64n (proj kernel, 8 warps)
__device__ __forceinline__ void mma_chunk3_64n(
    float (&acc)[2][8][4],
    uint32_t aH, uint32_t aL, uint32_t bH, uint32_t bL,
    int lane, int wm, int wn)
{
    const int la15 = lane & 15;
    const int lhi  = (lane >> 4) << 3;
    const int brow = ((lane >> 4) << 3) + (lane & 7);
    const int bko  = ((lane >> 3) & 1) << 3;
#pragma unroll
    for (int kk = 0; kk < 2; ++kk) {
        const int kb = kk * 16;
        uint32_t fah[2][4], fal[2][4];
#pragma unroll
        for (int mb = 0; mb < 2; ++mb) {
            const uint32_t off = (uint32_t)((wm * 32 + mb * 16 + la15) * LDT + kb + lhi) * 2;
            ldsm_x4(fah[mb], aH + off);
            ldsm_x4(fal[mb], aL + off);
        }
#pragma unroll
        for (int nbp = 0; nbp < 4; ++nbp) {
            const uint32_t off = (uint32_t)((wn * 64 + nbp * 16 + brow) * LDT + kb + bko) * 2;
            uint32_t fbh[4], fbl[4];
            ldsm_x4(fbh, bH + off);
            ldsm_x4(fbl, bL + off);
#pragma unroll
            for (int mb = 0; mb < 2; ++mb) {
                mma_bf16(acc[mb][nbp * 2],     fah[mb], fbh);
                mma_bf16(acc[mb][nbp * 2],     fah[mb], fbl);
                mma_bf16(acc[mb][nbp * 2],     fal[mb], fbh);
                mma_bf16(acc[mb][nbp * 2 + 1], fah[mb], fbh + 2);
                mma_bf16(acc[mb][nbp * 2 + 1], fah[mb], fbl + 2);
                mma_bf16(acc[mb][nbp * 2 + 1], fal[mb], fbh + 2);
            }
        }
    }
}

// warp tile 32m x 32n (fused kernel, 16 warps: wm 0..3, wn 0..3)
__device__ __forceinline__ void mma_chunk3_32n(
    float (&acc)[2][4][4],
    uint32_t aH, uint32_t aL, uint32_t bH, uint32_t bL,
    int lane, int wm, int wn)
{
    const int la15 = lane & 15;
    const int lhi  = (lane >> 4) << 3;
    const int brow = ((lane >> 4) << 3) + (lane & 7);
    const int bko  = ((lane >> 3) & 1) << 3;
#pragma unroll
    for (int kk = 0; kk < 2; ++kk) {
        const int kb = kk * 16;
        uint32_t fah[2][4], fal[2][4];
#pragma unroll
        for (int mb = 0; mb < 2; ++mb) {
            const uint32_t off = (uint32_t)((wm * 32 + mb * 16 + la15) * LDT + kb + lhi) * 2;
            ldsm_x4(fah[mb], aH + off);
            ldsm_x4(fal[mb], aL + off);
        }
#pragma unroll
        for (int nbp = 0; nbp < 2; ++nbp) {
            const uint32_t off = (uint32_t)((wn * 32 + nbp * 16 + brow) * LDT + kb + bko) * 2;
            uint32_t fbh[4], fbl[4];
            ldsm_x4(fbh, bH + off);
            ldsm_x4(fbl, bL + off);
#pragma unroll
            for (int mb = 0; mb < 2; ++mb) {
                mma_bf16(acc[mb][nbp * 2],     fah[mb], fbh);
                mma_bf16(acc[mb][nbp * 2],     fah[mb], fbl);
                mma_bf16(acc[mb][nbp * 2],     fal[mb], fbh);
                mma_bf16(acc[mb][nbp * 2 + 1], fah[mb], fbh + 2);
                mma_bf16(acc[mb][nbp * 2 + 1], fah[mb], fbl + 2);
                mma_bf16(acc[mb][nbp * 2 + 1], fal[mb], fbh + 2);
            }
        }
    }
}

// ---------------------------------------------------------------------------
// mask dtype detect + repack
// ---------------------------------------------------------------------------
__global__ void mask_detect_kernel(const unsigned int* __restrict__ m) {
    __shared__ int cF, cHi;
    if (threadIdx.x == 0) { cF = 0; cHi = 0; }
    __syncthreads();
    int lf = 0, lh = 0;
    for (int i = threadIdx.x; i < 16384; i += 256) {
        unsigned int w = m[i];
        if (w == 0x3F800000u) lf++;
        else if ((w & 0xFFFFFF00u) != 0u) lh++;
    }
    atomicAdd(&cF, lf);
    atomicAdd(&cHi, lh);
    __syncthreads();
    if (threadIdx.x == 0) {
        if (cF > 16) g_mflag = 2;
        else if (cHi > 16) g_mflag = 0;
        else g_mflag = 1;
    }
}

__global__ void mask_repack_kernel(const void* __restrict__ mraw) {
    const long long i4 = (long long)blockIdx.x * 256 + threadIdx.x;
    if (i4 * 4 >= (long long)N_ACT * N_KEY) return;
    const int flag = g_mflag;
    uchar4 o;
    if (flag == 0) {
        uchar4 b = ((const uchar4*)mraw)[i4];
        o.x = b.x ? 1 : 0; o.y = b.y ? 1 : 0; o.z = b.z ? 1 : 0; o.w = b.w ? 1 : 0;
    } else if (flag == 1) {
        int4 b = ((const int4*)mraw)[i4];
        o.x = b.x ? 1 : 0; o.y = b.y ? 1 : 0; o.z = b.z ? 1 : 0; o.w = b.w ? 1 : 0;
    } else {
        float4 b = ((const float4*)mraw)[i4];
        o.x = (b.x != 0.f) ? 1 : 0; o.y = (b.y != 0.f) ? 1 : 0;
        o.z = (b.z != 0.f) ? 1 : 0; o.w = (b.w != 0.f) ? 1 : 0;
    }
    ((uchar4*)g_mask)[i4] = o;
}

// fp32 -> split bf16 (hi + lo)
__global__ void conv_split_kernel(const float* __restrict__ src,
                                  __nv_bfloat16* __restrict__ hi,
                                  __nv_bfloat16* __restrict__ lo,
                                  int n4, int fix) {
    int i = blockIdx.x * 256 + threadIdx.x;
    if (i >= n4) return;
    float4 v = ((const float4*)src)[i];
    if (fix) { v.x = nanfix(v.x); v.y = nanfix(v.y); v.z = nanfix(v.z); v.w = nanfix(v.w); }
    float a[4] = {v.x, v.y, v.z, v.w};
#pragma unroll
    for (int j = 0; j < 4; ++j) {
        __nv_bfloat16 h = __float2bfloat16(a[j]);
        hi[i * 4 + j] = h;
        lo[i * 4 + j] = __float2bfloat16(a[j] - __bfloat162float(h));
    }
}

__global__ void build_wt_kernel(const float* __restrict__ ow,
                                const float* __restrict__ ob) {
    int idx = blockIdx.x * 256 + threadIdx.x;
    if (idx < DKH * DMODEL) {
        int dk = idx >> 9, c = idx & 511;
        g_wt[idx] = 0.25f * (ow[dk * DMODEL + c] + ow[(dk + DKH) * DMODEL + c] +
                             ow[(dk + 2 * DKH) * DMODEL + c] + ow[(dk + 3 * DKH) * DMODEL + c]);
    }
    if (idx < DKH)
        g_bt[idx] = 0.25f * (ob[idx] + ob[idx + DKH] + ob[idx + 2 * DKH] + ob[idx + 3 * DKH]);
}

// ---------------------------------------------------------------------------
// Bias stats pre-pass: per row n -> Mb, Zb, valid.
// ---------------------------------------------------------------------------
__global__ __launch_bounds__(256) void bias_stats_kernel(const float* __restrict__ weight) {
    __shared__ float red[256];
    __shared__ int sv;
    const int n = blockIdx.x, tid = threadIdx.x;
    if (tid == 0) sv = 0;
    __syncthreads();
    const long long base = (long long)n * N_KEY;
    float b[16];
    float mx = -INFINITY; int anym = 0;
#pragma unroll
    for (int j = 0; j < 4; ++j) {
        int m = tid * 4 + j * 1024;
        float4 w = *(const float4*)&weight[base + m];
        uchar4 mk = *(const uchar4*)&g_mask[base + m];
        float b0 = mk.x ? nanfix(w.x) : NEGV;
        float b1 = mk.y ? nanfix(w.y) : NEGV;
        float b2 = mk.z ? nanfix(w.z) : NEGV;
        float b3 = mk.w ? nanfix(w.w) : NEGV;
        b[j*4+0] = b0; b[j*4+1] = b1; b[j*4+2] = b2; b[j*4+3] = b3;
        anym |= (mk.x | mk.y | mk.z | mk.w);
        mx = fmaxf(fmaxf(fmaxf(mx, b0), fmaxf(b1, b2)), b3);
    }
    if (anym) atomicOr(&sv, 1);
    red[tid] = mx;
    __syncthreads();
    for (int s = 128; s > 0; s >>= 1) {
        if (tid < s) red[tid] = fmaxf(red[tid], red[tid + s]);
        __syncthreads();
    }
    float Mb = red[0];
    __syncthreads();
    float zs = 0.f;
#pragma unroll
    for (int j = 0; j < 16; ++j) zs += fexp(b[j] - Mb);
    red[tid] = zs;
    __syncthreads();
    for (int s = 128; s > 0; s >>= 1) {
        if (tid < s) red[tid] += red[tid + s];
        __syncthreads();
    }
    if (tid == 0) { g_mb[n] = Mb; g_zb[n] = red[0]; g_valid[n] = sv; }
}

// ---------------------------------------------------------------------------
// QKV projection: grid (12, 32), 256 threads, ldmatrix fragments (passing).
// ---------------------------------------------------------------------------
__global__ __launch_bounds__(256) void proj_mma_kernel(const float* __restrict__ ipb) {
    __shared__ __align__(16) unsigned char smraw[4 * 128 * LDT * 2];
    __nv_bfloat16* sm = (__nv_bfloat16*)smraw;
    __nv_bfloat16* sAh = sm;
    __nv_bfloat16* sAl = sm + 128 * LDT;
    __nv_bfloat16* sBh = sm + 2 * 128 * LDT;
    __nv_bfloat16* sBl = sm + 3 * 128 * LDT;
    const int ot = blockIdx.x, nt = blockIdx.y;
    const int which = ot >> 2;
    const __nv_bfloat16* Xh = (which == 0) ? g_ah : g_bvh;
    const __nv_bfloat16* Xl = (which == 0) ? g_al : g_bvl;
    const __nv_bfloat16* Wh = g_wh + (long long)ot * 128 * DMODEL;
    const __nv_bfloat16* Wl = g_wl + (long long)ot * 128 * DMODEL;

    const int tid = threadIdx.x;
    const int lane = tid & 31, warp = tid >> 5;
    const int wm = warp >> 1, wn = warp & 1;
    const int g = lane >> 2, t4 = lane & 3;
    const int lr = tid >> 2, lc = (tid & 3) * 8;
    const uint32_t aHa = smem_to_u32(sAh), aLa = smem_to_u32(sAl);
    const uint32_t bHa = smem_to_u32(sBh), bLa = smem_to_u32(sBl);

    float acc[2][8][4];
#pragma unroll
    for (int i = 0; i < 2; ++i)
#pragma unroll
        for (int j = 0; j < 8; ++j)
#pragma unroll
            for (int r = 0; r < 4; ++r) acc[i][j][r] = 0.f;

    for (int c = 0; c < 16; ++c) {
        const long long co = (long long)c * 32 + lc;
        *(uint4*)&sAh[lr * LDT + lc] = *(const uint4*)&Xh[((long long)nt * 128 + lr) * DMODEL + co];
        *(uint4*)&sAh[(lr + 64) * LDT + lc] = *(const uint4*)&Xh[((long long)nt * 128 + lr + 64) * DMODEL + co];
        *(uint4*)&sAl[lr * LDT + lc] = *(const uint4*)&Xl[((long long)nt * 128 + lr) * DMODEL + co];
        *(uint4*)&sAl[(lr + 64) * LDT + lc] = *(const uint4*)&Xl[((long long)nt * 128 + lr + 64) * DMODEL + co];
        *(uint4*)&sBh[lr * LDT + lc] = *(const uint4*)&Wh[(long long)lr * DMODEL + co];
        *(uint4*)&sBh[(lr + 64) * LDT + lc] = *(const uint4*)&Wh[(long long)(lr + 64) * DMODEL + co];
        *(uint4*)&sBl[lr * LDT + lc] = *(const uint4*)&Wl[(long long)lr * DMODEL + co];
        *(uint4*)&sBl[(lr + 64) * LDT + lc] = *(const uint4*)&Wl[(long long)(lr + 64) * DMODEL + co];
        __syncthreads();
        mma_chunk3_64n(acc, aHa, aLa, bHa, bLa, lane, wm, wn);
        __syncthreads();
    }

    const float scale = (which == 0) ? QSCALE : 1.f;
#pragma unroll
    for (int mb = 0; mb < 2; ++mb)
#pragma unroll
        for (int nb = 0; nb < 8; ++nb)
#pragma unroll
            for (int half = 0; half < 2; ++half) {
                const long long n = (long long)nt * 128 + wm * 32 + mb * 16 + g + half * 8;
                const int og = ot * 128 + wn * 64 + nb * 8 + t4 * 2;
                float v0 = scale * (acc[mb][nb][half * 2 + 0] + ipb[og]);
                float v1 = scale * (acc[mb][nb][half * 2 + 1] + ipb[og + 1]);
                __nv_bfloat16 h0 = __float2bfloat16(v0);
                __nv_bfloat16 l0 = __float2bfloat16(v0 - __bfloat162float(h0));
                __nv_bfloat16 h1 = __float2bfloat16(v1);
                __nv_bfloat16 l1 = __float2bfloat16(v1 - __bfloat162float(h1));
                if (which == 0) {
                    g_qh[n * DMODEL + og] = h0; g_qh[n * DMODEL + og + 1] = h1;
                    g_ql[n * DMODEL + og] = l0; g_ql[n * DMODEL + og + 1] = l1;
                } else if (which == 1) {
                    const int c = og - 512;
                    g_kh[n * DMODEL + c] = h0; g_kh[n * DMODEL + c + 1] = h1;
                    g_kl[n * DMODEL + c] = l0; g_kl[n * DMODEL + c + 1] = l1;
                } else {
                    const long long d = og - 1024;
                    g_vth[d * N_KEY + n] = h0; g_vth[(d + 1) * N_KEY + n] = h1;
                    g_vtl[d * N_KEY + n] = l0; g_vtl[(d + 1) * N_KEY + n] = l1;
                }
            }
}

// ---------------------------------------------------------------------------
// FUSED flash attention: grid (32 nt, 4 h), 512 threads (16 warps, 4x4).
// Group-scoped named barriers: K/V staging per wn group, softmax per wm group.
// ---------------------------------------------------------------------------
#define CHUNK_BF16 (128 * LDT)
#define SQ_OFF    0
#define SQL_OFF   (4 * CHUNK_BF16)
#define SP_OFF    (8 * CHUNK_BF16)
#define SPL_OFF   (12 * CHUNK_BF16)
#define SKH_OFF   (16 * CHUNK_BF16)
#define SKL_OFF   (18 * CHUNK_BF16)
#define SMEM_BF16_TOTAL (20 * CHUNK_BF16)
#define FUSED_SMEM_BYTES (SMEM_BF16_TOTAL * 2 + 128 * 4 * 4)

__global__ __launch_bounds__(512, 1) void fused_attn_kernel(const float* __restrict__ weight) {
    extern __shared__ __align__(16) unsigned char smem_raw[];
    __nv_bfloat16* sm = (__nv_bfloat16*)smem_raw;
    __nv_bfloat16* sQh = sm + SQ_OFF;
    __nv_bfloat16* sQl = sm + SQL_OFF;
    __nv_bfloat16* sPh = sm + SP_OFF;
    __nv_bfloat16* sPl = sm + SPL_OFF;
    float* sBias = (float*)(sm + SP_OFF);            // overlay on sP region
    float* sRed  = (float*)(sm + SMEM_BF16_TOTAL);   // 128*4 floats

    const uint32_t sQh_u = smem_to_u32(sQh), sQl_u = smem_to_u32(sQl);
    const uint32_t sPh_u = smem_to_u32(sPh), sPl_u = smem_to_u32(sPl);
    const uint32_t sKh_u = smem_to_u32(sm + SKH_OFF), sKl_u = smem_to_u32(sm + SKL_OFF);

    const int nt = blockIdx.x, h = blockIdx.y;
    const int tid = threadIdx.x;
    const int lane = tid & 31, warp = tid >> 5;
    const int wm = warp >> 2, wn = warp & 3;         // 4x4 warp grid
    const int g = lane >> 2, t4 = lane & 3;
    const long long nBase = (long long)nt * 128;

    // wn-group K/V staging: group covers rows [32*wn, 32*wn+32), 32 cols
    const int rloc = ((warp >> 2) << 3) + (lane >> 2);   // 0..31 within group
    const int cloc = (lane & 3) * 8;
    const int soK = (wn * 32 + rloc) * LDT + cloc;
    // wm-group bias staging: rows [32*wm, 32*wm+32)
    const int rlocB = (wn << 3) + (lane >> 2);
    const int browL = wm * 32 + rlocB;
    const long long browG = (nBase + browL) * (long long)N_KEY;

    // stage Q (4 chunks, hi+lo) — full block
    for (int u = tid; u < 2048; u += 512) {
        const int c = u >> 9;
        const int r = (u >> 2) & 127;
        const int cc = (u & 3) * 8;
        const long long gofs = (nBase + r) * DMODEL + h * DKH + c * 32 + cc;
        *(uint4*)&sQh[(c * 128 + r) * LDT + cc] = *(const uint4*)&g_qh[gofs];
        *(uint4*)&sQl[(c * 128 + r) * LDT + cc] = *(const uint4*)&g_ql[gofs];
    }

    float acc_o[2][4][4];
#pragma unroll
    for (int i = 0; i < 2; ++i)
#pragma unroll
        for (int j = 0; j < 4; ++j)
#pragma unroll
            for (int r = 0; r < 4; ++r) acc_o[i][j][r] = 0.f;

    float zh[4] = {0.f, 0.f, 0.f, 0.f};
    float ch[4] = {0.f, 0.f, 0.f, 0.f};
    float Mold[4] = {-INFINITY, -INFINITY, -INFINITY, -INFINITY};
    float Mbr[4];
#pragma unroll
    for (int mb = 0; mb < 2; ++mb)
#pragma unroll
        for (int half = 0; half < 2; ++half)
            Mbr[mb * 2 + half] = g_mb[nBase + wm * 32 + mb * 16 + half * 8 + g];

    // prefetch K chunk0 of m-tile 0 (group slice)
    uint4 kh0, kl0;
    {
        const long long gk = (long long)(wn * 32 + rloc) * DMODEL + h * DKH + cloc;
        kh0 = *(const uint4*)&g_kh[gk];
        kl0 = *(const uint4*)&g_kl[gk];
    }

    __syncthreads();

    for (int mt = 0; mt < N_KEY / 128; ++mt) {
        const long long mBase = (long long)mt * 128;
        float acc_s[2][4][4];
#pragma unroll
        for (int i = 0; i < 2; ++i)
#pragma unroll
            for (int j = 0; j < 4; ++j)
#pragma unroll
                for (int r = 0; r < 4; ++r) acc_s[i][j][r] = 0.f;

        // ---- QK^T over 4 K-chunks; staging + barriers scoped to wn groups ----
        {
            uint4 ph = kh0, pl = kl0;
            for (int c = 0; c < 4; ++c) {
                const int buf = (c & 1) * CHUNK_BF16;
                *(uint4*)&sm[SKH_OFF + buf + soK] = ph;
                *(uint4*)&sm[SKL_OFF + buf + soK] = pl;
                // bias slice chunk c (wm-partitioned rows)
                {
                    const long long bcol = mBase + c * 32 + cloc;
                    float4 w0 = *(const float4*)&weight[browG + bcol];
                    float4 w1 = *(const float4*)&weight[browG + bcol + 4];
                    uchar4 m0 = *(const uchar4*)&g_mask[browG + bcol];
                    uchar4 m1 = *(const uchar4*)&g_mask[browG + bcol + 4];
                    float4 b0, b1;
                    b0.x = m0.x ? nanfix(w0.x) : NEGV;
                    b0.y = m0.y ? nanfix(w0.y) : NEGV;
                    b0.z = m0.z ? nanfix(w0.z) : NEGV;
                    b0.w = m0.w ? nanfix(w0.w) : NEGV;
                    b1.x = m1.x ? nanfix(w1.x) : NEGV;
                    b1.y = m1.y ? nanfix(w1.y) : NEGV;
                    b1.z = m1.z ? nanfix(w1.z) : NEGV;
                    b1.w = m1.w ? nanfix(w1.w) : NEGV;
                    *(float4*)&sBias[browL * 132 + c * 32 + cloc] = b0;
                    *(float4*)&sBias[browL * 132 + c * 32 + cloc + 4] = b1;
                }
                BARW(1 + wn);
                if (c < 3) {
                    const long long gk = (mBase + wn * 32 + rloc) * DMODEL + h * DKH + (c + 1) * 32 + cloc;
                    ph = *(const uint4*)&g_kh[gk];
                    pl = *(const uint4*)&g_kl[gk];
                }
                mma_chunk3_32n(acc_s, sQh_u + (uint32_t)(c * CHUNK_BF16) * 2,
                               sQl_u + (uint32_t)(c * CHUNK_BF16) * 2,
                               sKh_u + (uint32_t)buf * 2, sKl_u + (uint32_t)buf * 2,
                               lane, wm, wn);
            }
        }

        // prefetch V chunk0 (group slice), hidden under softmax
        uint4 vh0, vl0;
        {
            const long long gv = (long long)(h * DKH + wn * 32 + rloc) * N_KEY + mBase + cloc;
            vh0 = *(const uint4*)&g_vth[gv];
            vl0 = *(const uint4*)&g_vtl[gv];
        }

        BARW(5 + wm);   // bias writes visible within wm group

        // ---- bias add (from sBias) + tile row max ----
#pragma unroll
        for (int mb = 0; mb < 2; ++mb)
#pragma unroll
            for (int half = 0; half < 2; ++half) {
                const int rl = wm * 32 + mb * 16 + half * 8 + g;
                float smax = -INFINITY;
#pragma unroll
                for (int nb = 0; nb < 4; ++nb) {
                    const int col = wn * 32 + nb * 8 + t4 * 2;
                    const float b0 = sBias[rl * 132 + col];
                    const float b1 = sBias[rl * 132 + col + 1];
                    const float s0 = acc_s[mb][nb][half * 2 + 0] + b0;
                    const float s1 = acc_s[mb][nb][half * 2 + 1] + b1;
                    acc_s[mb][nb][half * 2 + 0] = s0;
                    acc_s[mb][nb][half * 2 + 1] = s1;
                    smax = fmaxf(smax, fmaxf(s0, s1));
                }
                smax = fmaxf(smax, __shfl_xor_sync(0xffffffffu, smax, 1));
                smax = fmaxf(smax, __shfl_xor_sync(0xffffffffu, smax, 2));
                if (t4 == 0) sRed[rl * 4 + wn] = smax;
            }
        BARW(5 + wm);   // sRed visible within wm group

        // ---- online softmax update (MUFU exp) ----
#pragma unroll
        for (int mb = 0; mb < 2; ++mb)
#pragma unroll
            for (int half = 0; half < 2; ++half) {
                const int slot = mb * 2 + half;
                const int rl = wm * 32 + mb * 16 + half * 8 + g;
                const float Mtile = fmaxf(fmaxf(sRed[rl * 4], sRed[rl * 4 + 1]),
                                          fmaxf(sRed[rl * 4 + 2], sRed[rl * 4 + 3]));
                const float Mnew = fmaxf(Mold[slot], Mtile);
                const float alpha = fexp(Mold[slot] - Mnew);
                Mold[slot] = Mnew;
                float z = zh[slot] * alpha;
                float cc = ch[slot] * alpha;
#pragma unroll
                for (int nb = 0; nb < 4; ++nb) {
                    const int col = wn * 32 + nb * 8 + t4 * 2;
#pragma unroll
                    for (int r = 0; r < 2; ++r) {
                        const float s = acc_s[mb][nb][half * 2 + r];
                        const float p = fexp(s - Mnew);
                        acc_s[mb][nb][half * 2 + r] = p;
                        z += p;
                        const float b = sBias[rl * 132 + col + r];
                        cc = fmaf(fexp(b - Mbr[slot]), p, cc);
                    }
                    acc_o[mb][nb][half * 2 + 0] *= alpha;
                    acc_o[mb][nb][half * 2 + 1] *= alpha;
                }
                zh[slot] = z;
                ch[slot] = cc;
            }
        __syncthreads();   // FULL: sBias overlay reads done before P writes (cross-wm)

        // ---- write P (split bf16) into smem chunk layout ----
#pragma unroll
        for (int mb = 0; mb < 2; ++mb)
#pragma unroll
            for (int half = 0; half < 2; ++half) {
                const int rl = wm * 32 + mb * 16 + half * 8 + g;
#pragma unroll
                for (int nb = 0; nb < 4; ++nb) {
                    const int col = wn * 32 + nb * 8 + t4 * 2;
                    const int chunk = col >> 5, c32 = col & 31;
                    const float p0 = acc_s[mb][nb][half * 2 + 0];
                    const float p1 = acc_s[mb][nb][half * 2 + 1];
                    const __nv_bfloat16 h0 = __float2bfloat16(p0);
                    const __nv_bfloat16 h1 = __float2bfloat16(p1);
                    const __nv_bfloat16 l0 = __float2bfloat16(p0 - __bfloat162float(h0));
                    const __nv_bfloat16 l1 = __float2bfloat16(p1 - __bfloat162float(h1));
                    const uint32_t ph = (uint32_t)__bfloat16_as_ushort(h0) |
                                        ((uint32_t)__bfloat16_as_ushort(h1) << 16);
                    const uint32_t pl = (uint32_t)__bfloat16_as_ushort(l0) |
                                        ((uint32_t)__bfloat16_as_ushort(l1) << 16);
                    *(uint32_t*)&sPh[(chunk * 128 + rl) * LDT + c32] = ph;
                    *(uint32_t*)&sPl[(chunk * 128 + rl) * LDT + c32] = pl;
                }
            }

        // prefetch K chunk0 of next m-tile (group slice), hidden under ctx
        if (mt < N_KEY / 128 - 1) {
            const long long gk = (mBase + 128 + wn * 32 + rloc) * DMODEL + h * DKH + cloc;
            kh0 = *(const uint4*)&g_kh[gk];
            kl0 = *(const uint4*)&g_kl[gk];
        }

        BARW(5 + wm);   // P writes visible to all wn within wm group

        // ---- ctx accumulate: P @ V^T over 4 m-chunks; wn-group staging ----
        {
            uint4 ph = vh0, pl = vl0;
            for (int c = 0; c < 4; ++c) {
                const int buf = (c & 1) * CHUNK_BF16;
                *(uint4*)&sm[SKH_OFF + buf + soK] = ph;
                *(uint4*)&sm[SKL_OFF + buf + soK] = pl;
                BARW(1 + wn);
                if (c < 3) {
                    const long long gv = (long long)(h * DKH + wn * 32 + rloc) * N_KEY + mBase + (c + 1) * 32 + cloc;
                    ph = *(const uint4*)&g_vth[gv];
                    pl = *(const uint4*)&g_vtl[gv];
                }
                mma_chunk3_32n(acc_o, sPh_u + (uint32_t)(c * CHUNK_BF16) * 2,
                               sPl_u + (uint32_t)(c * CHUNK_BF16) * 2,
                               sKh_u + (uint32_t)buf * 2, sKl_u + (uint32_t)buf * 2,
                               lane, wm, wn);
            }
        }
        __syncthreads();   // FULL: protect sP overlay + K buffers for next m-tile
    }

    // ---- final reductions of zh, ch across t4 and wn ----
    float zt[4], ct[4];
#pragma unroll
    for (int slot = 0; slot < 4; ++slot) {
        float z = zh[slot];
        z += __shfl_xor_sync(0xffffffffu, z, 1);
        z += __shfl_xor_sync(0xffffffffu, z, 2);
        zh[slot] = z;
        float c = ch[slot];
        c += __shfl_xor_sync(0xffffffffu, c, 1);
        c += __shfl_xor_sync(0xffffffffu, c, 2);
        ch[slot] = c;
    }
#pragma unroll
    for (int mb = 0; mb < 2; ++mb)
#pragma unroll
        for (int half = 0; half < 2; ++half) {
            const int rl = wm * 32 + mb * 16 + half * 8 + g;
            if (t4 == 0) sRed[rl * 4 + wn] = zh[mb * 2 + half];
        }
    __syncthreads();
#pragma unroll
    for (int mb = 0; mb < 2; ++mb)
#pragma unroll
        for (int half = 0; half < 2; ++half) {
            const int rl = wm * 32 + mb * 16 + half * 8 + g;
            zt[mb * 2 + half] = (sRed[rl * 4] + sRed[rl * 4 + 1]) +
                                (sRed[rl * 4 + 2] + sRed[rl * 4 + 3]);
        }
    __syncthreads();
#pragma unroll
    for (int mb = 0; mb < 2; ++mb)
#pragma unroll
        for (int half = 0; half < 2; ++half) {
            const int rl = wm * 32 + mb * 16 + half * 8 + g;
            if (t4 == 0) sRed[rl * 4 + wn] = ch[mb * 2 + half];
        }
    __syncthreads();
#pragma unroll
    for (int mb = 0; mb < 2; ++mb)
#pragma unroll
        for (int half = 0; half < 2; ++half) {
            const int rl = wm * 32 + mb * 16 + half * 8 + g;
            ct[mb * 2 + half] = (sRed[rl * 4] + sRed[rl * 4 + 1]) +
                                (sRed[rl * 4 + 2] + sRed[rl * 4 + 3]);
        }

    // ---- outputs ----
#pragma unroll
    for (int mb = 0; mb < 2; ++mb)
#pragma unroll
        for (int half = 0; half < 2; ++half) {
            const int slot = mb * 2 + half;
            const int rl = wm * 32 + mb * 16 + half * 8 + g;
            const long long n = nBase + rl;
            const float zi = 1.f / zt[slot];
            if (t4 == 0 && wn == 0) g_chz[h * N_ACT + n] = ct[slot] * zi;
#pragma unroll
            for (int nb = 0; nb < 4; ++nb) {
                const int d = wn * 32 + nb * 8 + t4 * 2;
                float2 o;
                o.x = acc_o[mb][nb][half * 2 + 0] * zi;
                o.y = acc_o[mb][nb][half * 2 + 1] * zi;
                *(float2*)&g_ctx[n * DMODEL + h * DKH + d] = o;
            }
        }
}

// ---------------------------------------------------------------------------
// influence finisher
// ---------------------------------------------------------------------------
__global__ void influence_kernel(float* __restrict__ inf_out) {
    const int n = blockIdx.x * 256 + threadIdx.x;
    if (n >= N_ACT) return;
    const float s = g_chz[n] + g_chz[N_ACT + n] + g_chz[2 * N_ACT + n] + g_chz[3 * N_ACT + n];
    inf_out[n] = g_valid[n] ? (0.25f * s / g_zb[n]) : 0.f;
}

// ---------------------------------------------------------------------------
// Topic GEMM (FFMA, small): C[n][o] = ctx . wt[o] + bt[o], valid-gated.
// ---------------------------------------------------------------------------
__global__ __launch_bounds__(256) void gemm_nt_kernel(
    const float* __restrict__ X, const float* __restrict__ W,
    const float* __restrict__ bias, float* __restrict__ out,
    int ldo, const int* __restrict__ valid)
{
    __shared__ float Xs[64 * 36];
    __shared__ float Ws[64 * 36];
    const int tid = threadIdx.x;
    const int rowBase = blockIdx.y * 64;
    const int colBase = blockIdx.x * 64;
    const int og = tid & 15, ngr = tid >> 4;

    float acc[4][4];
#pragma unroll
    for (int i = 0; i < 4; ++i)
#pragma unroll
        for (int j = 0; j < 4; ++j) acc[i][j] = 0.f;

    for (int kk = 0; kk < 512; kk += 32) {
#pragma unroll
        for (int jj = 0; jj < 2; ++jj) {
            int idx = tid + jj * 256;
            int r = idx >> 3, c4 = (idx & 7) << 2;
            *(float4*)&Xs[r * 36 + c4] = *(const float4*)&X[(rowBase + r) * 512 + kk + c4];
            *(float4*)&Ws[r * 36 + c4] = *(const float4*)&W[(colBase + r) * 512 + kk + c4];
        }
        __syncthreads();
#pragma unroll
        for (int k4 = 0; k4 < 32; k4 += 4) {
            float4 xv[4], wv[4];
#pragma unroll
            for (int i = 0; i < 4; ++i) xv[i] = *(const float4*)&Xs[(ngr * 4 + i) * 36 + k4];
#pragma unroll
            for (int j = 0; j < 4; ++j) wv[j] = *(const float4*)&Ws[(og * 4 + j) * 36 + k4];
#pragma unroll
            for (int i = 0; i < 4; ++i)
#pragma unroll
                for (int j = 0; j < 4; ++j) {
                    acc[i][j] = fmaf(xv[i].x, wv[j].x, acc[i][j]);
                    acc[i][j] = fmaf(xv[i].y, wv[j].y, acc[i][j]);
                    acc[i][j] = fmaf(xv[i].z, wv[j].z, acc[i][j]);
                    acc[i][j] = fmaf(xv[i].w, wv[j].w, acc[i][j]);
                }
        }
        __syncthreads();
    }
#pragma unroll
    for (int i = 0; i < 4; ++i) {
        int n = rowBase + ngr * 4 + i;
        float vmul = valid[n] ? 1.f : 0.f;
#pragma unroll
        for (int j = 0; j < 4; ++j) {
            int o = colBase + og * 4 + j;
            out[n * ldo + o] = vmul * (acc[i][j] + bias[o]);
        }
    }
}

// ---------------------------------------------------------------------------
extern "C" void kernel_launch(void* const* d_in, const int* in_sizes, int n_in,
                              void* d_out, int out_size) {
    const float* a      = (const float*)d_in[0];
    const float* bv     = (const float*)d_in[1];
    const void*  mraw   = (const void*)d_in[2];
    const float* weight = (const float*)d_in[3];
    const float* ipw    = (const float*)d_in[4];
    const float* ipb    = (const float*)d_in[5];
    const float* ow     = (const float*)d_in[6];
    const float* ob     = (const float*)d_in[7];
    float* out = (float*)d_out;

    void *pctx, *pwt, *pbt, *pvalid;
    cudaGetSymbolAddress(&pctx, g_ctx);
    cudaGetSymbolAddress(&pwt, g_wt);
    cudaGetSymbolAddress(&pbt, g_bt);
    cudaGetSymbolAddress(&pvalid, g_valid);
    void *pah, *pal, *pbh, *pbl, *pwh, *pwl;
    cudaGetSymbolAddress(&pah, g_ah); cudaGetSymbolAddress(&pal, g_al);
    cudaGetSymbolAddress(&pbh, g_bvh); cudaGetSymbolAddress(&pbl, g_bvl);
    cudaGetSymbolAddress(&pwh, g_wh); cudaGetSymbolAddress(&pwl, g_wl);

    cudaFuncSetAttribute(fused_attn_kernel, cudaFuncAttributeMaxDynamicSharedMemorySize,
                         FUSED_SMEM_BYTES);

    mask_detect_kernel<<<1, 256>>>((const unsigned int*)mraw);
    mask_repack_kernel<<<16384, 256>>>(mraw);

    conv_split_kernel<<<2048, 256>>>(a,  (__nv_bfloat16*)pah, (__nv_bfloat16*)pal, N_ACT * DMODEL / 4, 1);
    conv_split_kernel<<<2048, 256>>>(bv, (__nv_bfloat16*)pbh, (__nv_bfloat16*)pbl, N_KEY * DMODEL / 4, 1);
    conv_split_kernel<<<768, 256>>>(ipw, (__nv_bfloat16*)pwh, (__nv_bfloat16*)pwl, 3 * DMODEL * DMODEL / 4, 0);

    build_wt_kernel<<<(DKH * DMODEL + 255) / 256, 256>>>(ow, ob);

    proj_mma_kernel<<<dim3(12, 32), 256>>>(ipb);
    bias_stats_kernel<<<N_ACT, 256>>>(weight);

    fused_attn_kernel<<<dim3(32, 4), 512, FUSED_SMEM_BYTES>>>(weight);

    influence_kernel<<<16, 256>>>(out + N_ACT * DKH);

    gemm_nt_kernel<<<dim3(2, 64), 256>>>((const float*)pctx, (const float*)pwt,
                                         (const float*)pbt, out, DKH, (const int*)pvalid);
}